// round 1
// baseline (speedup 1.0000x reference)
#include <cuda_runtime.h>
#include <cuda_bf16.h>
#include <math.h>

// ---------------- problem constants ----------------
#define Dm    512
#define NHh   8
#define DH    64
#define NBLK  6
#define SEQ   257          // 256 patch tokens + 1 (register or action)
#define NZR   1542         // 6*257
#define NXA   1285         // 5*257
#define NTOK  2827         // NZR + NXA
#define HIDm  2048

// ---------------- scratch (device globals; no allocation allowed) ----------------
__device__ float g_state[NTOK*Dm];
__device__ float g_norm [NTOK*Dm];
__device__ float g_q    [NTOK*Dm];
__device__ float g_k    [NTOK*Dm];
__device__ float g_v    [NTOK*Dm];
__device__ float g_att  [NTOK*Dm];
__device__ float g_atto [NTOK*Dm];
__device__ float g_h    [NTOK*Dm];
__device__ float g_gg   [NTOK*2*HIDm];
__device__ float g_actb [NTOK*HIDm];
__device__ float g_ff   [NTOK*Dm];

__device__ float g_cond [7*Dm];      // classes 0..5 = cond frames, 6 = clean (time_emb[0])
__device__ float g_silu [7*Dm];
__device__ float g_m1   [NBLK*7*1024];   // mod1 scale(512)|shift(512)
__device__ float g_m2   [NBLK*7*1024];
__device__ float g_ga   [NBLK*7*Dm];     // gate1
__device__ float g_gb   [NBLK*7*Dm];     // gate2

// ---------------- helpers ----------------
__device__ __forceinline__ float warpSum(float v){
    #pragma unroll
    for (int o = 16; o > 0; o >>= 1) v += __shfl_xor_sync(0xffffffffu, v, o);
    return v;
}
__device__ __forceinline__ float warpMax(float v){
    #pragma unroll
    for (int o = 16; o > 0; o >>= 1) v = fmaxf(v, __shfl_xor_sync(0xffffffffu, v, o));
    return v;
}
// 128-thread block reduce of (sum, sumsq); result broadcast to all threads
__device__ __forceinline__ void blockReduce2(float& s, float& q){
    s = warpSum(s); q = warpSum(q);
    __shared__ float sh[8];
    int w = threadIdx.x >> 5;
    if ((threadIdx.x & 31) == 0) { sh[w] = s; sh[4+w] = q; }
    __syncthreads();
    s = sh[0]+sh[1]+sh[2]+sh[3];
    q = sh[4]+sh[5]+sh[6]+sh[7];
    __syncthreads();
}
__device__ __forceinline__ int frame_class(int t){ return (t < NZR) ? (t / SEQ) : 6; }

// ---------------- conditioning vectors ----------------
__global__ void cond_kernel(const int* __restrict__ ts, const float* __restrict__ time_emb){
    int c = blockIdx.x;                 // 0..6
    int row = (c < 6) ? ts[c] : 0;
    for (int d = threadIdx.x; d < Dm; d += blockDim.x){
        float x = time_emb[row*Dm + d];
        g_cond[c*Dm + d] = x;
        g_silu[c*Dm + d] = x / (1.0f + expf(-x));
    }
}

// Per-(block, class) modulation/gate vectors.
// grid.x = NBLK*7, grid.y = 12 (3072 outputs / 256)
__global__ void modvec_kernel(const float* __restrict__ Wm1, const float* __restrict__ bm1,
                              const float* __restrict__ Wm2, const float* __restrict__ bm2,
                              const float* __restrict__ Wg1, const float* __restrict__ bg1,
                              const float* __restrict__ Wg2, const float* __restrict__ bg2){
    int ic = blockIdx.x;               // i*7 + c
    int i  = ic / 7, c = ic % 7;
    int j  = blockIdx.y * 256 + threadIdx.x;   // 0..3071
    __shared__ float vs[Dm], vp[Dm];
    for (int k = threadIdx.x; k < Dm; k += 256){
        vs[k] = g_silu[c*Dm + k];
        vp[k] = g_cond[c*Dm + k];
    }
    __syncthreads();
    const float* W; const float* b; float* out; int nd; const float* v; int col;
    if (j < 1024)      { W = Wm1 + i*Dm*1024; b = bm1 + i*1024; out = g_m1 + ic*1024; nd = 1024; v = vs; col = j; }
    else if (j < 2048) { W = Wm2 + i*Dm*1024; b = bm2 + i*1024; out = g_m2 + ic*1024; nd = 1024; v = vs; col = j - 1024; }
    else if (j < 2560) { W = Wg1 + i*Dm*Dm;   b = bg1 + i*Dm;   out = g_ga + ic*Dm;   nd = Dm;   v = vp; col = j - 2048; }
    else               { W = Wg2 + i*Dm*Dm;   b = bg2 + i*Dm;   out = g_gb + ic*Dm;   nd = Dm;   v = vp; col = j - 2560; }
    float acc = b[col];
    #pragma unroll 8
    for (int k = 0; k < Dm; k++) acc += v[k] * W[k*nd + col];
    out[col] = acc;
}

// ---------------- embed (patchify + pe, registers, actions) ----------------
__global__ void embed_kernel(const float* __restrict__ z, const float* __restrict__ frames,
                             const int* __restrict__ actions,
                             const float* __restrict__ Wp, const float* __restrict__ bp,
                             const float* __restrict__ regs, const float* __restrict__ pe,
                             const float* __restrict__ aemb){
    int t = blockIdx.x;
    int tid = threadIdx.x;
    int f, s;
    const float* img;
    const float* special = nullptr;
    if (t < NZR) {
        f = t / SEQ; s = t % SEQ; img = z;
        if (s == SEQ-1) special = regs;                 // registers[0]
    } else {
        int u = t - NZR; f = u / SEQ; s = u % SEQ; img = frames;
        if (s == SEQ-1) special = aemb + actions[f]*Dm; // action token (frames 0..4)
    }
    if (special){
        for (int d = tid; d < Dm; d += 128) g_state[t*Dm + d] = special[d];
        return;
    }
    __shared__ float pv[12];
    if (tid < 12){
        int c = tid >> 2, ph = (tid >> 1) & 1, pw = tid & 1;
        int h2 = s >> 4, w2 = s & 15;
        pv[tid] = img[f*3072 + c*1024 + (h2*2 + ph)*32 + (w2*2 + pw)];
    }
    __syncthreads();
    for (int d = tid; d < Dm; d += 128){
        float acc = bp[d] + pe[s*Dm + d];
        #pragma unroll
        for (int jj = 0; jj < 12; jj++) acc += pv[jj] * Wp[jj*Dm + d];
        g_state[t*Dm + d] = acc;
    }
}

// ---------------- AdaLN (mod1): state -> norm ----------------
__global__ void mod_kernel(int blk){
    int t = blockIdx.x, tid = threadIdx.x;
    int c = frame_class(t);
    float4 v = ((const float4*)(g_state + t*Dm))[tid];
    float s = v.x+v.y+v.z+v.w;
    float q = v.x*v.x + v.y*v.y + v.z*v.z + v.w*v.w;
    blockReduce2(s, q);
    float mu  = s * (1.0f/Dm);
    float var = q * (1.0f/Dm) - mu*mu;
    float rstd = rsqrtf(var + 1e-5f);
    const float* ms = g_m1 + (blk*7 + c)*1024;
    int d = tid*4;
    float4 o;
    o.x = (v.x-mu)*rstd*(1.0f+ms[d+0]) + ms[512+d+0];
    o.y = (v.y-mu)*rstd*(1.0f+ms[d+1]) + ms[512+d+1];
    o.z = (v.z-mu)*rstd*(1.0f+ms[d+2]) + ms[512+d+2];
    o.w = (v.w-mu)*rstd*(1.0f+ms[d+3]) + ms[512+d+3];
    ((float4*)(g_norm + t*Dm))[tid] = o;
}

// ---------------- post-attn: h = mod2( norm*g1 + atto ) ----------------
__global__ void postattn_kernel(int blk){
    int t = blockIdx.x, tid = threadIdx.x;
    int c = frame_class(t);
    const float* g1v = g_ga + (blk*7 + c)*Dm;
    float4 n = ((const float4*)(g_norm + t*Dm))[tid];
    float4 a = ((const float4*)(g_atto + t*Dm))[tid];
    int d = tid*4;
    float4 v;
    v.x = n.x*g1v[d+0] + a.x;
    v.y = n.y*g1v[d+1] + a.y;
    v.z = n.z*g1v[d+2] + a.z;
    v.w = n.w*g1v[d+3] + a.w;
    float s = v.x+v.y+v.z+v.w;
    float q = v.x*v.x + v.y*v.y + v.z*v.z + v.w*v.w;
    blockReduce2(s, q);
    float mu  = s * (1.0f/Dm);
    float var = q * (1.0f/Dm) - mu*mu;
    float rstd = rsqrtf(var + 1e-5f);
    const float* ms = g_m2 + (blk*7 + c)*1024;
    float4 o;
    o.x = (v.x-mu)*rstd*(1.0f+ms[d+0]) + ms[512+d+0];
    o.y = (v.y-mu)*rstd*(1.0f+ms[d+1]) + ms[512+d+1];
    o.z = (v.z-mu)*rstd*(1.0f+ms[d+2]) + ms[512+d+2];
    o.w = (v.w-mu)*rstd*(1.0f+ms[d+3]) + ms[512+d+3];
    ((float4*)(g_h + t*Dm))[tid] = o;
}

// ---------------- GEGLU activation ----------------
__global__ void act_kernel(){
    int i = blockIdx.x*256 + threadIdx.x;          // exactly NTOK*HIDm threads
    int t = i / HIDm, j = i % HIDm;
    float a = g_gg[t*2*HIDm + j];
    float g = g_gg[t*2*HIDm + HIDm + j];
    float ge = 0.5f*g*(1.0f + erff(g*0.70710678118654752440f));
    g_actb[i] = a*ge;
}

// ---------------- gate2: state = ff * g2 ----------------
__global__ void gate2_kernel(int blk){
    int i = blockIdx.x*256 + threadIdx.x;          // exactly NTOK*Dm threads
    int t = i / Dm, d = i % Dm;
    int c = frame_class(t);
    g_state[i] = g_ff[i] * g_gb[(blk*7 + c)*Dm + d];
}

// ---------------- SGEMM: C[M,N] = A[M,K] @ B[K,N] + bias[N] ----------------
// 64x64x16 tile, 256 threads, 4x4 per thread
__global__ __launch_bounds__(256) void sgemm_bias(const float* __restrict__ A,
                                                  const float* __restrict__ B,
                                                  const float* __restrict__ bias,
                                                  float* __restrict__ C,
                                                  int M, int N, int K){
    __shared__ float As[16][64];   // [k][m]
    __shared__ float Bs[16][64];   // [k][n]
    int tid = threadIdx.x;
    int bm = blockIdx.y * 64, bn = blockIdx.x * 64;
    int tx = tid & 15, ty = tid >> 4;
    int arow = tid >> 2,  ac0 = (tid & 3) * 4;     // A: 64 rows x 16 k
    int brow = tid >> 4,  bc0 = (tid & 15) * 4;    // B: 16 k x 64 n
    float acc[4][4] = {};
    for (int k0 = 0; k0 < K; k0 += 16){
        float4 av;
        if (bm + arow < M) av = *(const float4*)(A + (bm+arow)*K + k0 + ac0);
        else               av = make_float4(0.f,0.f,0.f,0.f);
        As[ac0+0][arow] = av.x; As[ac0+1][arow] = av.y;
        As[ac0+2][arow] = av.z; As[ac0+3][arow] = av.w;
        *(float4*)&Bs[brow][bc0] = *(const float4*)(B + (k0+brow)*N + bn + bc0);
        __syncthreads();
        #pragma unroll
        for (int kk = 0; kk < 16; kk++){
            float4 a = *(const float4*)&As[kk][ty*4];
            float4 b = *(const float4*)&Bs[kk][tx*4];
            acc[0][0] += a.x*b.x; acc[0][1] += a.x*b.y; acc[0][2] += a.x*b.z; acc[0][3] += a.x*b.w;
            acc[1][0] += a.y*b.x; acc[1][1] += a.y*b.y; acc[1][2] += a.y*b.z; acc[1][3] += a.y*b.w;
            acc[2][0] += a.z*b.x; acc[2][1] += a.z*b.y; acc[2][2] += a.z*b.z; acc[2][3] += a.z*b.w;
            acc[3][0] += a.w*b.x; acc[3][1] += a.w*b.y; acc[3][2] += a.w*b.z; acc[3][3] += a.w*b.w;
        }
        __syncthreads();
    }
    float4 bb = *(const float4*)(bias + bn + tx*4);
    #pragma unroll
    for (int i = 0; i < 4; i++){
        int row = bm + ty*4 + i;
        if (row < M){
            float4 o;
            o.x = acc[i][0] + bb.x; o.y = acc[i][1] + bb.y;
            o.z = acc[i][2] + bb.z; o.w = acc[i][3] + bb.w;
            *(float4*)(C + row*N + bn + tx*4) = o;
        }
    }
}

// ---------------- attention ----------------
// grid: (11 frames * 65 qgroups, 8 heads); 128 threads; 4 queries/block.
// Every token is a query exactly once (zr via cross-attn, xa via self-attn);
// each query has 1-2 contiguous key ranges in the global K/V buffers.
#define QPB 4
#define QGRP 65
__global__ __launch_bounds__(128) void attn_kernel(const float* __restrict__ Q,
                                                   const float* __restrict__ K,
                                                   const float* __restrict__ V,
                                                   float* __restrict__ O){
    int frame = blockIdx.x / QGRP;         // 0..10  (0..5 zr, 6..10 xa)
    int qi0   = (blockIdx.x % QGRP) * QPB;
    int h     = blockIdx.y;
    int qbase, r0s, r0n, r1s, r1n;
    if (frame < 6){
        qbase = frame*SEQ;
        r0s = frame*SEQ;              r0n = SEQ;                 // own zr frame
        int lo = frame-4; if (lo < 0) lo = 0;
        r1s = NZR + lo*SEQ;           r1n = (frame - lo)*SEQ;    // xa window [f-4, f-1]
    } else {
        int f = frame - 6;
        qbase = NZR + f*SEQ;
        r0s = NZR;                    r0n = (f+1)*SEQ;           // causal xa prefix
        r1s = 0;                      r1n = 0;
    }
    int nq = SEQ - qi0; if (nq > QPB) nq = QPB;
    int nk = r0n + r1n;

    __shared__ float qs[QPB][DH];
    __shared__ float sc[QPB][1300];
    __shared__ float red[QPB][4];
    __shared__ float bm_[QPB], bl_[QPB];

    int tid = threadIdx.x, lane = tid & 31, wid = tid >> 5;

    for (int idx = tid; idx < QPB*DH; idx += 128){
        int j = idx >> 6, d = idx & 63;
        qs[j][d] = (j < nq) ? Q[(qbase+qi0+j)*Dm + h*DH + d] : 0.0f;
    }
    __syncthreads();

    // scores
    float lmax[QPB] = {-1e30f,-1e30f,-1e30f,-1e30f};
    for (int i = tid; i < nk; i += 128){
        int g = (i < r0n) ? (r0s + i) : (r1s + i - r0n);
        const float4* kr = (const float4*)(K + g*Dm + h*DH);
        float s0=0.f, s1=0.f, s2=0.f, s3=0.f;
        #pragma unroll
        for (int d4 = 0; d4 < 16; d4++){
            float4 kv = kr[d4];
            int d = d4*4;
            s0 += kv.x*qs[0][d] + kv.y*qs[0][d+1] + kv.z*qs[0][d+2] + kv.w*qs[0][d+3];
            s1 += kv.x*qs[1][d] + kv.y*qs[1][d+1] + kv.z*qs[1][d+2] + kv.w*qs[1][d+3];
            s2 += kv.x*qs[2][d] + kv.y*qs[2][d+1] + kv.z*qs[2][d+2] + kv.w*qs[2][d+3];
            s3 += kv.x*qs[3][d] + kv.y*qs[3][d+1] + kv.z*qs[3][d+2] + kv.w*qs[3][d+3];
        }
        s0 *= 0.125f; s1 *= 0.125f; s2 *= 0.125f; s3 *= 0.125f;
        sc[0][i] = s0; sc[1][i] = s1; sc[2][i] = s2; sc[3][i] = s3;
        lmax[0] = fmaxf(lmax[0], s0); lmax[1] = fmaxf(lmax[1], s1);
        lmax[2] = fmaxf(lmax[2], s2); lmax[3] = fmaxf(lmax[3], s3);
    }
    // block max per query
    #pragma unroll
    for (int j = 0; j < QPB; j++){
        float w = warpMax(lmax[j]);
        if (lane == 0) red[j][wid] = w;
    }
    __syncthreads();
    if (tid < QPB) bm_[tid] = fmaxf(fmaxf(red[tid][0], red[tid][1]), fmaxf(red[tid][2], red[tid][3]));
    __syncthreads();

    // exp + sum
    float lsum[QPB] = {0.f,0.f,0.f,0.f};
    float m0 = bm_[0], m1 = bm_[1], m2 = bm_[2], m3 = bm_[3];
    for (int i = tid; i < nk; i += 128){
        float p0 = __expf(sc[0][i] - m0); sc[0][i] = p0; lsum[0] += p0;
        float p1 = __expf(sc[1][i] - m1); sc[1][i] = p1; lsum[1] += p1;
        float p2 = __expf(sc[2][i] - m2); sc[2][i] = p2; lsum[2] += p2;
        float p3 = __expf(sc[3][i] - m3); sc[3][i] = p3; lsum[3] += p3;
    }
    #pragma unroll
    for (int j = 0; j < QPB; j++){
        float w = warpSum(lsum[j]);
        if (lane == 0) red[j][wid] = w;
    }
    __syncthreads();
    if (tid < QPB) bl_[tid] = red[tid][0] + red[tid][1] + red[tid][2] + red[tid][3];
    __syncthreads();

    // PV: 64 dims, 2 halves over key range
    int d = tid & 63, half = tid >> 6;
    float a0=0.f, a1=0.f, a2=0.f, a3=0.f;
    for (int i = half; i < nk; i += 2){
        int g = (i < r0n) ? (r0s + i) : (r1s + i - r0n);
        float pv = V[g*Dm + h*DH + d];
        a0 += sc[0][i]*pv; a1 += sc[1][i]*pv; a2 += sc[2][i]*pv; a3 += sc[3][i]*pv;
    }
    __syncthreads();
    if (half == 1){ qs[0][d]=a0; qs[1][d]=a1; qs[2][d]=a2; qs[3][d]=a3; }
    __syncthreads();
    if (half == 0){
        float acc[QPB] = {a0,a1,a2,a3};
        #pragma unroll
        for (int j = 0; j < QPB; j++){
            if (j < nq){
                float o = (acc[j] + qs[j][d]) / bl_[j];
                O[(qbase+qi0+j)*Dm + h*DH + d] = o;
            }
        }
    }
}

// ---------------- unpatch ----------------
__global__ void unpatch_kernel(const float* __restrict__ Wu, const float* __restrict__ bu,
                               float* __restrict__ out){
    int token = blockIdx.x;               // 0..1535
    int f = token >> 8, s = token & 255;
    const float* x = g_state + (f*SEQ + s)*Dm;
    __shared__ float xs[Dm];
    int tid = threadIdx.x;
    for (int d2 = tid; d2 < Dm; d2 += 128) xs[d2] = x[d2];
    __syncthreads();
    int warp = tid >> 5, lane = tid & 31;
    for (int j = warp; j < 12; j += 4){
        float acc = 0.f;
        for (int d2 = lane; d2 < Dm; d2 += 32) acc += xs[d2] * Wu[d2*12 + j];
        acc = warpSum(acc);
        if (lane == 0){
            int c = j >> 2, ph = (j >> 1) & 1, pw = j & 1;
            int h2 = s >> 4, w2 = s & 15;
            out[f*3072 + c*1024 + (h2*2 + ph)*32 + (w2*2 + pw)] = acc + bu[j];
        }
    }
}

// ---------------- host ----------------
static float* symaddr(const void* sym){
    void* p = nullptr;
    cudaGetSymbolAddress(&p, sym);
    return (float*)p;
}

extern "C" void kernel_launch(void* const* d_in, const int* in_sizes, int n_in,
                              void* d_out, int out_size){
    const float* z        = (const float*)d_in[0];
    const float* frames   = (const float*)d_in[1];
    const int*   actions  = (const int*)  d_in[2];
    const int*   ts       = (const int*)  d_in[3];
    const float* W_patch  = (const float*)d_in[4];
    const float* b_patch  = (const float*)d_in[5];
    const float* W_unpatch= (const float*)d_in[6];
    const float* b_unpatch= (const float*)d_in[7];
    const float* registers= (const float*)d_in[8];
    const float* pe_grid  = (const float*)d_in[9];
    const float* action_e = (const float*)d_in[10];
    const float* time_emb = (const float*)d_in[11];
    const float* W_mod1   = (const float*)d_in[12];
    const float* b_mod1   = (const float*)d_in[13];
    const float* W_mod2   = (const float*)d_in[14];
    const float* b_mod2   = (const float*)d_in[15];
    const float* W_q      = (const float*)d_in[16];
    const float* b_q      = (const float*)d_in[17];
    const float* W_k      = (const float*)d_in[18];
    const float* b_k      = (const float*)d_in[19];
    const float* W_v      = (const float*)d_in[20];
    const float* b_v      = (const float*)d_in[21];
    const float* W_o      = (const float*)d_in[22];
    const float* b_o      = (const float*)d_in[23];
    const float* W_geglu  = (const float*)d_in[28];
    const float* b_geglu  = (const float*)d_in[29];
    const float* W_ffout  = (const float*)d_in[30];
    const float* b_ffout  = (const float*)d_in[31];
    const float* W_g1     = (const float*)d_in[24];
    const float* b_g1     = (const float*)d_in[25];
    const float* W_g2     = (const float*)d_in[26];
    const float* b_g2     = (const float*)d_in[27];
    float* out = (float*)d_out;

    float* pNorm = symaddr(g_norm);
    float* pQ    = symaddr(g_q);
    float* pK    = symaddr(g_k);
    float* pV    = symaddr(g_v);
    float* pAtt  = symaddr(g_att);
    float* pAtto = symaddr(g_atto);
    float* pH    = symaddr(g_h);
    float* pGG   = symaddr(g_gg);
    float* pAct  = symaddr(g_actb);
    float* pFF   = symaddr(g_ff);

    cond_kernel<<<7, 128>>>(ts, time_emb);
    modvec_kernel<<<dim3(NBLK*7, 12), 256>>>(W_mod1, b_mod1, W_mod2, b_mod2,
                                             W_g1, b_g1, W_g2, b_g2);
    embed_kernel<<<NTOK, 128>>>(z, frames, actions, W_patch, b_patch,
                                registers, pe_grid, action_e);

    dim3 gemm512(8, 45);     // N=512, M=2827
    dim3 gemm4096(64, 45);   // N=4096
    for (int i = 0; i < NBLK; i++){
        mod_kernel<<<NTOK, 128>>>(i);
        sgemm_bias<<<gemm512, 256>>>(pNorm, W_q + i*Dm*Dm, b_q + i*Dm, pQ, NTOK, Dm, Dm);
        sgemm_bias<<<gemm512, 256>>>(pNorm, W_k + i*Dm*Dm, b_k + i*Dm, pK, NTOK, Dm, Dm);
        sgemm_bias<<<gemm512, 256>>>(pNorm, W_v + i*Dm*Dm, b_v + i*Dm, pV, NTOK, Dm, Dm);
        attn_kernel<<<dim3(11*QGRP, NHh), 128>>>(pQ, pK, pV, pAtt);
        sgemm_bias<<<gemm512, 256>>>(pAtt, W_o + i*Dm*Dm, b_o + i*Dm, pAtto, NTOK, Dm, Dm);
        postattn_kernel<<<NTOK, 128>>>(i);
        sgemm_bias<<<gemm4096, 256>>>(pH, W_geglu + i*Dm*2*HIDm, b_geglu + i*2*HIDm, pGG,
                                      NTOK, 2*HIDm, Dm);
        act_kernel<<<(NTOK*HIDm)/256, 256>>>();
        sgemm_bias<<<gemm512, 256>>>(pAct, W_ffout + i*HIDm*Dm, b_ffout + i*Dm, pFF,
                                     NTOK, Dm, HIDm);
        gate2_kernel<<<(NTOK*Dm)/256, 256>>>(i);
    }
    unpatch_kernel<<<1536, 128>>>(W_unpatch, b_unpatch, out);
}

// round 4
// speedup vs baseline: 1.3023x; 1.3023x over previous
#include <cuda_runtime.h>
#include <cuda_bf16.h>
#include <cstdint>
#include <math.h>

// ---------------- problem constants ----------------
#define Dm    512
#define NHh   8
#define DH    64
#define NBLK  6
#define SEQ   257
#define NZR   1542
#define NXA   1285
#define NTOK  2827
#define HIDm  2048
#define QKVD  1536

// ---------------- scratch ----------------
__device__ float g_state[NTOK*Dm];
__device__ float g_qkv  [NTOK*QKVD];
__device__ float g_atto [NTOK*Dm];

__device__ __nv_bfloat16 g_nh[NTOK*Dm];     // norm split
__device__ __nv_bfloat16 g_nl[NTOK*Dm];
__device__ __nv_bfloat16 g_xh[NTOK*Dm];     // att / h split
__device__ __nv_bfloat16 g_xl[NTOK*Dm];
__device__ __nv_bfloat16 g_yh[NTOK*HIDm];   // act split
__device__ __nv_bfloat16 g_yl[NTOK*HIDm];

__device__ float g_cond [7*Dm];
__device__ float g_silu [7*Dm];
__device__ float g_m1   [NBLK*7*1024];
__device__ float g_m2   [NBLK*7*1024];
__device__ float g_ga   [NBLK*7*Dm];
__device__ float g_gb   [NBLK*7*Dm];

// pre-transposed, split weights (row = output col n, K contiguous)
__device__ __nv_bfloat16 g_wqkv_h[NBLK*QKVD*Dm];
__device__ __nv_bfloat16 g_wqkv_l[NBLK*QKVD*Dm];
__device__ __nv_bfloat16 g_wo_h  [NBLK*Dm*Dm];
__device__ __nv_bfloat16 g_wo_l  [NBLK*Dm*Dm];
__device__ __nv_bfloat16 g_wgg_h [NBLK*2*HIDm*Dm];
__device__ __nv_bfloat16 g_wgg_l [NBLK*2*HIDm*Dm];
__device__ __nv_bfloat16 g_wff_h [NBLK*Dm*HIDm];
__device__ __nv_bfloat16 g_wff_l [NBLK*Dm*HIDm];
__device__ float g_bqkv[NBLK*QKVD];
__device__ float g_bgg2[NBLK*2*HIDm];

// ---------------- helpers ----------------
__device__ __forceinline__ uint32_t smem_u32(const void* p){
    uint32_t a;
    asm("{ .reg .u64 t; cvta.to.shared.u64 t, %1; cvt.u32.u64 %0, t; }" : "=r"(a) : "l"(p));
    return a;
}
#define SW128(off) ((off) ^ (((off)>>3) & 0x70))

__device__ __forceinline__ void ldsm4(uint32_t* r, uint32_t addr){
    asm volatile("ldmatrix.sync.aligned.m8n8.x4.shared.b16 {%0,%1,%2,%3}, [%4];"
        : "=r"(r[0]), "=r"(r[1]), "=r"(r[2]), "=r"(r[3]) : "r"(addr));
}
__device__ __forceinline__ void mma_bf16(float* d, const uint32_t* a, uint32_t b0, uint32_t b1){
    asm volatile("mma.sync.aligned.m16n8k16.row.col.f32.bf16.bf16.f32 "
        "{%0,%1,%2,%3}, {%4,%5,%6,%7}, {%8,%9}, {%0,%1,%2,%3};"
        : "+f"(d[0]), "+f"(d[1]), "+f"(d[2]), "+f"(d[3])
        : "r"(a[0]), "r"(a[1]), "r"(a[2]), "r"(a[3]), "r"(b0), "r"(b1));
}

__device__ __forceinline__ float warpSum(float v){
    #pragma unroll
    for (int o = 16; o > 0; o >>= 1) v += __shfl_xor_sync(0xffffffffu, v, o);
    return v;
}
__device__ __forceinline__ float warpMax(float v){
    #pragma unroll
    for (int o = 16; o > 0; o >>= 1) v = fmaxf(v, __shfl_xor_sync(0xffffffffu, v, o));
    return v;
}
__device__ __forceinline__ void blockReduce2(float& s, float& q){
    s = warpSum(s); q = warpSum(q);
    __shared__ float sh[8];
    int w = threadIdx.x >> 5;
    if ((threadIdx.x & 31) == 0) { sh[w] = s; sh[4+w] = q; }
    __syncthreads();
    s = sh[0]+sh[1]+sh[2]+sh[3];
    q = sh[4]+sh[5]+sh[6]+sh[7];
    __syncthreads();
}
__device__ __forceinline__ int frame_class(int t){ return (t < NZR) ? (t / SEQ) : 6; }

__device__ __forceinline__ void split2(float x, float y, uint32_t& h, uint32_t& l){
    __nv_bfloat16 hx = __float2bfloat16(x), hy = __float2bfloat16(y);
    __nv_bfloat16 lx = __float2bfloat16(x - __bfloat162float(hx));
    __nv_bfloat16 ly = __float2bfloat16(y - __bfloat162float(hy));
    h = (uint32_t)__bfloat16_as_ushort(hx) | ((uint32_t)__bfloat16_as_ushort(hy) << 16);
    l = (uint32_t)__bfloat16_as_ushort(lx) | ((uint32_t)__bfloat16_as_ushort(ly) << 16);
}

// ---------------- conditioning ----------------
__global__ void cond_kernel(const int* __restrict__ ts, const float* __restrict__ time_emb){
    int c = blockIdx.x;
    int row = (c < 6) ? ts[c] : 0;
    for (int d = threadIdx.x; d < Dm; d += blockDim.x){
        float x = time_emb[row*Dm + d];
        g_cond[c*Dm + d] = x;
        g_silu[c*Dm + d] = x / (1.0f + expf(-x));
    }
}

__global__ void modvec_kernel(const float* __restrict__ Wm1, const float* __restrict__ bm1,
                              const float* __restrict__ Wm2, const float* __restrict__ bm2,
                              const float* __restrict__ Wg1, const float* __restrict__ bg1,
                              const float* __restrict__ Wg2, const float* __restrict__ bg2){
    int ic = blockIdx.x;
    int i  = ic / 7, c = ic % 7;
    int j  = blockIdx.y * 256 + threadIdx.x;
    __shared__ float vs[Dm], vp[Dm];
    for (int k = threadIdx.x; k < Dm; k += 256){
        vs[k] = g_silu[c*Dm + k];
        vp[k] = g_cond[c*Dm + k];
    }
    __syncthreads();
    const float* W; const float* b; float* out; int nd; const float* v; int col;
    if (j < 1024)      { W = Wm1 + i*Dm*1024; b = bm1 + i*1024; out = g_m1 + ic*1024; nd = 1024; v = vs; col = j; }
    else if (j < 2048) { W = Wm2 + i*Dm*1024; b = bm2 + i*1024; out = g_m2 + ic*1024; nd = 1024; v = vs; col = j - 1024; }
    else if (j < 2560) { W = Wg1 + i*Dm*Dm;   b = bg1 + i*Dm;   out = g_ga + ic*Dm;   nd = Dm;   v = vp; col = j - 2048; }
    else               { W = Wg2 + i*Dm*Dm;   b = bg2 + i*Dm;   out = g_gb + ic*Dm;   nd = Dm;   v = vp; col = j - 2560; }
    float acc = b[col];
    #pragma unroll 8
    for (int k = 0; k < Dm; k++) acc += v[k] * W[k*nd + col];
    out[col] = acc;
}

// ---------------- embed ----------------
__global__ void embed_kernel(const float* __restrict__ z, const float* __restrict__ frames,
                             const int* __restrict__ actions,
                             const float* __restrict__ Wp, const float* __restrict__ bp,
                             const float* __restrict__ regs, const float* __restrict__ pe,
                             const float* __restrict__ aemb){
    int t = blockIdx.x;
    int tid = threadIdx.x;
    int f, s;
    const float* img;
    const float* special = nullptr;
    if (t < NZR) {
        f = t / SEQ; s = t % SEQ; img = z;
        if (s == SEQ-1) special = regs;
    } else {
        int u = t - NZR; f = u / SEQ; s = u % SEQ; img = frames;
        if (s == SEQ-1) special = aemb + actions[f]*Dm;
    }
    if (special){
        for (int d = tid; d < Dm; d += 128) g_state[t*Dm + d] = special[d];
        return;
    }
    __shared__ float pv[12];
    if (tid < 12){
        int c = tid >> 2, ph = (tid >> 1) & 1, pw = tid & 1;
        int h2 = s >> 4, w2 = s & 15;
        pv[tid] = img[f*3072 + c*1024 + (h2*2 + ph)*32 + (w2*2 + pw)];
    }
    __syncthreads();
    for (int d = tid; d < Dm; d += 128){
        float acc = bp[d] + pe[s*Dm + d];
        #pragma unroll
        for (int jj = 0; jj < 12; jj++) acc += pv[jj] * Wp[jj*Dm + d];
        g_state[t*Dm + d] = acc;
    }
}

// ---------------- weight prep ----------------
__global__ void transp_split(const float* __restrict__ in, __nv_bfloat16* __restrict__ ohi,
                             __nv_bfloat16* __restrict__ olo, int K, int N, int il){
    __shared__ float t[32][33];
    int r0 = blockIdx.x*32, k0 = blockIdx.y*32;
    int tx = threadIdx.x, ty = threadIdx.y;
    int u0 = r0 >> 1;
    for (int i = ty; i < 32; i += 8){
        int col = il ? ((tx < 16) ? (u0 + tx) : (HIDm + u0 + tx - 16)) : (r0 + tx);
        t[i][tx] = in[(size_t)(k0 + i)*N + col];
    }
    __syncthreads();
    for (int j = ty; j < 32; j += 8){
        int ci = il ? ((j>>1) + ((j&1)?16:0)) : j;
        float v = t[tx][ci];
        __nv_bfloat16 h = __float2bfloat16(v);
        __nv_bfloat16 l = __float2bfloat16(v - __bfloat162float(h));
        size_t o = (size_t)(r0 + j)*K + k0 + tx;
        ohi[o] = h; olo[o] = l;
    }
}

__global__ void prep_bias(const float* __restrict__ bq, const float* __restrict__ bk,
                          const float* __restrict__ bv, const float* __restrict__ bgg){
    int i = blockIdx.x;
    for (int j = threadIdx.x; j < QKVD; j += 256){
        float v = (j < 512) ? bq[i*512 + j] : (j < 1024) ? bk[i*512 + j - 512] : bv[i*512 + j - 1024];
        g_bqkv[i*QKVD + j] = v;
    }
    for (int p = threadIdx.x; p < 2*HIDm; p += 256){
        int u = p >> 1;
        g_bgg2[i*2*HIDm + p] = (p & 1) ? bgg[i*2*HIDm + HIDm + u] : bgg[i*2*HIDm + u];
    }
}

// ---------------- AdaLN mod1: state -> nh/nl split ----------------
__global__ void mod_kernel(int blk){
    int t = blockIdx.x, tid = threadIdx.x;
    int c = frame_class(t);
    float4 v = ((const float4*)(g_state + (size_t)t*Dm))[tid];
    float s = v.x+v.y+v.z+v.w;
    float q = v.x*v.x + v.y*v.y + v.z*v.z + v.w*v.w;
    blockReduce2(s, q);
    float mu  = s * (1.0f/Dm);
    float var = q * (1.0f/Dm) - mu*mu;
    float rstd = rsqrtf(var + 1e-5f);
    const float* ms = g_m1 + (blk*7 + c)*1024;
    int d = tid*4;
    float o0 = (v.x-mu)*rstd*(1.0f+ms[d+0]) + ms[512+d+0];
    float o1 = (v.y-mu)*rstd*(1.0f+ms[d+1]) + ms[512+d+1];
    float o2 = (v.z-mu)*rstd*(1.0f+ms[d+2]) + ms[512+d+2];
    float o3 = (v.w-mu)*rstd*(1.0f+ms[d+3]) + ms[512+d+3];
    uint32_t h0,l0,h1,l1;
    split2(o0,o1,h0,l0); split2(o2,o3,h1,l1);
    ((uint2*)(g_nh + (size_t)t*Dm))[tid] = make_uint2(h0,h1);
    ((uint2*)(g_nl + (size_t)t*Dm))[tid] = make_uint2(l0,l1);
}

// ---------------- post-attn: h = mod2( norm*g1 + atto ) -> xh/xl ----------------
__global__ void postattn_kernel(int blk){
    int t = blockIdx.x, tid = threadIdx.x;
    int c = frame_class(t);
    const float* g1v = g_ga + (blk*7 + c)*Dm;
    float4 a = ((const float4*)(g_atto + (size_t)t*Dm))[tid];
    int d = tid*4;
    const __nv_bfloat16* nh = g_nh + (size_t)t*Dm + d;
    const __nv_bfloat16* nl = g_nl + (size_t)t*Dm + d;
    float n0 = __bfloat162float(nh[0]) + __bfloat162float(nl[0]);
    float n1 = __bfloat162float(nh[1]) + __bfloat162float(nl[1]);
    float n2 = __bfloat162float(nh[2]) + __bfloat162float(nl[2]);
    float n3 = __bfloat162float(nh[3]) + __bfloat162float(nl[3]);
    float4 v;
    v.x = n0*g1v[d+0] + a.x;
    v.y = n1*g1v[d+1] + a.y;
    v.z = n2*g1v[d+2] + a.z;
    v.w = n3*g1v[d+3] + a.w;
    float s = v.x+v.y+v.z+v.w;
    float q = v.x*v.x + v.y*v.y + v.z*v.z + v.w*v.w;
    blockReduce2(s, q);
    float mu  = s * (1.0f/Dm);
    float var = q * (1.0f/Dm) - mu*mu;
    float rstd = rsqrtf(var + 1e-5f);
    const float* ms = g_m2 + (blk*7 + c)*1024;
    float o0 = (v.x-mu)*rstd*(1.0f+ms[d+0]) + ms[512+d+0];
    float o1 = (v.y-mu)*rstd*(1.0f+ms[d+1]) + ms[512+d+1];
    float o2 = (v.z-mu)*rstd*(1.0f+ms[d+2]) + ms[512+d+2];
    float o3 = (v.w-mu)*rstd*(1.0f+ms[d+3]) + ms[512+d+3];
    uint32_t h0,l0,h1,l1;
    split2(o0,o1,h0,l0); split2(o2,o3,h1,l1);
    ((uint2*)(g_xh + (size_t)t*Dm))[tid] = make_uint2(h0,h1);
    ((uint2*)(g_xl + (size_t)t*Dm))[tid] = make_uint2(l0,l1);
}

// ---------------- bf16 split GEMM on mma.sync (HMMA) ----------------
// C[M,N] += A @ B^T with A = Ah+Al ([M][K] bf16 split), B rows = out cols ([N][K] split).
// mode 0: C fp32 = acc + bias
// mode 1: GEGLU interleaved: out[m][u] = (a+ba)*gelu(g+bg), split bf16 into Oh/Ol (stride HIDm)
// mode 2: C fp32 = (acc + bias) * g_gb
#define BUFSZ 65536
__global__ __launch_bounds__(256) void gemm_mma(
    const __nv_bfloat16* __restrict__ Ah, const __nv_bfloat16* __restrict__ Al,
    const __nv_bfloat16* __restrict__ Bh, const __nv_bfloat16* __restrict__ Bl,
    const float* __restrict__ bias, float* __restrict__ C,
    __nv_bfloat16* __restrict__ Oh, __nv_bfloat16* __restrict__ Ol,
    int M, int N, int K, int mode, int blk)
{
    extern __shared__ char smem[];
    uint32_t sb = smem_u32(smem);
    int tid = threadIdx.x, lane = tid & 31, wid = tid >> 5;
    int bm = blockIdx.y * 128, bn = blockIdx.x * 128;
    int wm = wid >> 1, wn = wid & 1;
    int lr = lane & 7, mid = lane >> 3;

    float acc[2][8][4];
    #pragma unroll
    for (int i=0;i<2;i++){
        #pragma unroll
        for (int j=0;j<8;j++){
            #pragma unroll
            for (int k=0;k<4;k++) acc[i][j][k] = 0.f;
        }
    }

    auto load_chunk = [&](int cc, int buf){
        int kc = cc << 6;
        uint32_t sbase = sb + buf*BUFSZ;
        #pragma unroll
        for (int p = 0; p < 4; p++){
            int idx = p*256 + tid;
            int r = idx >> 3, ch = idx & 7;
            uint32_t so = SW128((uint32_t)(r*128 + ch*16));
            int row = bm + r;
            size_t aoff = (size_t)((row < M) ? row : (M-1))*K + kc + ch*8;
            uint32_t pr = (row < M) ? 16u : 0u;
            asm volatile("cp.async.cg.shared.global [%0], [%1], 16, %2;" :: "r"(sbase + so),         "l"(Ah + aoff), "r"(pr));
            asm volatile("cp.async.cg.shared.global [%0], [%1], 16, %2;" :: "r"(sbase + 16384 + so), "l"(Al + aoff), "r"(pr));
            size_t boff = (size_t)(bn + r)*K + kc + ch*8;
            asm volatile("cp.async.cg.shared.global [%0], [%1], 16;" :: "r"(sbase + 32768 + so), "l"(Bh + boff));
            asm volatile("cp.async.cg.shared.global [%0], [%1], 16;" :: "r"(sbase + 49152 + so), "l"(Bl + boff));
        }
        asm volatile("cp.async.commit_group;" ::: "memory");
    };

    int nchunk = K >> 6;
    load_chunk(0, 0);
    for (int c = 0; c < nchunk; c++){
        int buf = c & 1;
        if (c + 1 < nchunk){
            load_chunk(c + 1, buf ^ 1);
            asm volatile("cp.async.wait_group 1;" ::: "memory");
        } else {
            asm volatile("cp.async.wait_group 0;" ::: "memory");
        }
        __syncthreads();
        uint32_t abase = sb + buf*BUFSZ;
        uint32_t bbase = abase + 32768;
        #pragma unroll
        for (int ks = 0; ks < 4; ks++){
            uint32_t ah[2][4], al[2][4];
            #pragma unroll
            for (int mf = 0; mf < 2; mf++){
                int row = wm*32 + mf*16 + (mid & 1)*8 + lr;
                uint32_t off = SW128((uint32_t)(row*128 + (ks*2 + (mid >> 1))*16));
                ldsm4(ah[mf], abase + off);
                ldsm4(al[mf], abase + 16384 + off);
            }
            uint32_t bh[4][4], bl[4][4];
            #pragma unroll
            for (int np = 0; np < 4; np++){
                int row = wn*64 + np*16 + (mid >> 1)*8 + lr;
                uint32_t off = SW128((uint32_t)(row*128 + (ks*2 + (mid & 1))*16));
                ldsm4(bh[np], bbase + off);
                ldsm4(bl[np], bbase + 16384 + off);
            }
            #pragma unroll
            for (int mf = 0; mf < 2; mf++){
                #pragma unroll
                for (int nf = 0; nf < 8; nf++){
                    uint32_t* ph = &bh[nf >> 1][(nf & 1)*2];
                    uint32_t* pl = &bl[nf >> 1][(nf & 1)*2];
                    mma_bf16(acc[mf][nf], ah[mf], ph[0], ph[1]);
                    mma_bf16(acc[mf][nf], ah[mf], pl[0], pl[1]);
                    mma_bf16(acc[mf][nf], al[mf], ph[0], ph[1]);
                }
            }
        }
        __syncthreads();
    }

    // epilogue
    #pragma unroll
    for (int mf = 0; mf < 2; mf++){
        int m0 = bm + wm*32 + mf*16 + (lane >> 2);
        #pragma unroll
        for (int half = 0; half < 2; half++){
            int m = m0 + half*8;
            if (m >= M) continue;
            #pragma unroll
            for (int nf = 0; nf < 8; nf++){
                float d0 = acc[mf][nf][half*2 + 0];
                float d1 = acc[mf][nf][half*2 + 1];
                int c0 = bn + wn*64 + nf*8 + (lane & 3)*2;
                if (mode == 0){
                    float2 o = make_float2(d0 + bias[c0], d1 + bias[c0+1]);
                    *(float2*)(C + (size_t)m*N + c0) = o;
                } else if (mode == 1){
                    float a = d0 + bias[c0];
                    float g = d1 + bias[c0+1];
                    float ge = 0.5f*g*(1.0f + erff(g*0.70710678118654752440f));
                    float v = a*ge;
                    int u = c0 >> 1;
                    __nv_bfloat16 hh = __float2bfloat16(v);
                    __nv_bfloat16 ll = __float2bfloat16(v - __bfloat162float(hh));
                    Oh[(size_t)m*HIDm + u] = hh;
                    Ol[(size_t)m*HIDm + u] = ll;
                } else {
                    const float* gv = g_gb + (blk*7 + frame_class(m))*Dm;
                    float2 o;
                    o.x = (d0 + bias[c0])   * gv[c0];
                    o.y = (d1 + bias[c0+1]) * gv[c0+1];
                    *(float2*)(C + (size_t)m*N + c0) = o;
                }
            }
        }
    }
}

// ---------------- attention (qkv packed fp32, writes bf16 split) ----------------
#define QPB 4
#define QGRP 65
__global__ __launch_bounds__(128) void attn_kernel(const float* __restrict__ QKV){
    int frame = blockIdx.x / QGRP;
    int qi0   = (blockIdx.x % QGRP) * QPB;
    int h     = blockIdx.y;
    int qbase, r0s, r0n, r1s, r1n;
    if (frame < 6){
        qbase = frame*SEQ;
        r0s = frame*SEQ;              r0n = SEQ;
        int lo = frame-4; if (lo < 0) lo = 0;
        r1s = NZR + lo*SEQ;           r1n = (frame - lo)*SEQ;
    } else {
        int f = frame - 6;
        qbase = NZR + f*SEQ;
        r0s = NZR;                    r0n = (f+1)*SEQ;
        r1s = 0;                      r1n = 0;
    }
    int nq = SEQ - qi0; if (nq > QPB) nq = QPB;
    int nk = r0n + r1n;

    __shared__ float qs[QPB][DH];
    __shared__ float sc[QPB][1300];
    __shared__ float red[QPB][4];
    __shared__ float bm_[QPB], bl_[QPB];

    int tid = threadIdx.x, lane = tid & 31, wid = tid >> 5;

    for (int idx = tid; idx < QPB*DH; idx += 128){
        int j = idx >> 6, d = idx & 63;
        qs[j][d] = (j < nq) ? QKV[(size_t)(qbase+qi0+j)*QKVD + h*DH + d] : 0.0f;
    }
    __syncthreads();

    float lmax[QPB] = {-1e30f,-1e30f,-1e30f,-1e30f};
    for (int i = tid; i < nk; i += 128){
        int g = (i < r0n) ? (r0s + i) : (r1s + i - r0n);
        const float4* kr = (const float4*)(QKV + (size_t)g*QKVD + 512 + h*DH);
        float s0=0.f, s1=0.f, s2=0.f, s3=0.f;
        #pragma unroll
        for (int d4 = 0; d4 < 16; d4++){
            float4 kv = kr[d4];
            int d = d4*4;
            s0 += kv.x*qs[0][d] + kv.y*qs[0][d+1] + kv.z*qs[0][d+2] + kv.w*qs[0][d+3];
            s1 += kv.x*qs[1][d] + kv.y*qs[1][d+1] + kv.z*qs[1][d+2] + kv.w*qs[1][d+3];
            s2 += kv.x*qs[2][d] + kv.y*qs[2][d+1] + kv.z*qs[2][d+2] + kv.w*qs[2][d+3];
            s3 += kv.x*qs[3][d] + kv.y*qs[3][d+1] + kv.z*qs[3][d+2] + kv.w*qs[3][d+3];
        }
        s0 *= 0.125f; s1 *= 0.125f; s2 *= 0.125f; s3 *= 0.125f;
        sc[0][i] = s0; sc[1][i] = s1; sc[2][i] = s2; sc[3][i] = s3;
        lmax[0] = fmaxf(lmax[0], s0); lmax[1] = fmaxf(lmax[1], s1);
        lmax[2] = fmaxf(lmax[2], s2); lmax[3] = fmaxf(lmax[3], s3);
    }
    #pragma unroll
    for (int j = 0; j < QPB; j++){
        float w = warpMax(lmax[j]);
        if (lane == 0) red[j][wid] = w;
    }
    __syncthreads();
    if (tid < QPB) bm_[tid] = fmaxf(fmaxf(red[tid][0], red[tid][1]), fmaxf(red[tid][2], red[tid][3]));
    __syncthreads();

    float lsum[QPB] = {0.f,0.f,0.f,0.f};
    float m0 = bm_[0], m1 = bm_[1], m2 = bm_[2], m3 = bm_[3];
    for (int i = tid; i < nk; i += 128){
        float p0 = __expf(sc[0][i] - m0); sc[0][i] = p0; lsum[0] += p0;
        float p1 = __expf(sc[1][i] - m1); sc[1][i] = p1; lsum[1] += p1;
        float p2 = __expf(sc[2][i] - m2); sc[2][i] = p2; lsum[2] += p2;
        float p3 = __expf(sc[3][i] - m3); sc[3][i] = p3; lsum[3] += p3;
    }
    #pragma unroll
    for (int j = 0; j < QPB; j++){
        float w = warpSum(lsum[j]);
        if (lane == 0) red[j][wid] = w;
    }
    __syncthreads();
    if (tid < QPB) bl_[tid] = red[tid][0] + red[tid][1] + red[tid][2] + red[tid][3];
    __syncthreads();

    int d = tid & 63, half = tid >> 6;
    float a0=0.f, a1=0.f, a2=0.f, a3=0.f;
    for (int i = half; i < nk; i += 2){
        int g = (i < r0n) ? (r0s + i) : (r1s + i - r0n);
        float pv = QKV[(size_t)g*QKVD + 1024 + h*DH + d];
        a0 += sc[0][i]*pv; a1 += sc[1][i]*pv; a2 += sc[2][i]*pv; a3 += sc[3][i]*pv;
    }
    __syncthreads();
    if (half == 1){ qs[0][d]=a0; qs[1][d]=a1; qs[2][d]=a2; qs[3][d]=a3; }
    __syncthreads();
    if (half == 0){
        float accq[QPB] = {a0,a1,a2,a3};
        #pragma unroll
        for (int j = 0; j < QPB; j++){
            if (j < nq){
                float o = (accq[j] + qs[j][d]) / bl_[j];
                size_t idx = (size_t)(qbase+qi0+j)*Dm + h*DH + d;
                __nv_bfloat16 hh = __float2bfloat16(o);
                g_xh[idx] = hh;
                g_xl[idx] = __float2bfloat16(o - __bfloat162float(hh));
            }
        }
    }
}

// ---------------- unpatch ----------------
__global__ void unpatch_kernel(const float* __restrict__ Wu, const float* __restrict__ bu,
                               float* __restrict__ out){
    int token = blockIdx.x;
    int f = token >> 8, s = token & 255;
    const float* x = g_state + (size_t)(f*SEQ + s)*Dm;
    __shared__ float xs[Dm];
    int tid = threadIdx.x;
    for (int d2 = tid; d2 < Dm; d2 += 128) xs[d2] = x[d2];
    __syncthreads();
    int warp = tid >> 5, lane = tid & 31;
    for (int j = warp; j < 12; j += 4){
        float acc = 0.f;
        for (int d2 = lane; d2 < Dm; d2 += 32) acc += xs[d2] * Wu[d2*12 + j];
        acc = warpSum(acc);
        if (lane == 0){
            int c = j >> 2, ph = (j >> 1) & 1, pw = j & 1;
            int h2 = s >> 4, w2 = s & 15;
            out[f*3072 + c*1024 + (h2*2 + ph)*32 + (w2*2 + pw)] = acc + bu[j];
        }
    }
}

// ---------------- host ----------------
template <typename T>
static T* symaddr(const void* sym){
    void* p = nullptr;
    cudaGetSymbolAddress(&p, sym);
    return (T*)p;
}

extern "C" void kernel_launch(void* const* d_in, const int* in_sizes, int n_in,
                              void* d_out, int out_size){
    const float* z        = (const float*)d_in[0];
    const float* frames   = (const float*)d_in[1];
    const int*   actions  = (const int*)  d_in[2];
    const int*   ts       = (const int*)  d_in[3];
    const float* W_patch  = (const float*)d_in[4];
    const float* b_patch  = (const float*)d_in[5];
    const float* W_unpatch= (const float*)d_in[6];
    const float* b_unpatch= (const float*)d_in[7];
    const float* registers= (const float*)d_in[8];
    const float* pe_grid  = (const float*)d_in[9];
    const float* action_e = (const float*)d_in[10];
    const float* time_emb = (const float*)d_in[11];
    const float* W_mod1   = (const float*)d_in[12];
    const float* b_mod1   = (const float*)d_in[13];
    const float* W_mod2   = (const float*)d_in[14];
    const float* b_mod2   = (const float*)d_in[15];
    const float* W_q      = (const float*)d_in[16];
    const float* b_q      = (const float*)d_in[17];
    const float* W_k      = (const float*)d_in[18];
    const float* b_k      = (const float*)d_in[19];
    const float* W_v      = (const float*)d_in[20];
    const float* b_v      = (const float*)d_in[21];
    const float* W_o      = (const float*)d_in[22];
    const float* b_o      = (const float*)d_in[23];
    const float* W_g1     = (const float*)d_in[24];
    const float* b_g1     = (const float*)d_in[25];
    const float* W_g2     = (const float*)d_in[26];
    const float* b_g2     = (const float*)d_in[27];
    const float* W_geglu  = (const float*)d_in[28];
    const float* b_geglu  = (const float*)d_in[29];
    const float* W_ffout  = (const float*)d_in[30];
    const float* b_ffout  = (const float*)d_in[31];
    float* out = (float*)d_out;

    float* pState = symaddr<float>(g_state);
    float* pQKV   = symaddr<float>(g_qkv);
    float* pAtto  = symaddr<float>(g_atto);
    float* pBqkv  = symaddr<float>(g_bqkv);
    float* pBgg   = symaddr<float>(g_bgg2);
    __nv_bfloat16* nh = symaddr<__nv_bfloat16>(g_nh);
    __nv_bfloat16* nl = symaddr<__nv_bfloat16>(g_nl);
    __nv_bfloat16* xh = symaddr<__nv_bfloat16>(g_xh);
    __nv_bfloat16* xl = symaddr<__nv_bfloat16>(g_xl);
    __nv_bfloat16* yh = symaddr<__nv_bfloat16>(g_yh);
    __nv_bfloat16* yl = symaddr<__nv_bfloat16>(g_yl);
    __nv_bfloat16* wqkvh = symaddr<__nv_bfloat16>(g_wqkv_h);
    __nv_bfloat16* wqkvl = symaddr<__nv_bfloat16>(g_wqkv_l);
    __nv_bfloat16* woh   = symaddr<__nv_bfloat16>(g_wo_h);
    __nv_bfloat16* wol   = symaddr<__nv_bfloat16>(g_wo_l);
    __nv_bfloat16* wggh  = symaddr<__nv_bfloat16>(g_wgg_h);
    __nv_bfloat16* wggl  = symaddr<__nv_bfloat16>(g_wgg_l);
    __nv_bfloat16* wffh  = symaddr<__nv_bfloat16>(g_wff_h);
    __nv_bfloat16* wffl  = symaddr<__nv_bfloat16>(g_wff_l);

    cudaFuncSetAttribute(gemm_mma, cudaFuncAttributeMaxDynamicSharedMemorySize, 2*BUFSZ);

    cond_kernel<<<7, 128>>>(ts, time_emb);
    modvec_kernel<<<dim3(NBLK*7, 12), 256>>>(W_mod1, b_mod1, W_mod2, b_mod2,
                                             W_g1, b_g1, W_g2, b_g2);
    embed_kernel<<<NTOK, 128>>>(z, frames, actions, W_patch, b_patch,
                                registers, pe_grid, action_e);

    dim3 tb(32, 8);
    for (int i = 0; i < NBLK; i++){
        size_t w512 = (size_t)i*512*512;
        transp_split<<<dim3(16,16), tb>>>(W_q + w512, wqkvh + ((size_t)i*QKVD       )*512, wqkvl + ((size_t)i*QKVD       )*512, 512, 512, 0);
        transp_split<<<dim3(16,16), tb>>>(W_k + w512, wqkvh + ((size_t)i*QKVD +  512)*512, wqkvl + ((size_t)i*QKVD +  512)*512, 512, 512, 0);
        transp_split<<<dim3(16,16), tb>>>(W_v + w512, wqkvh + ((size_t)i*QKVD + 1024)*512, wqkvl + ((size_t)i*QKVD + 1024)*512, 512, 512, 0);
        transp_split<<<dim3(16,16), tb>>>(W_o + w512, woh + w512, wol + w512, 512, 512, 0);
        transp_split<<<dim3(128,16), tb>>>(W_geglu + (size_t)i*512*4096, wggh + (size_t)i*4096*512, wggl + (size_t)i*4096*512, 512, 4096, 1);
        transp_split<<<dim3(16,64), tb>>>(W_ffout + (size_t)i*2048*512, wffh + (size_t)i*512*2048, wffl + (size_t)i*512*2048, 2048, 512, 0);
    }
    prep_bias<<<NBLK, 256>>>(b_q, b_k, b_v, b_geglu);

    int mt = (NTOK + 127) / 128;   // 23
    for (int i = 0; i < NBLK; i++){
        mod_kernel<<<NTOK, 128>>>(i);
        gemm_mma<<<dim3(QKVD/128, mt), 256, 2*BUFSZ>>>(nh, nl,
            wqkvh + (size_t)i*QKVD*512, wqkvl + (size_t)i*QKVD*512,
            pBqkv + i*QKVD, pQKV, nullptr, nullptr, NTOK, QKVD, 512, 0, i);
        attn_kernel<<<dim3(11*QGRP, NHh), 128>>>(pQKV);
        gemm_mma<<<dim3(4, mt), 256, 2*BUFSZ>>>(xh, xl,
            woh + (size_t)i*512*512, wol + (size_t)i*512*512,
            b_o + i*512, pAtto, nullptr, nullptr, NTOK, 512, 512, 0, i);
        postattn_kernel<<<NTOK, 128>>>(i);
        gemm_mma<<<dim3(32, mt), 256, 2*BUFSZ>>>(xh, xl,
            wggh + (size_t)i*4096*512, wggl + (size_t)i*4096*512,
            pBgg + i*4096, nullptr, yh, yl, NTOK, 4096, 512, 1, i);
        gemm_mma<<<dim3(4, mt), 256, 2*BUFSZ>>>(yh, yl,
            wffh + (size_t)i*512*2048, wffl + (size_t)i*512*2048,
            b_ffout + i*512, pState, nullptr, nullptr, NTOK, 512, 2048, 2, i);
    }
    unpatch_kernel<<<1536, 128>>>(W_unpatch, b_unpatch, out);
}

// round 11
// speedup vs baseline: 4.0540x; 3.1130x over previous
#include <cuda_runtime.h>
#include <cuda_bf16.h>
#include <cstdint>
#include <math.h>

// ---------------- problem constants ----------------
#define Dm    512
#define NHh   8
#define DH    64
#define NBLK  6
#define SEQ   257
#define NZR   1542
#define NXA   1285
#define NTOK  2827
#define HIDm  2048
#define QKVD  1536

// ---------------- scratch ----------------
__device__ float g_state[NTOK*Dm];
__device__ float g_qkv  [NTOK*QKVD];
__device__ float g_atto [NTOK*Dm];

__device__ __nv_bfloat16 g_nh[NTOK*Dm];     // norm split
__device__ __nv_bfloat16 g_nl[NTOK*Dm];
__device__ __nv_bfloat16 g_xh[NTOK*Dm];     // att / h split
__device__ __nv_bfloat16 g_xl[NTOK*Dm];
__device__ __nv_bfloat16 g_yh[NTOK*HIDm];   // act split
__device__ __nv_bfloat16 g_yl[NTOK*HIDm];

__device__ float g_cond [7*Dm];
__device__ float g_silu [7*Dm];
__device__ float g_m1   [NBLK*7*1024];
__device__ float g_m2   [NBLK*7*1024];
__device__ float g_ga   [NBLK*7*Dm];
__device__ float g_gb   [NBLK*7*Dm];

// pre-transposed, split weights (row = output col n, K contiguous)
__device__ __nv_bfloat16 g_wqkv_h[NBLK*QKVD*Dm];
__device__ __nv_bfloat16 g_wqkv_l[NBLK*QKVD*Dm];
__device__ __nv_bfloat16 g_wo_h  [NBLK*Dm*Dm];
__device__ __nv_bfloat16 g_wo_l  [NBLK*Dm*Dm];
__device__ __nv_bfloat16 g_wgg_h [NBLK*2*HIDm*Dm];
__device__ __nv_bfloat16 g_wgg_l [NBLK*2*HIDm*Dm];
__device__ __nv_bfloat16 g_wff_h [NBLK*Dm*HIDm];
__device__ __nv_bfloat16 g_wff_l [NBLK*Dm*HIDm];
__device__ float g_bqkv[NBLK*QKVD];
__device__ float g_bgg2[NBLK*2*HIDm];

// ---------------- helpers ----------------
__device__ __forceinline__ uint32_t smem_u32(const void* p){
    uint32_t a;
    asm("{ .reg .u64 t; cvta.to.shared.u64 t, %1; cvt.u32.u64 %0, t; }" : "=r"(a) : "l"(p));
    return a;
}
#define SW128(off) ((off) ^ (((off)>>3) & 0x70))

__device__ __forceinline__ void ldsm4(uint32_t* r, uint32_t addr){
    asm volatile("ldmatrix.sync.aligned.m8n8.x4.shared.b16 {%0,%1,%2,%3}, [%4];"
        : "=r"(r[0]), "=r"(r[1]), "=r"(r[2]), "=r"(r[3]) : "r"(addr));
}
__device__ __forceinline__ void ldsm4t(uint32_t* r, uint32_t addr){
    asm volatile("ldmatrix.sync.aligned.m8n8.x4.trans.shared.b16 {%0,%1,%2,%3}, [%4];"
        : "=r"(r[0]), "=r"(r[1]), "=r"(r[2]), "=r"(r[3]) : "r"(addr));
}
__device__ __forceinline__ void mma_bf16(float* d, const uint32_t* a, uint32_t b0, uint32_t b1){
    asm volatile("mma.sync.aligned.m16n8k16.row.col.f32.bf16.bf16.f32 "
        "{%0,%1,%2,%3}, {%4,%5,%6,%7}, {%8,%9}, {%0,%1,%2,%3};"
        : "+f"(d[0]), "+f"(d[1]), "+f"(d[2]), "+f"(d[3])
        : "r"(a[0]), "r"(a[1]), "r"(a[2]), "r"(a[3]), "r"(b0), "r"(b1));
}

__device__ __forceinline__ float warpSum(float v){
    #pragma unroll
    for (int o = 16; o > 0; o >>= 1) v += __shfl_xor_sync(0xffffffffu, v, o);
    return v;
}
__device__ __forceinline__ void blockReduce2(float& s, float& q){
    s = warpSum(s); q = warpSum(q);
    __shared__ float sh[8];
    int w = threadIdx.x >> 5;
    if ((threadIdx.x & 31) == 0) { sh[w] = s; sh[4+w] = q; }
    __syncthreads();
    s = sh[0]+sh[1]+sh[2]+sh[3];
    q = sh[4]+sh[5]+sh[6]+sh[7];
    __syncthreads();
}
__device__ __forceinline__ int frame_class(int t){ return (t < NZR) ? (t / SEQ) : 6; }

__device__ __forceinline__ void split2(float x, float y, uint32_t& h, uint32_t& l){
    __nv_bfloat16 hx = __float2bfloat16(x), hy = __float2bfloat16(y);
    __nv_bfloat16 lx = __float2bfloat16(x - __bfloat162float(hx));
    __nv_bfloat16 ly = __float2bfloat16(y - __bfloat162float(hy));
    h = (uint32_t)__bfloat16_as_ushort(hx) | ((uint32_t)__bfloat16_as_ushort(hy) << 16);
    l = (uint32_t)__bfloat16_as_ushort(lx) | ((uint32_t)__bfloat16_as_ushort(ly) << 16);
}
__device__ __forceinline__ uint2 pack4h(float4 v){
    __nv_bfloat16 a = __float2bfloat16(v.x), b = __float2bfloat16(v.y);
    __nv_bfloat16 c = __float2bfloat16(v.z), d = __float2bfloat16(v.w);
    return make_uint2((uint32_t)__bfloat16_as_ushort(a) | ((uint32_t)__bfloat16_as_ushort(b) << 16),
                      (uint32_t)__bfloat16_as_ushort(c) | ((uint32_t)__bfloat16_as_ushort(d) << 16));
}

// ---------------- conditioning ----------------
__global__ void cond_kernel(const int* __restrict__ ts, const float* __restrict__ time_emb){
    int c = blockIdx.x;
    int row = (c < 6) ? ts[c] : 0;
    for (int d = threadIdx.x; d < Dm; d += blockDim.x){
        float x = time_emb[row*Dm + d];
        g_cond[c*Dm + d] = x;
        g_silu[c*Dm + d] = x / (1.0f + expf(-x));
    }
}

__global__ void modvec_kernel(const float* __restrict__ Wm1, const float* __restrict__ bm1,
                              const float* __restrict__ Wm2, const float* __restrict__ bm2,
                              const float* __restrict__ Wg1, const float* __restrict__ bg1,
                              const float* __restrict__ Wg2, const float* __restrict__ bg2){
    int ic = blockIdx.x;
    int i  = ic / 7, c = ic % 7;
    int j  = blockIdx.y * 256 + threadIdx.x;
    __shared__ float vs[Dm], vp[Dm];
    for (int k = threadIdx.x; k < Dm; k += 256){
        vs[k] = g_silu[c*Dm + k];
        vp[k] = g_cond[c*Dm + k];
    }
    __syncthreads();
    const float* W; const float* b; float* out; int nd; const float* v; int col;
    if (j < 1024)      { W = Wm1 + i*Dm*1024; b = bm1 + i*1024; out = g_m1 + ic*1024; nd = 1024; v = vs; col = j; }
    else if (j < 2048) { W = Wm2 + i*Dm*1024; b = bm2 + i*1024; out = g_m2 + ic*1024; nd = 1024; v = vs; col = j - 1024; }
    else if (j < 2560) { W = Wg1 + i*Dm*Dm;   b = bg1 + i*Dm;   out = g_ga + ic*Dm;   nd = Dm;   v = vp; col = j - 2048; }
    else               { W = Wg2 + i*Dm*Dm;   b = bg2 + i*Dm;   out = g_gb + ic*Dm;   nd = Dm;   v = vp; col = j - 2560; }
    float acc = b[col];
    #pragma unroll 8
    for (int k = 0; k < Dm; k++) acc += v[k] * W[k*nd + col];
    out[col] = acc;
}

// ---------------- embed ----------------
__global__ void embed_kernel(const float* __restrict__ z, const float* __restrict__ frames,
                             const int* __restrict__ actions,
                             const float* __restrict__ Wp, const float* __restrict__ bp,
                             const float* __restrict__ regs, const float* __restrict__ pe,
                             const float* __restrict__ aemb){
    int t = blockIdx.x;
    int tid = threadIdx.x;
    int f, s;
    const float* img;
    const float* special = nullptr;
    if (t < NZR) {
        f = t / SEQ; s = t % SEQ; img = z;
        if (s == SEQ-1) special = regs;
    } else {
        int u = t - NZR; f = u / SEQ; s = u % SEQ; img = frames;
        if (s == SEQ-1) special = aemb + actions[f]*Dm;
    }
    if (special){
        for (int d = tid; d < Dm; d += 128) g_state[t*Dm + d] = special[d];
        return;
    }
    __shared__ float pv[12];
    if (tid < 12){
        int c = tid >> 2, ph = (tid >> 1) & 1, pw = tid & 1;
        int h2 = s >> 4, w2 = s & 15;
        pv[tid] = img[f*3072 + c*1024 + (h2*2 + ph)*32 + (w2*2 + pw)];
    }
    __syncthreads();
    for (int d = tid; d < Dm; d += 128){
        float acc = bp[d] + pe[s*Dm + d];
        #pragma unroll
        for (int jj = 0; jj < 12; jj++) acc += pv[jj] * Wp[jj*Dm + d];
        g_state[t*Dm + d] = acc;
    }
}

// ---------------- weight prep (batched over DiT blocks via blockIdx.z) ----------------
__global__ void transp_split(const float* __restrict__ in, __nv_bfloat16* __restrict__ ohi,
                             __nv_bfloat16* __restrict__ olo, int K, int N, int il,
                             size_t inz, size_t outz){
    in  += (size_t)blockIdx.z * inz;
    ohi += (size_t)blockIdx.z * outz;
    olo += (size_t)blockIdx.z * outz;
    __shared__ float t[32][33];
    int r0 = blockIdx.x*32, k0 = blockIdx.y*32;
    int tx = threadIdx.x, ty = threadIdx.y;
    int u0 = r0 >> 1;
    for (int i = ty; i < 32; i += 8){
        int col = il ? ((tx < 16) ? (u0 + tx) : (HIDm + u0 + tx - 16)) : (r0 + tx);
        t[i][tx] = in[(size_t)(k0 + i)*N + col];
    }
    __syncthreads();
    for (int j = ty; j < 32; j += 8){
        int ci = il ? ((j>>1) + ((j&1)?16:0)) : j;
        float v = t[tx][ci];
        __nv_bfloat16 h = __float2bfloat16(v);
        __nv_bfloat16 l = __float2bfloat16(v - __bfloat162float(h));
        size_t o = (size_t)(r0 + j)*K + k0 + tx;
        ohi[o] = h; olo[o] = l;
    }
}

__global__ void prep_bias(const float* __restrict__ bq, const float* __restrict__ bk,
                          const float* __restrict__ bv, const float* __restrict__ bgg){
    int i = blockIdx.x;
    for (int j = threadIdx.x; j < QKVD; j += 256){
        float v = (j < 512) ? bq[i*512 + j] : (j < 1024) ? bk[i*512 + j - 512] : bv[i*512 + j - 1024];
        g_bqkv[i*QKVD + j] = v;
    }
    for (int p = threadIdx.x; p < 2*HIDm; p += 256){
        int u = p >> 1;
        g_bgg2[i*2*HIDm + p] = (p & 1) ? bgg[i*2*HIDm + HIDm + u] : bgg[i*2*HIDm + u];
    }
}

// ---------------- AdaLN mod1: state -> nh/nl split ----------------
__global__ void mod_kernel(int blk){
    int t = blockIdx.x, tid = threadIdx.x;
    int c = frame_class(t);
    float4 v = ((const float4*)(g_state + (size_t)t*Dm))[tid];
    float s = v.x+v.y+v.z+v.w;
    float q = v.x*v.x + v.y*v.y + v.z*v.z + v.w*v.w;
    blockReduce2(s, q);
    float mu  = s * (1.0f/Dm);
    float var = q * (1.0f/Dm) - mu*mu;
    float rstd = rsqrtf(var + 1e-5f);
    const float* ms = g_m1 + (blk*7 + c)*1024;
    int d = tid*4;
    float o0 = (v.x-mu)*rstd*(1.0f+ms[d+0]) + ms[512+d+0];
    float o1 = (v.y-mu)*rstd*(1.0f+ms[d+1]) + ms[512+d+1];
    float o2 = (v.z-mu)*rstd*(1.0f+ms[d+2]) + ms[512+d+2];
    float o3 = (v.w-mu)*rstd*(1.0f+ms[d+3]) + ms[512+d+3];
    uint32_t h0,l0,h1,l1;
    split2(o0,o1,h0,l0); split2(o2,o3,h1,l1);
    ((uint2*)(g_nh + (size_t)t*Dm))[tid] = make_uint2(h0,h1);
    ((uint2*)(g_nl + (size_t)t*Dm))[tid] = make_uint2(l0,l1);
}

// ---------------- post-attn: h = mod2( norm*g1 + atto ) -> xh/xl ----------------
__global__ void postattn_kernel(int blk){
    int t = blockIdx.x, tid = threadIdx.x;
    int c = frame_class(t);
    const float* g1v = g_ga + (blk*7 + c)*Dm;
    float4 a = ((const float4*)(g_atto + (size_t)t*Dm))[tid];
    int d = tid*4;
    const __nv_bfloat16* nh = g_nh + (size_t)t*Dm + d;
    const __nv_bfloat16* nl = g_nl + (size_t)t*Dm + d;
    float n0 = __bfloat162float(nh[0]) + __bfloat162float(nl[0]);
    float n1 = __bfloat162float(nh[1]) + __bfloat162float(nl[1]);
    float n2 = __bfloat162float(nh[2]) + __bfloat162float(nl[2]);
    float n3 = __bfloat162float(nh[3]) + __bfloat162float(nl[3]);
    float4 v;
    v.x = n0*g1v[d+0] + a.x;
    v.y = n1*g1v[d+1] + a.y;
    v.z = n2*g1v[d+2] + a.z;
    v.w = n3*g1v[d+3] + a.w;
    float s = v.x+v.y+v.z+v.w;
    float q = v.x*v.x + v.y*v.y + v.z*v.z + v.w*v.w;
    blockReduce2(s, q);
    float mu  = s * (1.0f/Dm);
    float var = q * (1.0f/Dm) - mu*mu;
    float rstd = rsqrtf(var + 1e-5f);
    const float* ms = g_m2 + (blk*7 + c)*1024;
    float o0 = (v.x-mu)*rstd*(1.0f+ms[d+0]) + ms[512+d+0];
    float o1 = (v.y-mu)*rstd*(1.0f+ms[d+1]) + ms[512+d+1];
    float o2 = (v.z-mu)*rstd*(1.0f+ms[d+2]) + ms[512+d+2];
    float o3 = (v.w-mu)*rstd*(1.0f+ms[d+3]) + ms[512+d+3];
    uint32_t h0,l0,h1,l1;
    split2(o0,o1,h0,l0); split2(o2,o3,h1,l1);
    ((uint2*)(g_xh + (size_t)t*Dm))[tid] = make_uint2(h0,h1);
    ((uint2*)(g_xl + (size_t)t*Dm))[tid] = make_uint2(l0,l1);
}

// ---------------- bf16 split GEMM on mma.sync (HMMA), templated M-tile ----------------
// C[M,N] += A @ B^T with A = Ah+Al ([M][K] bf16 split), B rows = out cols ([N][K] split).
// mode 0: C fp32 = acc + bias
// mode 1: GEGLU interleaved: out[m][u] = (a+ba)*gelu(g+bg), split bf16 into Oh/Ol (stride HIDm)
// mode 2: C fp32 = (acc + bias) * g_gb
template<int BM>
__global__ __launch_bounds__(BM*2) void gemm_mma_t(
    const __nv_bfloat16* __restrict__ Ah, const __nv_bfloat16* __restrict__ Al,
    const __nv_bfloat16* __restrict__ Bh, const __nv_bfloat16* __restrict__ Bl,
    const float* __restrict__ bias, float* __restrict__ C,
    __nv_bfloat16* __restrict__ Oh, __nv_bfloat16* __restrict__ Ol,
    int M, int N, int K, int mode, int blk)
{
    constexpr int T   = BM*2;
    constexpr int ASZ = BM*128;          // bytes of one A tile (BM x 64 bf16)
    constexpr int BUF = 2*ASZ + 32768;
    extern __shared__ char smem[];
    uint32_t sb = smem_u32(smem);
    int tid = threadIdx.x, lane = tid & 31, wid = tid >> 5;
    int bm = blockIdx.y * BM, bn = blockIdx.x * 128;
    int wm = wid >> 1, wn = wid & 1;
    int lr = lane & 7, mid = lane >> 3;

    float acc[2][8][4];
    #pragma unroll
    for (int i=0;i<2;i++)
        #pragma unroll
        for (int j=0;j<8;j++)
            #pragma unroll
            for (int k=0;k<4;k++) acc[i][j][k] = 0.f;

    auto load_chunk = [&](int cc, int buf){
        int kc = cc << 6;
        uint32_t sbase = sb + buf*BUF;
        #pragma unroll
        for (int p = 0; p < BM*8/T; p++){
            int idx = p*T + tid;
            int r = idx >> 3, ch = idx & 7;
            uint32_t so = SW128((uint32_t)(r*128 + ch*16));
            int row = bm + r;
            size_t aoff = (size_t)((row < M) ? row : (M-1))*K + kc + ch*8;
            uint32_t pr = (row < M) ? 16u : 0u;
            asm volatile("cp.async.cg.shared.global [%0], [%1], 16, %2;" :: "r"(sbase + so),       "l"(Ah + aoff), "r"(pr));
            asm volatile("cp.async.cg.shared.global [%0], [%1], 16, %2;" :: "r"(sbase + ASZ + so), "l"(Al + aoff), "r"(pr));
        }
        #pragma unroll
        for (int p = 0; p < 1024/T; p++){
            int idx = p*T + tid;
            int r = idx >> 3, ch = idx & 7;
            uint32_t so = SW128((uint32_t)(r*128 + ch*16));
            size_t boff = (size_t)(bn + r)*K + kc + ch*8;
            asm volatile("cp.async.cg.shared.global [%0], [%1], 16;" :: "r"(sbase + 2*ASZ + so),         "l"(Bh + boff));
            asm volatile("cp.async.cg.shared.global [%0], [%1], 16;" :: "r"(sbase + 2*ASZ + 16384 + so), "l"(Bl + boff));
        }
        asm volatile("cp.async.commit_group;" ::: "memory");
    };

    int nchunk = K >> 6;
    load_chunk(0, 0);
    for (int c = 0; c < nchunk; c++){
        int buf = c & 1;
        if (c + 1 < nchunk){
            load_chunk(c + 1, buf ^ 1);
            asm volatile("cp.async.wait_group 1;" ::: "memory");
        } else {
            asm volatile("cp.async.wait_group 0;" ::: "memory");
        }
        __syncthreads();
        uint32_t abase = sb + buf*BUF;
        uint32_t bbase = abase + 2*ASZ;
        #pragma unroll
        for (int ks = 0; ks < 4; ks++){
            uint32_t ah[2][4], al[2][4];
            #pragma unroll
            for (int mf = 0; mf < 2; mf++){
                int row = wm*32 + mf*16 + (mid & 1)*8 + lr;
                uint32_t off = SW128((uint32_t)(row*128 + (ks*2 + (mid >> 1))*16));
                ldsm4(ah[mf], abase + off);
                ldsm4(al[mf], abase + ASZ + off);
            }
            uint32_t bh[4][4], bl[4][4];
            #pragma unroll
            for (int np = 0; np < 4; np++){
                int row = wn*64 + np*16 + (mid >> 1)*8 + lr;
                uint32_t off = SW128((uint32_t)(row*128 + (ks*2 + (mid & 1))*16));
                ldsm4(bh[np], bbase + off);
                ldsm4(bl[np], bbase + 16384 + off);
            }
            #pragma unroll
            for (int mf = 0; mf < 2; mf++){
                #pragma unroll
                for (int nf = 0; nf < 8; nf++){
                    uint32_t* ph = &bh[nf >> 1][(nf & 1)*2];
                    uint32_t* pl = &bl[nf >> 1][(nf & 1)*2];
                    mma_bf16(acc[mf][nf], ah[mf], ph[0], ph[1]);
                    mma_bf16(acc[mf][nf], ah[mf], pl[0], pl[1]);
                    mma_bf16(acc[mf][nf], al[mf], ph[0], ph[1]);
                }
            }
        }
        __syncthreads();
    }

    // epilogue
    #pragma unroll
    for (int mf = 0; mf < 2; mf++){
        int m0 = bm + wm*32 + mf*16 + (lane >> 2);
        #pragma unroll
        for (int half = 0; half < 2; half++){
            int m = m0 + half*8;
            if (m >= M) continue;
            #pragma unroll
            for (int nf = 0; nf < 8; nf++){
                float d0 = acc[mf][nf][half*2 + 0];
                float d1 = acc[mf][nf][half*2 + 1];
                int c0 = bn + wn*64 + nf*8 + (lane & 3)*2;
                if (mode == 0){
                    float2 o = make_float2(d0 + bias[c0], d1 + bias[c0+1]);
                    *(float2*)(C + (size_t)m*N + c0) = o;
                } else if (mode == 1){
                    float a = d0 + bias[c0];
                    float g = d1 + bias[c0+1];
                    float ge = 0.5f*g*(1.0f + erff(g*0.70710678118654752440f));
                    float v = a*ge;
                    int u = c0 >> 1;
                    __nv_bfloat16 hh = __float2bfloat16(v);
                    __nv_bfloat16 ll = __float2bfloat16(v - __bfloat162float(hh));
                    Oh[(size_t)m*HIDm + u] = hh;
                    Ol[(size_t)m*HIDm + u] = ll;
                } else {
                    const float* gv = g_gb + (blk*7 + frame_class(m))*Dm;
                    float2 o;
                    o.x = (d0 + bias[c0])   * gv[c0];
                    o.y = (d1 + bias[c0+1]) * gv[c0+1];
                    *(float2*)(C + (size_t)m*N + c0) = o;
                }
            }
        }
    }
}

// ---------------- flash attention (HMMA), 64 queries x 64-key blocks ----------------
// grid: (11 frames, 5 qtiles, 8 heads), 128 threads (4 warps x 16 q rows)
// Shared memory is ONE 128B-aligned buffer carved into Qh/Ql/K/V (8KB each) so
// every ldmatrix / SW128 base is guaranteed aligned.
__global__ __launch_bounds__(128) void fattn(const float* __restrict__ QKV){
    int frame = blockIdx.x, qt = blockIdx.y, h = blockIdx.z;
    int qbase, r0s, r0n, r1s, r1n;
    if (frame < 6){
        qbase = frame*SEQ;
        r0s = frame*SEQ;              r0n = SEQ;
        int lo = frame-4; if (lo < 0) lo = 0;
        r1s = NZR + lo*SEQ;           r1n = (frame - lo)*SEQ;
    } else {
        int f = frame - 6;
        qbase = NZR + f*SEQ;
        r0s = NZR;                    r0n = (f+1)*SEQ;
        r1s = 0;                      r1n = 0;
    }
    int nk = r0n + r1n;
    int q0 = qt*64;
    int nq = SEQ - q0; if (nq > 64) nq = 64;   // qt=4 -> nq=1

    __shared__ __align__(128) char sbuf[32768];
    char* sQh = sbuf;
    char* sQl = sbuf + 8192;
    char* sKc = sbuf + 16384;
    char* sVc = sbuf + 24576;
    uint32_t bQh = smem_u32(sQh), bQl = smem_u32(sQl), bK = smem_u32(sKc), bV = smem_u32(sVc);
    int tid = threadIdx.x, lane = tid & 31, wid = tid >> 5;
    int lr = lane & 7, mid = lane >> 3;

    // load Q tile, split hi/lo
    for (int idx = tid; idx < 1024; idx += 128){
        int r = idx >> 4, c4 = idx & 15;
        int rr = (r < nq) ? r : (nq-1);
        float4 v = *(const float4*)(QKV + (size_t)(qbase + q0 + rr)*QKVD + h*DH + c4*4);
        uint32_t h0,l0,h1,l1;
        split2(v.x, v.y, h0, l0); split2(v.z, v.w, h1, l1);
        uint32_t off = SW128((uint32_t)(r*128 + c4*8));
        *(uint2*)(sQh + off) = make_uint2(h0,h1);
        *(uint2*)(sQl + off) = make_uint2(l0,l1);
    }
    __syncthreads();
    uint32_t qh[4][4], ql[4][4];
    #pragma unroll
    for (int ks = 0; ks < 4; ks++){
        uint32_t off = SW128((uint32_t)((wid*16 + (mid&1)*8 + lr)*128 + (ks*2 + (mid>>1))*16));
        ldsm4(qh[ks], bQh + off);
        ldsm4(ql[ks], bQl + off);
    }

    float o[8][4];
    #pragma unroll
    for (int j=0;j<8;j++){ o[j][0]=0.f;o[j][1]=0.f;o[j][2]=0.f;o[j][3]=0.f; }
    float m0=-1e30f, m1=-1e30f, l0=0.f, l1=0.f;

    int nkb = (nk + 63) >> 6;
    for (int kb = 0; kb < nkb; kb++){
        int k0 = kb << 6;
        __syncthreads();
        for (int idx = tid; idx < 1024; idx += 128){
            int r = idx >> 4, c4 = idx & 15;
            int i = k0 + r;
            int g = (i < r0n) ? (r0s + i) : ((i < nk) ? (r1s + i - r0n) : r0s);
            const float* base = QKV + (size_t)g*QKVD + h*DH + c4*4;
            float4 kv = *(const float4*)(base + 512);
            float4 vv = *(const float4*)(base + 1024);
            uint32_t off = SW128((uint32_t)(r*128 + c4*8));
            *(uint2*)(sKc + off) = pack4h(kv);
            *(uint2*)(sVc + off) = pack4h(vv);
        }
        __syncthreads();

        // S = Q K^T  (split Q: 2 mmas)
        float s[8][4];
        #pragma unroll
        for (int j=0;j<8;j++){ s[j][0]=0.f;s[j][1]=0.f;s[j][2]=0.f;s[j][3]=0.f; }
        #pragma unroll
        for (int ks = 0; ks < 4; ks++){
            #pragma unroll
            for (int np = 0; np < 4; np++){
                uint32_t bk[4];
                uint32_t off = SW128((uint32_t)((np*16 + (mid>>1)*8 + lr)*128 + (ks*2 + (mid&1))*16));
                ldsm4(bk, bK + off);
                mma_bf16(s[np*2],   qh[ks], bk[0], bk[1]);
                mma_bf16(s[np*2],   ql[ks], bk[0], bk[1]);
                mma_bf16(s[np*2+1], qh[ks], bk[2], bk[3]);
                mma_bf16(s[np*2+1], ql[ks], bk[2], bk[3]);
            }
        }
        // online softmax
        float mx0 = -1e30f, mx1 = -1e30f;
        #pragma unroll
        for (int j = 0; j < 8; j++){
            int c = k0 + j*8 + (lane & 3)*2;
            s[j][0] = (c   < nk) ? s[j][0]*0.125f : -1e30f;
            s[j][1] = (c+1 < nk) ? s[j][1]*0.125f : -1e30f;
            s[j][2] = (c   < nk) ? s[j][2]*0.125f : -1e30f;
            s[j][3] = (c+1 < nk) ? s[j][3]*0.125f : -1e30f;
            mx0 = fmaxf(mx0, fmaxf(s[j][0], s[j][1]));
            mx1 = fmaxf(mx1, fmaxf(s[j][2], s[j][3]));
        }
        mx0 = fmaxf(mx0, __shfl_xor_sync(0xffffffffu, mx0, 1));
        mx0 = fmaxf(mx0, __shfl_xor_sync(0xffffffffu, mx0, 2));
        mx1 = fmaxf(mx1, __shfl_xor_sync(0xffffffffu, mx1, 1));
        mx1 = fmaxf(mx1, __shfl_xor_sync(0xffffffffu, mx1, 2));
        float mn0 = fmaxf(m0, mx0), mn1 = fmaxf(m1, mx1);
        float f0 = __expf(m0 - mn0), f1 = __expf(m1 - mn1);
        m0 = mn0; m1 = mn1;
        l0 *= f0; l1 *= f1;
        #pragma unroll
        for (int j=0;j<8;j++){ o[j][0]*=f0; o[j][1]*=f0; o[j][2]*=f1; o[j][3]*=f1; }
        uint32_t ph[8][2], pl[8][2];
        #pragma unroll
        for (int j = 0; j < 8; j++){
            float p0 = __expf(s[j][0]-m0), p1 = __expf(s[j][1]-m0);
            float p2 = __expf(s[j][2]-m1), p3 = __expf(s[j][3]-m1);
            l0 += p0 + p1; l1 += p2 + p3;
            split2(p0, p1, ph[j][0], pl[j][0]);
            split2(p2, p3, ph[j][1], pl[j][1]);
        }
        // O += P V  (split P: 2 mmas)
        #pragma unroll
        for (int ks = 0; ks < 4; ks++){
            uint32_t ah[4] = {ph[2*ks][0], ph[2*ks][1], ph[2*ks+1][0], ph[2*ks+1][1]};
            uint32_t al[4] = {pl[2*ks][0], pl[2*ks][1], pl[2*ks+1][0], pl[2*ks+1][1]};
            #pragma unroll
            for (int vd = 0; vd < 4; vd++){
                uint32_t bv[4];
                uint32_t off = SW128((uint32_t)((ks*16 + (lane & 15))*128 + vd*32 + (lane >> 4)*16));
                ldsm4t(bv, bV + off);
                mma_bf16(o[vd*2],   ah, bv[0], bv[1]);
                mma_bf16(o[vd*2],   al, bv[0], bv[1]);
                mma_bf16(o[vd*2+1], ah, bv[2], bv[3]);
                mma_bf16(o[vd*2+1], al, bv[2], bv[3]);
            }
        }
    }
    l0 += __shfl_xor_sync(0xffffffffu, l0, 1);
    l0 += __shfl_xor_sync(0xffffffffu, l0, 2);
    l1 += __shfl_xor_sync(0xffffffffu, l1, 1);
    l1 += __shfl_xor_sync(0xffffffffu, l1, 2);
    float i0 = 1.0f/l0, i1 = 1.0f/l1;
    int row0 = wid*16 + (lane >> 2);
    #pragma unroll
    for (int j = 0; j < 8; j++){
        int c = j*8 + (lane & 3)*2;
        if (row0 < nq){
            size_t idx = (size_t)(qbase + q0 + row0)*Dm + h*DH + c;
            uint32_t hh, ll;
            split2(o[j][0]*i0, o[j][1]*i0, hh, ll);
            *(uint32_t*)(g_xh + idx) = hh;
            *(uint32_t*)(g_xl + idx) = ll;
        }
        if (row0 + 8 < nq){
            size_t idx = (size_t)(qbase + q0 + row0 + 8)*Dm + h*DH + c;
            uint32_t hh, ll;
            split2(o[j][2]*i1, o[j][3]*i1, hh, ll);
            *(uint32_t*)(g_xh + idx) = hh;
            *(uint32_t*)(g_xl + idx) = ll;
        }
    }
}

// ---------------- unpatch ----------------
__global__ void unpatch_kernel(const float* __restrict__ Wu, const float* __restrict__ bu,
                               float* __restrict__ out){
    int token = blockIdx.x;
    int f = token >> 8, s = token & 255;
    const float* x = g_state + (size_t)(f*SEQ + s)*Dm;
    __shared__ float xs[Dm];
    int tid = threadIdx.x;
    for (int d2 = tid; d2 < Dm; d2 += 128) xs[d2] = x[d2];
    __syncthreads();
    int warp = tid >> 5, lane = tid & 31;
    for (int j = warp; j < 12; j += 4){
        float acc = 0.f;
        for (int d2 = lane; d2 < Dm; d2 += 32) acc += xs[d2] * Wu[d2*12 + j];
        acc = warpSum(acc);
        if (lane == 0){
            int c = j >> 2, ph = (j >> 1) & 1, pw = j & 1;
            int h2 = s >> 4, w2 = s & 15;
            out[f*3072 + c*1024 + (h2*2 + ph)*32 + (w2*2 + pw)] = acc + bu[j];
        }
    }
}

// ---------------- host ----------------
template <typename T>
static T* symaddr(const void* sym){
    void* p = nullptr;
    cudaGetSymbolAddress(&p, sym);
    return (T*)p;
}

extern "C" void kernel_launch(void* const* d_in, const int* in_sizes, int n_in,
                              void* d_out, int out_size){
    const float* z        = (const float*)d_in[0];
    const float* frames   = (const float*)d_in[1];
    const int*   actions  = (const int*)  d_in[2];
    const int*   ts       = (const int*)  d_in[3];
    const float* W_patch  = (const float*)d_in[4];
    const float* b_patch  = (const float*)d_in[5];
    const float* W_unpatch= (const float*)d_in[6];
    const float* b_unpatch= (const float*)d_in[7];
    const float* registers= (const float*)d_in[8];
    const float* pe_grid  = (const float*)d_in[9];
    const float* action_e = (const float*)d_in[10];
    const float* time_emb = (const float*)d_in[11];
    const float* W_mod1   = (const float*)d_in[12];
    const float* b_mod1   = (const float*)d_in[13];
    const float* W_mod2   = (const float*)d_in[14];
    const float* b_mod2   = (const float*)d_in[15];
    const float* W_q      = (const float*)d_in[16];
    const float* b_q      = (const float*)d_in[17];
    const float* W_k      = (const float*)d_in[18];
    const float* b_k      = (const float*)d_in[19];
    const float* W_v      = (const float*)d_in[20];
    const float* b_v      = (const float*)d_in[21];
    const float* W_o      = (const float*)d_in[22];
    const float* b_o      = (const float*)d_in[23];
    const float* W_g1     = (const float*)d_in[24];
    const float* b_g1     = (const float*)d_in[25];
    const float* W_g2     = (const float*)d_in[26];
    const float* b_g2     = (const float*)d_in[27];
    const float* W_geglu  = (const float*)d_in[28];
    const float* b_geglu  = (const float*)d_in[29];
    const float* W_ffout  = (const float*)d_in[30];
    const float* b_ffout  = (const float*)d_in[31];
    float* out = (float*)d_out;

    float* pState = symaddr<float>(g_state);
    float* pQKV   = symaddr<float>(g_qkv);
    float* pAtto  = symaddr<float>(g_atto);
    float* pBqkv  = symaddr<float>(g_bqkv);
    float* pBgg   = symaddr<float>(g_bgg2);
    __nv_bfloat16* nh = symaddr<__nv_bfloat16>(g_nh);
    __nv_bfloat16* nl = symaddr<__nv_bfloat16>(g_nl);
    __nv_bfloat16* xh = symaddr<__nv_bfloat16>(g_xh);
    __nv_bfloat16* xl = symaddr<__nv_bfloat16>(g_xl);
    __nv_bfloat16* yh = symaddr<__nv_bfloat16>(g_yh);
    __nv_bfloat16* yl = symaddr<__nv_bfloat16>(g_yl);
    __nv_bfloat16* wqkvh = symaddr<__nv_bfloat16>(g_wqkv_h);
    __nv_bfloat16* wqkvl = symaddr<__nv_bfloat16>(g_wqkv_l);
    __nv_bfloat16* woh   = symaddr<__nv_bfloat16>(g_wo_h);
    __nv_bfloat16* wol   = symaddr<__nv_bfloat16>(g_wo_l);
    __nv_bfloat16* wggh  = symaddr<__nv_bfloat16>(g_wgg_h);
    __nv_bfloat16* wggl  = symaddr<__nv_bfloat16>(g_wgg_l);
    __nv_bfloat16* wffh  = symaddr<__nv_bfloat16>(g_wff_h);
    __nv_bfloat16* wffl  = symaddr<__nv_bfloat16>(g_wff_l);

    cudaFuncSetAttribute(gemm_mma_t<128>, cudaFuncAttributeMaxDynamicSharedMemorySize, 131072);
    cudaFuncSetAttribute(gemm_mma_t<64>,  cudaFuncAttributeMaxDynamicSharedMemorySize, 98304);

    cond_kernel<<<7, 128>>>(ts, time_emb);
    modvec_kernel<<<dim3(NBLK*7, 12), 256>>>(W_mod1, b_mod1, W_mod2, b_mod2,
                                             W_g1, b_g1, W_g2, b_g2);
    embed_kernel<<<NTOK, 128>>>(z, frames, actions, W_patch, b_patch,
                                registers, pe_grid, action_e);

    dim3 tb(32, 8);
    transp_split<<<dim3(16,16,NBLK), tb>>>(W_q, wqkvh,              wqkvl,              512, 512, 0,
                                           (size_t)512*512, (size_t)QKVD*512);
    transp_split<<<dim3(16,16,NBLK), tb>>>(W_k, wqkvh + 512*512,    wqkvl + 512*512,    512, 512, 0,
                                           (size_t)512*512, (size_t)QKVD*512);
    transp_split<<<dim3(16,16,NBLK), tb>>>(W_v, wqkvh + 1024*512,   wqkvl + 1024*512,   512, 512, 0,
                                           (size_t)512*512, (size_t)QKVD*512);
    transp_split<<<dim3(16,16,NBLK), tb>>>(W_o, woh, wol, 512, 512, 0,
                                           (size_t)512*512, (size_t)512*512);
    transp_split<<<dim3(128,16,NBLK), tb>>>(W_geglu, wggh, wggl, 512, 4096, 1,
                                            (size_t)512*4096, (size_t)4096*512);
    transp_split<<<dim3(16,64,NBLK), tb>>>(W_ffout, wffh, wffl, 2048, 512, 0,
                                           (size_t)2048*512, (size_t)512*2048);
    prep_bias<<<NBLK, 256>>>(b_q, b_k, b_v, b_geglu);

    int mt128 = (NTOK + 127) / 128;   // 23
    int mt64  = (NTOK + 63) / 64;     // 45
    for (int i = 0; i < NBLK; i++){
        mod_kernel<<<NTOK, 128>>>(i);
        gemm_mma_t<128><<<dim3(QKVD/128, mt128), 256, 131072>>>(nh, nl,
            wqkvh + (size_t)i*QKVD*512, wqkvl + (size_t)i*QKVD*512,
            pBqkv + i*QKVD, pQKV, nullptr, nullptr, NTOK, QKVD, 512, 0, i);
        fattn<<<dim3(11, 5, NHh), 128>>>(pQKV);
        gemm_mma_t<64><<<dim3(4, mt64), 128, 98304>>>(xh, xl,
            woh + (size_t)i*512*512, wol + (size_t)i*512*512,
            b_o + i*512, pAtto, nullptr, nullptr, NTOK, 512, 512, 0, i);
        postattn_kernel<<<NTOK, 128>>>(i);
        gemm_mma_t<128><<<dim3(32, mt128), 256, 131072>>>(xh, xl,
            wggh + (size_t)i*4096*512, wggl + (size_t)i*4096*512,
            pBgg + i*4096, nullptr, yh, yl, NTOK, 4096, 512, 1, i);
        gemm_mma_t<64><<<dim3(4, mt64), 128, 98304>>>(yh, yl,
            wffh + (size_t)i*512*2048, wffl + (size_t)i*512*2048,
            b_ffout + i*512, pState, nullptr, nullptr, NTOK, 512, 2048, 2, i);
    }
    unpatch_kernel<<<1536, 128>>>(W_unpatch, b_unpatch, out);
}

// round 13
// speedup vs baseline: 4.2369x; 1.0451x over previous
#include <cuda_runtime.h>
#include <cuda_bf16.h>
#include <cstdint>
#include <math.h>

// ---------------- problem constants ----------------
#define Dm    512
#define NHh   8
#define DH    64
#define NBLK  6
#define SEQ   257
#define NZR   1542
#define NXA   1285
#define NTOK  2827
#define HIDm  2048
#define QKVD  1536

// ---------------- scratch ----------------
__device__ float g_state[NTOK*Dm];
__device__ float g_qkv  [NTOK*QKVD];
__device__ float g_atto [NTOK*Dm];

__device__ __nv_bfloat16 g_nh[NTOK*Dm];     // norm split
__device__ __nv_bfloat16 g_nl[NTOK*Dm];
__device__ __nv_bfloat16 g_xh[NTOK*Dm];     // att / h split
__device__ __nv_bfloat16 g_xl[NTOK*Dm];
__device__ __nv_bfloat16 g_yh[NTOK*HIDm];   // act split
__device__ __nv_bfloat16 g_yl[NTOK*HIDm];

__device__ float g_cond [7*Dm];
__device__ float g_silu [7*Dm];
__device__ float g_m1   [NBLK*7*1024];
__device__ float g_m2   [NBLK*7*1024];
__device__ float g_ga   [NBLK*7*Dm];
__device__ float g_gb   [NBLK*7*Dm];

// pre-transposed, split weights (row = output col n, K contiguous)
__device__ __nv_bfloat16 g_wqkv_h[NBLK*QKVD*Dm];
__device__ __nv_bfloat16 g_wqkv_l[NBLK*QKVD*Dm];
__device__ __nv_bfloat16 g_wo_h  [NBLK*Dm*Dm];
__device__ __nv_bfloat16 g_wo_l  [NBLK*Dm*Dm];
__device__ __nv_bfloat16 g_wgg_h [NBLK*2*HIDm*Dm];
__device__ __nv_bfloat16 g_wgg_l [NBLK*2*HIDm*Dm];
__device__ __nv_bfloat16 g_wff_h [NBLK*Dm*HIDm];
__device__ __nv_bfloat16 g_wff_l [NBLK*Dm*HIDm];
__device__ float g_bqkv[NBLK*QKVD];
__device__ float g_bgg2[NBLK*2*HIDm];

// ---------------- helpers ----------------
__device__ __forceinline__ uint32_t smem_u32(const void* p){
    uint32_t a;
    asm("{ .reg .u64 t; cvta.to.shared.u64 t, %1; cvt.u32.u64 %0, t; }" : "=r"(a) : "l"(p));
    return a;
}
#define SW128(off) ((off) ^ (((off)>>3) & 0x70))

__device__ __forceinline__ void ldsm4(uint32_t* r, uint32_t addr){
    asm volatile("ldmatrix.sync.aligned.m8n8.x4.shared.b16 {%0,%1,%2,%3}, [%4];"
        : "=r"(r[0]), "=r"(r[1]), "=r"(r[2]), "=r"(r[3]) : "r"(addr));
}
__device__ __forceinline__ void ldsm4t(uint32_t* r, uint32_t addr){
    asm volatile("ldmatrix.sync.aligned.m8n8.x4.trans.shared.b16 {%0,%1,%2,%3}, [%4];"
        : "=r"(r[0]), "=r"(r[1]), "=r"(r[2]), "=r"(r[3]) : "r"(addr));
}
__device__ __forceinline__ void mma_bf16(float* d, const uint32_t* a, uint32_t b0, uint32_t b1){
    asm volatile("mma.sync.aligned.m16n8k16.row.col.f32.bf16.bf16.f32 "
        "{%0,%1,%2,%3}, {%4,%5,%6,%7}, {%8,%9}, {%0,%1,%2,%3};"
        : "+f"(d[0]), "+f"(d[1]), "+f"(d[2]), "+f"(d[3])
        : "r"(a[0]), "r"(a[1]), "r"(a[2]), "r"(a[3]), "r"(b0), "r"(b1));
}

__device__ __forceinline__ float warpSum(float v){
    #pragma unroll
    for (int o = 16; o > 0; o >>= 1) v += __shfl_xor_sync(0xffffffffu, v, o);
    return v;
}
__device__ __forceinline__ void blockReduce2(float& s, float& q){
    s = warpSum(s); q = warpSum(q);
    __shared__ float sh[8];
    int w = threadIdx.x >> 5;
    if ((threadIdx.x & 31) == 0) { sh[w] = s; sh[4+w] = q; }
    __syncthreads();
    s = sh[0]+sh[1]+sh[2]+sh[3];
    q = sh[4]+sh[5]+sh[6]+sh[7];
    __syncthreads();
}
__device__ __forceinline__ int frame_class(int t){ return (t < NZR) ? (t / SEQ) : 6; }

__device__ __forceinline__ void split2(float x, float y, uint32_t& h, uint32_t& l){
    __nv_bfloat16 hx = __float2bfloat16(x), hy = __float2bfloat16(y);
    __nv_bfloat16 lx = __float2bfloat16(x - __bfloat162float(hx));
    __nv_bfloat16 ly = __float2bfloat16(y - __bfloat162float(hy));
    h = (uint32_t)__bfloat16_as_ushort(hx) | ((uint32_t)__bfloat16_as_ushort(hy) << 16);
    l = (uint32_t)__bfloat16_as_ushort(lx) | ((uint32_t)__bfloat16_as_ushort(ly) << 16);
}
__device__ __forceinline__ uint2 pack4h(float4 v){
    __nv_bfloat16 a = __float2bfloat16(v.x), b = __float2bfloat16(v.y);
    __nv_bfloat16 c = __float2bfloat16(v.z), d = __float2bfloat16(v.w);
    return make_uint2((uint32_t)__bfloat16_as_ushort(a) | ((uint32_t)__bfloat16_as_ushort(b) << 16),
                      (uint32_t)__bfloat16_as_ushort(c) | ((uint32_t)__bfloat16_as_ushort(d) << 16));
}

// ---------------- conditioning ----------------
__global__ void cond_kernel(const int* __restrict__ ts, const float* __restrict__ time_emb){
    int c = blockIdx.x;
    int row = (c < 6) ? ts[c] : 0;
    for (int d = threadIdx.x; d < Dm; d += blockDim.x){
        float x = time_emb[row*Dm + d];
        g_cond[c*Dm + d] = x;
        g_silu[c*Dm + d] = x / (1.0f + expf(-x));
    }
}

__global__ void modvec_kernel(const float* __restrict__ Wm1, const float* __restrict__ bm1,
                              const float* __restrict__ Wm2, const float* __restrict__ bm2,
                              const float* __restrict__ Wg1, const float* __restrict__ bg1,
                              const float* __restrict__ Wg2, const float* __restrict__ bg2){
    int ic = blockIdx.x;
    int i  = ic / 7, c = ic % 7;
    int j  = blockIdx.y * 256 + threadIdx.x;
    __shared__ float vs[Dm], vp[Dm];
    for (int k = threadIdx.x; k < Dm; k += 256){
        vs[k] = g_silu[c*Dm + k];
        vp[k] = g_cond[c*Dm + k];
    }
    __syncthreads();
    const float* W; const float* b; float* out; int nd; const float* v; int col;
    if (j < 1024)      { W = Wm1 + i*Dm*1024; b = bm1 + i*1024; out = g_m1 + ic*1024; nd = 1024; v = vs; col = j; }
    else if (j < 2048) { W = Wm2 + i*Dm*1024; b = bm2 + i*1024; out = g_m2 + ic*1024; nd = 1024; v = vs; col = j - 1024; }
    else if (j < 2560) { W = Wg1 + i*Dm*Dm;   b = bg1 + i*Dm;   out = g_ga + ic*Dm;   nd = Dm;   v = vp; col = j - 2048; }
    else               { W = Wg2 + i*Dm*Dm;   b = bg2 + i*Dm;   out = g_gb + ic*Dm;   nd = Dm;   v = vp; col = j - 2560; }
    float acc = b[col];
    #pragma unroll 8
    for (int k = 0; k < Dm; k++) acc += v[k] * W[k*nd + col];
    out[col] = acc;
}

// ---------------- embed ----------------
__global__ void embed_kernel(const float* __restrict__ z, const float* __restrict__ frames,
                             const int* __restrict__ actions,
                             const float* __restrict__ Wp, const float* __restrict__ bp,
                             const float* __restrict__ regs, const float* __restrict__ pe,
                             const float* __restrict__ aemb){
    int t = blockIdx.x;
    int tid = threadIdx.x;
    int f, s;
    const float* img;
    const float* special = nullptr;
    if (t < NZR) {
        f = t / SEQ; s = t % SEQ; img = z;
        if (s == SEQ-1) special = regs;
    } else {
        int u = t - NZR; f = u / SEQ; s = u % SEQ; img = frames;
        if (s == SEQ-1) special = aemb + actions[f]*Dm;
    }
    if (special){
        for (int d = tid; d < Dm; d += 128) g_state[t*Dm + d] = special[d];
        return;
    }
    __shared__ float pv[12];
    if (tid < 12){
        int c = tid >> 2, ph = (tid >> 1) & 1, pw = tid & 1;
        int h2 = s >> 4, w2 = s & 15;
        pv[tid] = img[f*3072 + c*1024 + (h2*2 + ph)*32 + (w2*2 + pw)];
    }
    __syncthreads();
    for (int d = tid; d < Dm; d += 128){
        float acc = bp[d] + pe[s*Dm + d];
        #pragma unroll
        for (int jj = 0; jj < 12; jj++) acc += pv[jj] * Wp[jj*Dm + d];
        g_state[t*Dm + d] = acc;
    }
}

// ---------------- weight prep (batched over DiT blocks via blockIdx.z) ----------------
__global__ void transp_split(const float* __restrict__ in, __nv_bfloat16* __restrict__ ohi,
                             __nv_bfloat16* __restrict__ olo, int K, int N, int il,
                             size_t inz, size_t outz){
    in  += (size_t)blockIdx.z * inz;
    ohi += (size_t)blockIdx.z * outz;
    olo += (size_t)blockIdx.z * outz;
    __shared__ float t[32][33];
    int r0 = blockIdx.x*32, k0 = blockIdx.y*32;
    int tx = threadIdx.x, ty = threadIdx.y;
    int u0 = r0 >> 1;
    for (int i = ty; i < 32; i += 8){
        int col = il ? ((tx < 16) ? (u0 + tx) : (HIDm + u0 + tx - 16)) : (r0 + tx);
        t[i][tx] = in[(size_t)(k0 + i)*N + col];
    }
    __syncthreads();
    for (int j = ty; j < 32; j += 8){
        int ci = il ? ((j>>1) + ((j&1)?16:0)) : j;
        float v = t[tx][ci];
        __nv_bfloat16 h = __float2bfloat16(v);
        __nv_bfloat16 l = __float2bfloat16(v - __bfloat162float(h));
        size_t o = (size_t)(r0 + j)*K + k0 + tx;
        ohi[o] = h; olo[o] = l;
    }
}

__global__ void prep_bias(const float* __restrict__ bq, const float* __restrict__ bk,
                          const float* __restrict__ bv, const float* __restrict__ bgg){
    int i = blockIdx.x;
    for (int j = threadIdx.x; j < QKVD; j += 256){
        float v = (j < 512) ? bq[i*512 + j] : (j < 1024) ? bk[i*512 + j - 512] : bv[i*512 + j - 1024];
        g_bqkv[i*QKVD + j] = v;
    }
    for (int p = threadIdx.x; p < 2*HIDm; p += 256){
        int u = p >> 1;
        g_bgg2[i*2*HIDm + p] = (p & 1) ? bgg[i*2*HIDm + HIDm + u] : bgg[i*2*HIDm + u];
    }
}

// ---------------- AdaLN mod1: state -> nh/nl split ----------------
__global__ void mod_kernel(int blk){
    int t = blockIdx.x, tid = threadIdx.x;
    int c = frame_class(t);
    float4 v = ((const float4*)(g_state + (size_t)t*Dm))[tid];
    float s = v.x+v.y+v.z+v.w;
    float q = v.x*v.x + v.y*v.y + v.z*v.z + v.w*v.w;
    blockReduce2(s, q);
    float mu  = s * (1.0f/Dm);
    float var = q * (1.0f/Dm) - mu*mu;
    float rstd = rsqrtf(var + 1e-5f);
    const float* ms = g_m1 + (blk*7 + c)*1024;
    int d = tid*4;
    float o0 = (v.x-mu)*rstd*(1.0f+ms[d+0]) + ms[512+d+0];
    float o1 = (v.y-mu)*rstd*(1.0f+ms[d+1]) + ms[512+d+1];
    float o2 = (v.z-mu)*rstd*(1.0f+ms[d+2]) + ms[512+d+2];
    float o3 = (v.w-mu)*rstd*(1.0f+ms[d+3]) + ms[512+d+3];
    uint32_t h0,l0,h1,l1;
    split2(o0,o1,h0,l0); split2(o2,o3,h1,l1);
    ((uint2*)(g_nh + (size_t)t*Dm))[tid] = make_uint2(h0,h1);
    ((uint2*)(g_nl + (size_t)t*Dm))[tid] = make_uint2(l0,l1);
}

// ---------------- post-attn: h = mod2( norm*g1 + atto ) -> xh/xl ----------------
__global__ void postattn_kernel(int blk){
    int t = blockIdx.x, tid = threadIdx.x;
    int c = frame_class(t);
    const float* g1v = g_ga + (blk*7 + c)*Dm;
    float4 a = ((const float4*)(g_atto + (size_t)t*Dm))[tid];
    int d = tid*4;
    const __nv_bfloat16* nh = g_nh + (size_t)t*Dm + d;
    const __nv_bfloat16* nl = g_nl + (size_t)t*Dm + d;
    float n0 = __bfloat162float(nh[0]) + __bfloat162float(nl[0]);
    float n1 = __bfloat162float(nh[1]) + __bfloat162float(nl[1]);
    float n2 = __bfloat162float(nh[2]) + __bfloat162float(nl[2]);
    float n3 = __bfloat162float(nh[3]) + __bfloat162float(nl[3]);
    float4 v;
    v.x = n0*g1v[d+0] + a.x;
    v.y = n1*g1v[d+1] + a.y;
    v.z = n2*g1v[d+2] + a.z;
    v.w = n3*g1v[d+3] + a.w;
    float s = v.x+v.y+v.z+v.w;
    float q = v.x*v.x + v.y*v.y + v.z*v.z + v.w*v.w;
    blockReduce2(s, q);
    float mu  = s * (1.0f/Dm);
    float var = q * (1.0f/Dm) - mu*mu;
    float rstd = rsqrtf(var + 1e-5f);
    const float* ms = g_m2 + (blk*7 + c)*1024;
    float o0 = (v.x-mu)*rstd*(1.0f+ms[d+0]) + ms[512+d+0];
    float o1 = (v.y-mu)*rstd*(1.0f+ms[d+1]) + ms[512+d+1];
    float o2 = (v.z-mu)*rstd*(1.0f+ms[d+2]) + ms[512+d+2];
    float o3 = (v.w-mu)*rstd*(1.0f+ms[d+3]) + ms[512+d+3];
    uint32_t h0,l0,h1,l1;
    split2(o0,o1,h0,l0); split2(o2,o3,h1,l1);
    ((uint2*)(g_xh + (size_t)t*Dm))[tid] = make_uint2(h0,h1);
    ((uint2*)(g_xl + (size_t)t*Dm))[tid] = make_uint2(l0,l1);
}

// ---------------- bf16 split GEMM on mma.sync (HMMA), templated M-tile ----------------
// C[M,N] += A @ B^T with A = Ah+Al ([M][K] bf16 split), B rows = out cols ([N][K] split).
// mode 0: C fp32 = acc + bias
// mode 1: GEGLU interleaved: out[m][u] = (a+ba)*gelu(g+bg), split bf16 into Oh/Ol (stride HIDm)
// mode 2: C fp32 = (acc + bias) * g_gb
template<int BM>
__global__ __launch_bounds__(BM*2) void gemm_mma_t(
    const __nv_bfloat16* __restrict__ Ah, const __nv_bfloat16* __restrict__ Al,
    const __nv_bfloat16* __restrict__ Bh, const __nv_bfloat16* __restrict__ Bl,
    const float* __restrict__ bias, float* __restrict__ C,
    __nv_bfloat16* __restrict__ Oh, __nv_bfloat16* __restrict__ Ol,
    int M, int N, int K, int mode, int blk)
{
    constexpr int T   = BM*2;
    constexpr int ASZ = BM*128;          // bytes of one A tile (BM x 64 bf16)
    constexpr int BUF = 2*ASZ + 32768;
    extern __shared__ char smem[];
    uint32_t sb = smem_u32(smem);
    int tid = threadIdx.x, lane = tid & 31, wid = tid >> 5;
    int bm = blockIdx.y * BM, bn = blockIdx.x * 128;
    int wm = wid >> 1, wn = wid & 1;
    int lr = lane & 7, mid = lane >> 3;

    float acc[2][8][4];
    #pragma unroll
    for (int i=0;i<2;i++)
        #pragma unroll
        for (int j=0;j<8;j++)
            #pragma unroll
            for (int k=0;k<4;k++) acc[i][j][k] = 0.f;

    auto load_chunk = [&](int cc, int buf){
        int kc = cc << 6;
        uint32_t sbase = sb + buf*BUF;
        #pragma unroll
        for (int p = 0; p < BM*8/T; p++){
            int idx = p*T + tid;
            int r = idx >> 3, ch = idx & 7;
            uint32_t so = SW128((uint32_t)(r*128 + ch*16));
            int row = bm + r;
            size_t aoff = (size_t)((row < M) ? row : (M-1))*K + kc + ch*8;
            uint32_t pr = (row < M) ? 16u : 0u;
            asm volatile("cp.async.cg.shared.global [%0], [%1], 16, %2;" :: "r"(sbase + so),       "l"(Ah + aoff), "r"(pr));
            asm volatile("cp.async.cg.shared.global [%0], [%1], 16, %2;" :: "r"(sbase + ASZ + so), "l"(Al + aoff), "r"(pr));
        }
        #pragma unroll
        for (int p = 0; p < 1024/T; p++){
            int idx = p*T + tid;
            int r = idx >> 3, ch = idx & 7;
            uint32_t so = SW128((uint32_t)(r*128 + ch*16));
            size_t boff = (size_t)(bn + r)*K + kc + ch*8;
            asm volatile("cp.async.cg.shared.global [%0], [%1], 16;" :: "r"(sbase + 2*ASZ + so),         "l"(Bh + boff));
            asm volatile("cp.async.cg.shared.global [%0], [%1], 16;" :: "r"(sbase + 2*ASZ + 16384 + so), "l"(Bl + boff));
        }
        asm volatile("cp.async.commit_group;" ::: "memory");
    };

    int nchunk = K >> 6;
    load_chunk(0, 0);
    for (int c = 0; c < nchunk; c++){
        int buf = c & 1;
        if (c + 1 < nchunk){
            load_chunk(c + 1, buf ^ 1);
            asm volatile("cp.async.wait_group 1;" ::: "memory");
        } else {
            asm volatile("cp.async.wait_group 0;" ::: "memory");
        }
        __syncthreads();
        uint32_t abase = sb + buf*BUF;
        uint32_t bbase = abase + 2*ASZ;
        #pragma unroll
        for (int ks = 0; ks < 4; ks++){
            uint32_t ah[2][4], al[2][4];
            #pragma unroll
            for (int mf = 0; mf < 2; mf++){
                int row = wm*32 + mf*16 + (mid & 1)*8 + lr;
                uint32_t off = SW128((uint32_t)(row*128 + (ks*2 + (mid >> 1))*16));
                ldsm4(ah[mf], abase + off);
                ldsm4(al[mf], abase + ASZ + off);
            }
            uint32_t bh[4][4], bl[4][4];
            #pragma unroll
            for (int np = 0; np < 4; np++){
                int row = wn*64 + np*16 + (mid >> 1)*8 + lr;
                uint32_t off = SW128((uint32_t)(row*128 + (ks*2 + (mid & 1))*16));
                ldsm4(bh[np], bbase + off);
                ldsm4(bl[np], bbase + 16384 + off);
            }
            #pragma unroll
            for (int mf = 0; mf < 2; mf++){
                #pragma unroll
                for (int nf = 0; nf < 8; nf++){
                    uint32_t* ph = &bh[nf >> 1][(nf & 1)*2];
                    uint32_t* pl = &bl[nf >> 1][(nf & 1)*2];
                    mma_bf16(acc[mf][nf], ah[mf], ph[0], ph[1]);
                    mma_bf16(acc[mf][nf], ah[mf], pl[0], pl[1]);
                    mma_bf16(acc[mf][nf], al[mf], ph[0], ph[1]);
                }
            }
        }
        __syncthreads();
    }

    // epilogue
    #pragma unroll
    for (int mf = 0; mf < 2; mf++){
        int m0 = bm + wm*32 + mf*16 + (lane >> 2);
        #pragma unroll
        for (int half = 0; half < 2; half++){
            int m = m0 + half*8;
            if (m >= M) continue;
            #pragma unroll
            for (int nf = 0; nf < 8; nf++){
                float d0 = acc[mf][nf][half*2 + 0];
                float d1 = acc[mf][nf][half*2 + 1];
                int c0 = bn + wn*64 + nf*8 + (lane & 3)*2;
                if (mode == 0){
                    float2 o = make_float2(d0 + bias[c0], d1 + bias[c0+1]);
                    *(float2*)(C + (size_t)m*N + c0) = o;
                } else if (mode == 1){
                    float a = d0 + bias[c0];
                    float g = d1 + bias[c0+1];
                    float ge = 0.5f*g*(1.0f + erff(g*0.70710678118654752440f));
                    float v = a*ge;
                    int u = c0 >> 1;
                    __nv_bfloat16 hh = __float2bfloat16(v);
                    __nv_bfloat16 ll = __float2bfloat16(v - __bfloat162float(hh));
                    Oh[(size_t)m*HIDm + u] = hh;
                    Ol[(size_t)m*HIDm + u] = ll;
                } else {
                    const float* gv = g_gb + (blk*7 + frame_class(m))*Dm;
                    float2 o;
                    o.x = (d0 + bias[c0])   * gv[c0];
                    o.y = (d1 + bias[c0+1]) * gv[c0+1];
                    *(float2*)(C + (size_t)m*N + c0) = o;
                }
            }
        }
    }
}

// ---------------- flash attention (HMMA), 64 queries x 64-key blocks ----------------
// grid: (nframes, 5 qtiles, 8 heads), 128 threads (4 warps x 16 q rows)
__global__ __launch_bounds__(128) void fattn(const float* __restrict__ QKV){
    int frame = blockIdx.x, qt = blockIdx.y, h = blockIdx.z;
    int qbase, r0s, r0n, r1s, r1n;
    if (frame < 6){
        qbase = frame*SEQ;
        r0s = frame*SEQ;              r0n = SEQ;
        int lo = frame-4; if (lo < 0) lo = 0;
        r1s = NZR + lo*SEQ;           r1n = (frame - lo)*SEQ;
    } else {
        int f = frame - 6;
        qbase = NZR + f*SEQ;
        r0s = NZR;                    r0n = (f+1)*SEQ;
        r1s = 0;                      r1n = 0;
    }
    int nk = r0n + r1n;
    int q0 = qt*64;
    int nq = SEQ - q0; if (nq > 64) nq = 64;   // qt=4 -> nq=1

    __shared__ __align__(128) char sbuf[32768];
    char* sQh = sbuf;
    char* sQl = sbuf + 8192;
    char* sKc = sbuf + 16384;
    char* sVc = sbuf + 24576;
    uint32_t bQh = smem_u32(sQh), bQl = smem_u32(sQl), bK = smem_u32(sKc), bV = smem_u32(sVc);
    int tid = threadIdx.x, lane = tid & 31, wid = tid >> 5;
    int lr = lane & 7, mid = lane >> 3;

    // load Q tile, split hi/lo
    for (int idx = tid; idx < 1024; idx += 128){
        int r = idx >> 4, c4 = idx & 15;
        int rr = (r < nq) ? r : (nq-1);
        float4 v = *(const float4*)(QKV + (size_t)(qbase + q0 + rr)*QKVD + h*DH + c4*4);
        uint32_t h0,l0,h1,l1;
        split2(v.x, v.y, h0, l0); split2(v.z, v.w, h1, l1);
        uint32_t off = SW128((uint32_t)(r*128 + c4*8));
        *(uint2*)(sQh + off) = make_uint2(h0,h1);
        *(uint2*)(sQl + off) = make_uint2(l0,l1);
    }
    __syncthreads();
    uint32_t qh[4][4], ql[4][4];
    #pragma unroll
    for (int ks = 0; ks < 4; ks++){
        uint32_t off = SW128((uint32_t)((wid*16 + (mid&1)*8 + lr)*128 + (ks*2 + (mid>>1))*16));
        ldsm4(qh[ks], bQh + off);
        ldsm4(ql[ks], bQl + off);
    }

    float o[8][4];
    #pragma unroll
    for (int j=0;j<8;j++){ o[j][0]=0.f;o[j][1]=0.f;o[j][2]=0.f;o[j][3]=0.f; }
    float m0=-1e30f, m1=-1e30f, l0=0.f, l1=0.f;

    int nkb = (nk + 63) >> 6;
    for (int kb = 0; kb < nkb; kb++){
        int k0 = kb << 6;
        __syncthreads();
        for (int idx = tid; idx < 1024; idx += 128){
            int r = idx >> 4, c4 = idx & 15;
            int i = k0 + r;
            int g = (i < r0n) ? (r0s + i) : ((i < nk) ? (r1s + i - r0n) : r0s);
            const float* base = QKV + (size_t)g*QKVD + h*DH + c4*4;
            float4 kv = *(const float4*)(base + 512);
            float4 vv = *(const float4*)(base + 1024);
            uint32_t off = SW128((uint32_t)(r*128 + c4*8));
            *(uint2*)(sKc + off) = pack4h(kv);
            *(uint2*)(sVc + off) = pack4h(vv);
        }
        __syncthreads();

        // S = Q K^T  (split Q: 2 mmas)
        float s[8][4];
        #pragma unroll
        for (int j=0;j<8;j++){ s[j][0]=0.f;s[j][1]=0.f;s[j][2]=0.f;s[j][3]=0.f; }
        #pragma unroll
        for (int ks = 0; ks < 4; ks++){
            #pragma unroll
            for (int np = 0; np < 4; np++){
                uint32_t bk[4];
                uint32_t off = SW128((uint32_t)((np*16 + (mid>>1)*8 + lr)*128 + (ks*2 + (mid&1))*16));
                ldsm4(bk, bK + off);
                mma_bf16(s[np*2],   qh[ks], bk[0], bk[1]);
                mma_bf16(s[np*2],   ql[ks], bk[0], bk[1]);
                mma_bf16(s[np*2+1], qh[ks], bk[2], bk[3]);
                mma_bf16(s[np*2+1], ql[ks], bk[2], bk[3]);
            }
        }
        // online softmax
        float mx0 = -1e30f, mx1 = -1e30f;
        #pragma unroll
        for (int j = 0; j < 8; j++){
            int c = k0 + j*8 + (lane & 3)*2;
            s[j][0] = (c   < nk) ? s[j][0]*0.125f : -1e30f;
            s[j][1] = (c+1 < nk) ? s[j][1]*0.125f : -1e30f;
            s[j][2] = (c   < nk) ? s[j][2]*0.125f : -1e30f;
            s[j][3] = (c+1 < nk) ? s[j][3]*0.125f : -1e30f;
            mx0 = fmaxf(mx0, fmaxf(s[j][0], s[j][1]));
            mx1 = fmaxf(mx1, fmaxf(s[j][2], s[j][3]));
        }
        mx0 = fmaxf(mx0, __shfl_xor_sync(0xffffffffu, mx0, 1));
        mx0 = fmaxf(mx0, __shfl_xor_sync(0xffffffffu, mx0, 2));
        mx1 = fmaxf(mx1, __shfl_xor_sync(0xffffffffu, mx1, 1));
        mx1 = fmaxf(mx1, __shfl_xor_sync(0xffffffffu, mx1, 2));
        float mn0 = fmaxf(m0, mx0), mn1 = fmaxf(m1, mx1);
        float f0 = __expf(m0 - mn0), f1 = __expf(m1 - mn1);
        m0 = mn0; m1 = mn1;
        l0 *= f0; l1 *= f1;
        #pragma unroll
        for (int j=0;j<8;j++){ o[j][0]*=f0; o[j][1]*=f0; o[j][2]*=f1; o[j][3]*=f1; }
        uint32_t ph[8][2], pl[8][2];
        #pragma unroll
        for (int j = 0; j < 8; j++){
            float p0 = __expf(s[j][0]-m0), p1 = __expf(s[j][1]-m0);
            float p2 = __expf(s[j][2]-m1), p3 = __expf(s[j][3]-m1);
            l0 += p0 + p1; l1 += p2 + p3;
            split2(p0, p1, ph[j][0], pl[j][0]);
            split2(p2, p3, ph[j][1], pl[j][1]);
        }
        // O += P V  (split P: 2 mmas)
        #pragma unroll
        for (int ks = 0; ks < 4; ks++){
            uint32_t ah[4] = {ph[2*ks][0], ph[2*ks][1], ph[2*ks+1][0], ph[2*ks+1][1]};
            uint32_t al[4] = {pl[2*ks][0], pl[2*ks][1], pl[2*ks+1][0], pl[2*ks+1][1]};
            #pragma unroll
            for (int vd = 0; vd < 4; vd++){
                uint32_t bv[4];
                uint32_t off = SW128((uint32_t)((ks*16 + (lane & 15))*128 + vd*32 + (lane >> 4)*16));
                ldsm4t(bv, bV + off);
                mma_bf16(o[vd*2],   ah, bv[0], bv[1]);
                mma_bf16(o[vd*2],   al, bv[0], bv[1]);
                mma_bf16(o[vd*2+1], ah, bv[2], bv[3]);
                mma_bf16(o[vd*2+1], al, bv[2], bv[3]);
            }
        }
    }
    l0 += __shfl_xor_sync(0xffffffffu, l0, 1);
    l0 += __shfl_xor_sync(0xffffffffu, l0, 2);
    l1 += __shfl_xor_sync(0xffffffffu, l1, 1);
    l1 += __shfl_xor_sync(0xffffffffu, l1, 2);
    float i0 = 1.0f/l0, i1 = 1.0f/l1;
    int row0 = wid*16 + (lane >> 2);
    #pragma unroll
    for (int j = 0; j < 8; j++){
        int c = j*8 + (lane & 3)*2;
        if (row0 < nq){
            size_t idx = (size_t)(qbase + q0 + row0)*Dm + h*DH + c;
            uint32_t hh, ll;
            split2(o[j][0]*i0, o[j][1]*i0, hh, ll);
            *(uint32_t*)(g_xh + idx) = hh;
            *(uint32_t*)(g_xl + idx) = ll;
        }
        if (row0 + 8 < nq){
            size_t idx = (size_t)(qbase + q0 + row0 + 8)*Dm + h*DH + c;
            uint32_t hh, ll;
            split2(o[j][2]*i1, o[j][3]*i1, hh, ll);
            *(uint32_t*)(g_xh + idx) = hh;
            *(uint32_t*)(g_xl + idx) = ll;
        }
    }
}

// ---------------- unpatch ----------------
__global__ void unpatch_kernel(const float* __restrict__ Wu, const float* __restrict__ bu,
                               float* __restrict__ out){
    int token = blockIdx.x;
    int f = token >> 8, s = token & 255;
    const float* x = g_state + (size_t)(f*SEQ + s)*Dm;
    __shared__ float xs[Dm];
    int tid = threadIdx.x;
    for (int d2 = tid; d2 < Dm; d2 += 128) xs[d2] = x[d2];
    __syncthreads();
    int warp = tid >> 5, lane = tid & 31;
    for (int j = warp; j < 12; j += 4){
        float acc = 0.f;
        for (int d2 = lane; d2 < Dm; d2 += 32) acc += xs[d2] * Wu[d2*12 + j];
        acc = warpSum(acc);
        if (lane == 0){
            int c = j >> 2, ph = (j >> 1) & 1, pw = j & 1;
            int h2 = s >> 4, w2 = s & 15;
            out[f*3072 + c*1024 + (h2*2 + ph)*32 + (w2*2 + pw)] = acc + bu[j];
        }
    }
}

// ---------------- host ----------------
template <typename T>
static T* symaddr(const void* sym){
    void* p = nullptr;
    cudaGetSymbolAddress(&p, sym);
    return (T*)p;
}

extern "C" void kernel_launch(void* const* d_in, const int* in_sizes, int n_in,
                              void* d_out, int out_size){
    const float* z        = (const float*)d_in[0];
    const float* frames   = (const float*)d_in[1];
    const int*   actions  = (const int*)  d_in[2];
    const int*   ts       = (const int*)  d_in[3];
    const float* W_patch  = (const float*)d_in[4];
    const float* b_patch  = (const float*)d_in[5];
    const float* W_unpatch= (const float*)d_in[6];
    const float* b_unpatch= (const float*)d_in[7];
    const float* registers= (const float*)d_in[8];
    const float* pe_grid  = (const float*)d_in[9];
    const float* action_e = (const float*)d_in[10];
    const float* time_emb = (const float*)d_in[11];
    const float* W_mod1   = (const float*)d_in[12];
    const float* b_mod1   = (const float*)d_in[13];
    const float* W_mod2   = (const float*)d_in[14];
    const float* b_mod2   = (const float*)d_in[15];
    const float* W_q      = (const float*)d_in[16];
    const float* b_q      = (const float*)d_in[17];
    const float* W_k      = (const float*)d_in[18];
    const float* b_k      = (const float*)d_in[19];
    const float* W_v      = (const float*)d_in[20];
    const float* b_v      = (const float*)d_in[21];
    const float* W_o      = (const float*)d_in[22];
    const float* b_o      = (const float*)d_in[23];
    const float* W_g1     = (const float*)d_in[24];
    const float* b_g1     = (const float*)d_in[25];
    const float* W_g2     = (const float*)d_in[26];
    const float* b_g2     = (const float*)d_in[27];
    const float* W_geglu  = (const float*)d_in[28];
    const float* b_geglu  = (const float*)d_in[29];
    const float* W_ffout  = (const float*)d_in[30];
    const float* b_ffout  = (const float*)d_in[31];
    float* out = (float*)d_out;

    float* pState = symaddr<float>(g_state);
    float* pQKV   = symaddr<float>(g_qkv);
    float* pAtto  = symaddr<float>(g_atto);
    float* pBqkv  = symaddr<float>(g_bqkv);
    float* pBgg   = symaddr<float>(g_bgg2);
    __nv_bfloat16* nh = symaddr<__nv_bfloat16>(g_nh);
    __nv_bfloat16* nl = symaddr<__nv_bfloat16>(g_nl);
    __nv_bfloat16* xh = symaddr<__nv_bfloat16>(g_xh);
    __nv_bfloat16* xl = symaddr<__nv_bfloat16>(g_xl);
    __nv_bfloat16* yh = symaddr<__nv_bfloat16>(g_yh);
    __nv_bfloat16* yl = symaddr<__nv_bfloat16>(g_yl);
    __nv_bfloat16* wqkvh = symaddr<__nv_bfloat16>(g_wqkv_h);
    __nv_bfloat16* wqkvl = symaddr<__nv_bfloat16>(g_wqkv_l);
    __nv_bfloat16* woh   = symaddr<__nv_bfloat16>(g_wo_h);
    __nv_bfloat16* wol   = symaddr<__nv_bfloat16>(g_wo_l);
    __nv_bfloat16* wggh  = symaddr<__nv_bfloat16>(g_wgg_h);
    __nv_bfloat16* wggl  = symaddr<__nv_bfloat16>(g_wgg_l);
    __nv_bfloat16* wffh  = symaddr<__nv_bfloat16>(g_wff_h);
    __nv_bfloat16* wffl  = symaddr<__nv_bfloat16>(g_wff_l);

    cudaFuncSetAttribute(gemm_mma_t<128>, cudaFuncAttributeMaxDynamicSharedMemorySize, 131072);
    cudaFuncSetAttribute(gemm_mma_t<64>,  cudaFuncAttributeMaxDynamicSharedMemorySize, 98304);

    cond_kernel<<<7, 128>>>(ts, time_emb);
    modvec_kernel<<<dim3(NBLK*7, 12), 256>>>(W_mod1, b_mod1, W_mod2, b_mod2,
                                             W_g1, b_g1, W_g2, b_g2);
    embed_kernel<<<NTOK, 128>>>(z, frames, actions, W_patch, b_patch,
                                registers, pe_grid, action_e);

    dim3 tb(32, 8);
    transp_split<<<dim3(16,16,NBLK), tb>>>(W_q, wqkvh,              wqkvl,              512, 512, 0,
                                           (size_t)512*512, (size_t)QKVD*512);
    transp_split<<<dim3(16,16,NBLK), tb>>>(W_k, wqkvh + 512*512,    wqkvl + 512*512,    512, 512, 0,
                                           (size_t)512*512, (size_t)QKVD*512);
    transp_split<<<dim3(16,16,NBLK), tb>>>(W_v, wqkvh + 1024*512,   wqkvl + 1024*512,   512, 512, 0,
                                           (size_t)512*512, (size_t)QKVD*512);
    transp_split<<<dim3(16,16,NBLK), tb>>>(W_o, woh, wol, 512, 512, 0,
                                           (size_t)512*512, (size_t)512*512);
    transp_split<<<dim3(128,16,NBLK), tb>>>(W_geglu, wggh, wggl, 512, 4096, 1,
                                            (size_t)512*4096, (size_t)4096*512);
    transp_split<<<dim3(16,64,NBLK), tb>>>(W_ffout, wffh, wffl, 2048, 512, 0,
                                           (size_t)2048*512, (size_t)512*2048);
    prep_bias<<<NBLK, 256>>>(b_q, b_k, b_v, b_geglu);

    for (int i = 0; i < NBLK; i++){
        // Last block: xa stream's post-attention work is dead (only zr reaches the output).
        int Mpost   = (i == NBLK-1) ? NZR : NTOK;
        int nframes = (i == NBLK-1) ? 6   : 11;
        int mt128   = (Mpost + 127) / 128;
        int mt64    = (Mpost + 63) / 64;
        int qt128   = (NTOK + 127) / 128;   // QKV always full (K/V needed for cross-attn)

        mod_kernel<<<NTOK, 128>>>(i);
        gemm_mma_t<128><<<dim3(QKVD/128, qt128), 256, 131072>>>(nh, nl,
            wqkvh + (size_t)i*QKVD*512, wqkvl + (size_t)i*QKVD*512,
            pBqkv + i*QKVD, pQKV, nullptr, nullptr, NTOK, QKVD, 512, 0, i);
        fattn<<<dim3(nframes, 5, NHh), 128>>>(pQKV);
        gemm_mma_t<64><<<dim3(4, mt64), 128, 98304>>>(xh, xl,
            woh + (size_t)i*512*512, wol + (size_t)i*512*512,
            b_o + i*512, pAtto, nullptr, nullptr, Mpost, 512, 512, 0, i);
        postattn_kernel<<<Mpost, 128>>>(i);
        gemm_mma_t<128><<<dim3(32, mt128), 256, 131072>>>(xh, xl,
            wggh + (size_t)i*4096*512, wggl + (size_t)i*4096*512,
            pBgg + i*4096, nullptr, yh, yl, Mpost, 4096, 512, 1, i);
        gemm_mma_t<64><<<dim3(4, mt64), 128, 98304>>>(yh, yl,
            wffh + (size_t)i*512*2048, wffl + (size_t)i*512*2048,
            b_ffout + i*512, pState, nullptr, nullptr, Mpost, 512, 2048, 2, i);
    }
    unpatch_kernel<<<1536, 128>>>(W_unpatch, b_unpatch, out);
}

// round 14
// speedup vs baseline: 4.4862x; 1.0588x over previous
#include <cuda_runtime.h>
#include <cuda_bf16.h>
#include <cstdint>
#include <math.h>

// ---------------- problem constants ----------------
#define Dm    512
#define NHh   8
#define DH    64
#define NBLK  6
#define SEQ   257
#define NZR   1542
#define NXA   1285
#define NTOK  2827
#define HIDm  2048
#define QKVD  1536

// ---------------- scratch ----------------
__device__ float g_state[NTOK*Dm];
__device__ float g_qkv  [NTOK*QKVD];
__device__ float g_atto [NTOK*Dm];

__device__ __nv_bfloat16 g_nh[NTOK*Dm];     // norm split
__device__ __nv_bfloat16 g_nl[NTOK*Dm];
__device__ __nv_bfloat16 g_xh[NTOK*Dm];     // att / h split
__device__ __nv_bfloat16 g_xl[NTOK*Dm];
__device__ __nv_bfloat16 g_yh[NTOK*HIDm];   // act split
__device__ __nv_bfloat16 g_yl[NTOK*HIDm];

__device__ float g_cond [7*Dm];
__device__ float g_silu [7*Dm];
__device__ float g_m1   [NBLK*7*1024];
__device__ float g_m2   [NBLK*7*1024];
__device__ float g_ga   [NBLK*7*Dm];
__device__ float g_gb   [NBLK*7*Dm];

// pre-transposed, split weights (row = output col n, K contiguous)
__device__ __nv_bfloat16 g_wqkv_h[NBLK*QKVD*Dm];
__device__ __nv_bfloat16 g_wqkv_l[NBLK*QKVD*Dm];
__device__ __nv_bfloat16 g_wo_h  [NBLK*Dm*Dm];
__device__ __nv_bfloat16 g_wo_l  [NBLK*Dm*Dm];
__device__ __nv_bfloat16 g_wgg_h [NBLK*2*HIDm*Dm];
__device__ __nv_bfloat16 g_wgg_l [NBLK*2*HIDm*Dm];
__device__ __nv_bfloat16 g_wff_h [NBLK*Dm*HIDm];
__device__ __nv_bfloat16 g_wff_l [NBLK*Dm*HIDm];
__device__ float g_bqkv[NBLK*QKVD];
__device__ float g_bgg2[NBLK*2*HIDm];

// ---------------- helpers ----------------
__device__ __forceinline__ uint32_t smem_u32(const void* p){
    uint32_t a;
    asm("{ .reg .u64 t; cvta.to.shared.u64 t, %1; cvt.u32.u64 %0, t; }" : "=r"(a) : "l"(p));
    return a;
}
#define SW128(off) ((off) ^ (((off)>>3) & 0x70))

__device__ __forceinline__ void ldsm4(uint32_t* r, uint32_t addr){
    asm volatile("ldmatrix.sync.aligned.m8n8.x4.shared.b16 {%0,%1,%2,%3}, [%4];"
        : "=r"(r[0]), "=r"(r[1]), "=r"(r[2]), "=r"(r[3]) : "r"(addr));
}
__device__ __forceinline__ void ldsm4t(uint32_t* r, uint32_t addr){
    asm volatile("ldmatrix.sync.aligned.m8n8.x4.trans.shared.b16 {%0,%1,%2,%3}, [%4];"
        : "=r"(r[0]), "=r"(r[1]), "=r"(r[2]), "=r"(r[3]) : "r"(addr));
}
__device__ __forceinline__ void mma_bf16(float* d, const uint32_t* a, uint32_t b0, uint32_t b1){
    asm volatile("mma.sync.aligned.m16n8k16.row.col.f32.bf16.bf16.f32 "
        "{%0,%1,%2,%3}, {%4,%5,%6,%7}, {%8,%9}, {%0,%1,%2,%3};"
        : "+f"(d[0]), "+f"(d[1]), "+f"(d[2]), "+f"(d[3])
        : "r"(a[0]), "r"(a[1]), "r"(a[2]), "r"(a[3]), "r"(b0), "r"(b1));
}

__device__ __forceinline__ float warpSum(float v){
    #pragma unroll
    for (int o = 16; o > 0; o >>= 1) v += __shfl_xor_sync(0xffffffffu, v, o);
    return v;
}
__device__ __forceinline__ void blockReduce2(float& s, float& q){
    s = warpSum(s); q = warpSum(q);
    __shared__ float sh[8];
    int w = threadIdx.x >> 5;
    if ((threadIdx.x & 31) == 0) { sh[w] = s; sh[4+w] = q; }
    __syncthreads();
    s = sh[0]+sh[1]+sh[2]+sh[3];
    q = sh[4]+sh[5]+sh[6]+sh[7];
    __syncthreads();
}
__device__ __forceinline__ int frame_class(int t){ return (t < NZR) ? (t / SEQ) : 6; }

__device__ __forceinline__ void split2(float x, float y, uint32_t& h, uint32_t& l){
    __nv_bfloat16 hx = __float2bfloat16(x), hy = __float2bfloat16(y);
    __nv_bfloat16 lx = __float2bfloat16(x - __bfloat162float(hx));
    __nv_bfloat16 ly = __float2bfloat16(y - __bfloat162float(hy));
    h = (uint32_t)__bfloat16_as_ushort(hx) | ((uint32_t)__bfloat16_as_ushort(hy) << 16);
    l = (uint32_t)__bfloat16_as_ushort(lx) | ((uint32_t)__bfloat16_as_ushort(ly) << 16);
}
__device__ __forceinline__ uint32_t pack2h(float x, float y){
    __nv_bfloat16 a = __float2bfloat16(x), b = __float2bfloat16(y);
    return (uint32_t)__bfloat16_as_ushort(a) | ((uint32_t)__bfloat16_as_ushort(b) << 16);
}
__device__ __forceinline__ uint2 pack4h(float4 v){
    return make_uint2(pack2h(v.x, v.y), pack2h(v.z, v.w));
}

// ---------------- conditioning ----------------
__global__ void cond_kernel(const int* __restrict__ ts, const float* __restrict__ time_emb){
    int c = blockIdx.x;
    int row = (c < 6) ? ts[c] : 0;
    for (int d = threadIdx.x; d < Dm; d += blockDim.x){
        float x = time_emb[row*Dm + d];
        g_cond[c*Dm + d] = x;
        g_silu[c*Dm + d] = x / (1.0f + expf(-x));
    }
}

__global__ void modvec_kernel(const float* __restrict__ Wm1, const float* __restrict__ bm1,
                              const float* __restrict__ Wm2, const float* __restrict__ bm2,
                              const float* __restrict__ Wg1, const float* __restrict__ bg1,
                              const float* __restrict__ Wg2, const float* __restrict__ bg2){
    int ic = blockIdx.x;
    int i  = ic / 7, c = ic % 7;
    int j  = blockIdx.y * 256 + threadIdx.x;
    __shared__ float vs[Dm], vp[Dm];
    for (int k = threadIdx.x; k < Dm; k += 256){
        vs[k] = g_silu[c*Dm + k];
        vp[k] = g_cond[c*Dm + k];
    }
    __syncthreads();
    const float* W; const float* b; float* out; int nd; const float* v; int col;
    if (j < 1024)      { W = Wm1 + i*Dm*1024; b = bm1 + i*1024; out = g_m1 + ic*1024; nd = 1024; v = vs; col = j; }
    else if (j < 2048) { W = Wm2 + i*Dm*1024; b = bm2 + i*1024; out = g_m2 + ic*1024; nd = 1024; v = vs; col = j - 1024; }
    else if (j < 2560) { W = Wg1 + i*Dm*Dm;   b = bg1 + i*Dm;   out = g_ga + ic*Dm;   nd = Dm;   v = vp; col = j - 2048; }
    else               { W = Wg2 + i*Dm*Dm;   b = bg2 + i*Dm;   out = g_gb + ic*Dm;   nd = Dm;   v = vp; col = j - 2560; }
    float acc = b[col];
    #pragma unroll 8
    for (int k = 0; k < Dm; k++) acc += v[k] * W[k*nd + col];
    out[col] = acc;
}

// ---------------- embed ----------------
__global__ void embed_kernel(const float* __restrict__ z, const float* __restrict__ frames,
                             const int* __restrict__ actions,
                             const float* __restrict__ Wp, const float* __restrict__ bp,
                             const float* __restrict__ regs, const float* __restrict__ pe,
                             const float* __restrict__ aemb){
    int t = blockIdx.x;
    int tid = threadIdx.x;
    int f, s;
    const float* img;
    const float* special = nullptr;
    if (t < NZR) {
        f = t / SEQ; s = t % SEQ; img = z;
        if (s == SEQ-1) special = regs;
    } else {
        int u = t - NZR; f = u / SEQ; s = u % SEQ; img = frames;
        if (s == SEQ-1) special = aemb + actions[f]*Dm;
    }
    if (special){
        for (int d = tid; d < Dm; d += 128) g_state[t*Dm + d] = special[d];
        return;
    }
    __shared__ float pv[12];
    if (tid < 12){
        int c = tid >> 2, ph = (tid >> 1) & 1, pw = tid & 1;
        int h2 = s >> 4, w2 = s & 15;
        pv[tid] = img[f*3072 + c*1024 + (h2*2 + ph)*32 + (w2*2 + pw)];
    }
    __syncthreads();
    for (int d = tid; d < Dm; d += 128){
        float acc = bp[d] + pe[s*Dm + d];
        #pragma unroll
        for (int jj = 0; jj < 12; jj++) acc += pv[jj] * Wp[jj*Dm + d];
        g_state[t*Dm + d] = acc;
    }
}

// ---------------- weight prep (batched over DiT blocks via blockIdx.z) ----------------
__global__ void transp_split(const float* __restrict__ in, __nv_bfloat16* __restrict__ ohi,
                             __nv_bfloat16* __restrict__ olo, int K, int N, int il,
                             size_t inz, size_t outz){
    in  += (size_t)blockIdx.z * inz;
    ohi += (size_t)blockIdx.z * outz;
    olo += (size_t)blockIdx.z * outz;
    __shared__ float t[32][33];
    int r0 = blockIdx.x*32, k0 = blockIdx.y*32;
    int tx = threadIdx.x, ty = threadIdx.y;
    int u0 = r0 >> 1;
    for (int i = ty; i < 32; i += 8){
        int col = il ? ((tx < 16) ? (u0 + tx) : (HIDm + u0 + tx - 16)) : (r0 + tx);
        t[i][tx] = in[(size_t)(k0 + i)*N + col];
    }
    __syncthreads();
    for (int j = ty; j < 32; j += 8){
        int ci = il ? ((j>>1) + ((j&1)?16:0)) : j;
        float v = t[tx][ci];
        __nv_bfloat16 h = __float2bfloat16(v);
        __nv_bfloat16 l = __float2bfloat16(v - __bfloat162float(h));
        size_t o = (size_t)(r0 + j)*K + k0 + tx;
        ohi[o] = h; olo[o] = l;
    }
}

__global__ void prep_bias(const float* __restrict__ bq, const float* __restrict__ bk,
                          const float* __restrict__ bv, const float* __restrict__ bgg){
    int i = blockIdx.x;
    for (int j = threadIdx.x; j < QKVD; j += 256){
        float v = (j < 512) ? bq[i*512 + j] : (j < 1024) ? bk[i*512 + j - 512] : bv[i*512 + j - 1024];
        g_bqkv[i*QKVD + j] = v;
    }
    for (int p = threadIdx.x; p < 2*HIDm; p += 256){
        int u = p >> 1;
        g_bgg2[i*2*HIDm + p] = (p & 1) ? bgg[i*2*HIDm + HIDm + u] : bgg[i*2*HIDm + u];
    }
}

// ---------------- AdaLN mod1: state -> nh/nl split ----------------
__global__ void mod_kernel(int blk){
    int t = blockIdx.x, tid = threadIdx.x;
    int c = frame_class(t);
    float4 v = ((const float4*)(g_state + (size_t)t*Dm))[tid];
    float s = v.x+v.y+v.z+v.w;
    float q = v.x*v.x + v.y*v.y + v.z*v.z + v.w*v.w;
    blockReduce2(s, q);
    float mu  = s * (1.0f/Dm);
    float var = q * (1.0f/Dm) - mu*mu;
    float rstd = rsqrtf(var + 1e-5f);
    const float* ms = g_m1 + (blk*7 + c)*1024;
    int d = tid*4;
    float o0 = (v.x-mu)*rstd*(1.0f+ms[d+0]) + ms[512+d+0];
    float o1 = (v.y-mu)*rstd*(1.0f+ms[d+1]) + ms[512+d+1];
    float o2 = (v.z-mu)*rstd*(1.0f+ms[d+2]) + ms[512+d+2];
    float o3 = (v.w-mu)*rstd*(1.0f+ms[d+3]) + ms[512+d+3];
    uint32_t h0,l0,h1,l1;
    split2(o0,o1,h0,l0); split2(o2,o3,h1,l1);
    ((uint2*)(g_nh + (size_t)t*Dm))[tid] = make_uint2(h0,h1);
    ((uint2*)(g_nl + (size_t)t*Dm))[tid] = make_uint2(l0,l1);
}

// ---------------- post-attn: h = mod2( norm*g1 + atto ) -> xh/xl ----------------
__global__ void postattn_kernel(int blk){
    int t = blockIdx.x, tid = threadIdx.x;
    int c = frame_class(t);
    const float* g1v = g_ga + (blk*7 + c)*Dm;
    float4 a = ((const float4*)(g_atto + (size_t)t*Dm))[tid];
    int d = tid*4;
    const __nv_bfloat16* nh = g_nh + (size_t)t*Dm + d;
    const __nv_bfloat16* nl = g_nl + (size_t)t*Dm + d;
    float n0 = __bfloat162float(nh[0]) + __bfloat162float(nl[0]);
    float n1 = __bfloat162float(nh[1]) + __bfloat162float(nl[1]);
    float n2 = __bfloat162float(nh[2]) + __bfloat162float(nl[2]);
    float n3 = __bfloat162float(nh[3]) + __bfloat162float(nl[3]);
    float4 v;
    v.x = n0*g1v[d+0] + a.x;
    v.y = n1*g1v[d+1] + a.y;
    v.z = n2*g1v[d+2] + a.z;
    v.w = n3*g1v[d+3] + a.w;
    float s = v.x+v.y+v.z+v.w;
    float q = v.x*v.x + v.y*v.y + v.z*v.z + v.w*v.w;
    blockReduce2(s, q);
    float mu  = s * (1.0f/Dm);
    float var = q * (1.0f/Dm) - mu*mu;
    float rstd = rsqrtf(var + 1e-5f);
    const float* ms = g_m2 + (blk*7 + c)*1024;
    float o0 = (v.x-mu)*rstd*(1.0f+ms[d+0]) + ms[512+d+0];
    float o1 = (v.y-mu)*rstd*(1.0f+ms[d+1]) + ms[512+d+1];
    float o2 = (v.z-mu)*rstd*(1.0f+ms[d+2]) + ms[512+d+2];
    float o3 = (v.w-mu)*rstd*(1.0f+ms[d+3]) + ms[512+d+3];
    uint32_t h0,l0,h1,l1;
    split2(o0,o1,h0,l0); split2(o2,o3,h1,l1);
    ((uint2*)(g_xh + (size_t)t*Dm))[tid] = make_uint2(h0,h1);
    ((uint2*)(g_xl + (size_t)t*Dm))[tid] = make_uint2(l0,l1);
}

// ---------------- bf16 split GEMM on mma.sync (HMMA), templated M-tile + #terms ----------------
// C[M,N] += A @ B^T with A = Ah+Al ([M][K] bf16 split), B rows = out cols ([N][K] split).
// TERMS==3: ah*bh + ah*bl + al*bh   TERMS==2: ah*bh + ah*bl (A-low never loaded)
// mode 0: C fp32 = acc + bias
// mode 1: GEGLU interleaved: out[m][u] = (a+ba)*gelu(g+bg), split bf16 into Oh/Ol (stride HIDm)
// mode 2: C fp32 = (acc + bias) * g_gb
template<int BM, int TERMS>
__global__ __launch_bounds__(BM*2) void gemm_mma_t(
    const __nv_bfloat16* __restrict__ Ah, const __nv_bfloat16* __restrict__ Al,
    const __nv_bfloat16* __restrict__ Bh, const __nv_bfloat16* __restrict__ Bl,
    const float* __restrict__ bias, float* __restrict__ C,
    __nv_bfloat16* __restrict__ Oh, __nv_bfloat16* __restrict__ Ol,
    int M, int N, int K, int mode, int blk)
{
    constexpr int T   = BM*2;
    constexpr int ASZ = BM*128;          // bytes of one A tile (BM x 64 bf16)
    constexpr int BUF = 2*ASZ + 32768;
    extern __shared__ char smem[];
    uint32_t sb = smem_u32(smem);
    int tid = threadIdx.x, lane = tid & 31, wid = tid >> 5;
    int bm = blockIdx.y * BM, bn = blockIdx.x * 128;
    int wm = wid >> 1, wn = wid & 1;
    int lr = lane & 7, mid = lane >> 3;

    float acc[2][8][4];
    #pragma unroll
    for (int i=0;i<2;i++)
        #pragma unroll
        for (int j=0;j<8;j++)
            #pragma unroll
            for (int k=0;k<4;k++) acc[i][j][k] = 0.f;

    auto load_chunk = [&](int cc, int buf){
        int kc = cc << 6;
        uint32_t sbase = sb + buf*BUF;
        #pragma unroll
        for (int p = 0; p < BM*8/T; p++){
            int idx = p*T + tid;
            int r = idx >> 3, ch = idx & 7;
            uint32_t so = SW128((uint32_t)(r*128 + ch*16));
            int row = bm + r;
            size_t aoff = (size_t)((row < M) ? row : (M-1))*K + kc + ch*8;
            uint32_t pr = (row < M) ? 16u : 0u;
            asm volatile("cp.async.cg.shared.global [%0], [%1], 16, %2;" :: "r"(sbase + so),       "l"(Ah + aoff), "r"(pr));
            if (TERMS == 3)
                asm volatile("cp.async.cg.shared.global [%0], [%1], 16, %2;" :: "r"(sbase + ASZ + so), "l"(Al + aoff), "r"(pr));
        }
        #pragma unroll
        for (int p = 0; p < 1024/T; p++){
            int idx = p*T + tid;
            int r = idx >> 3, ch = idx & 7;
            uint32_t so = SW128((uint32_t)(r*128 + ch*16));
            size_t boff = (size_t)(bn + r)*K + kc + ch*8;
            asm volatile("cp.async.cg.shared.global [%0], [%1], 16;" :: "r"(sbase + 2*ASZ + so),         "l"(Bh + boff));
            asm volatile("cp.async.cg.shared.global [%0], [%1], 16;" :: "r"(sbase + 2*ASZ + 16384 + so), "l"(Bl + boff));
        }
        asm volatile("cp.async.commit_group;" ::: "memory");
    };

    int nchunk = K >> 6;
    load_chunk(0, 0);
    for (int c = 0; c < nchunk; c++){
        int buf = c & 1;
        if (c + 1 < nchunk){
            load_chunk(c + 1, buf ^ 1);
            asm volatile("cp.async.wait_group 1;" ::: "memory");
        } else {
            asm volatile("cp.async.wait_group 0;" ::: "memory");
        }
        __syncthreads();
        uint32_t abase = sb + buf*BUF;
        uint32_t bbase = abase + 2*ASZ;
        #pragma unroll
        for (int ks = 0; ks < 4; ks++){
            uint32_t ah[2][4], al[2][4];
            #pragma unroll
            for (int mf = 0; mf < 2; mf++){
                int row = wm*32 + mf*16 + (mid & 1)*8 + lr;
                uint32_t off = SW128((uint32_t)(row*128 + (ks*2 + (mid >> 1))*16));
                ldsm4(ah[mf], abase + off);
                if (TERMS == 3) ldsm4(al[mf], abase + ASZ + off);
            }
            uint32_t bh[4][4], bl[4][4];
            #pragma unroll
            for (int np = 0; np < 4; np++){
                int row = wn*64 + np*16 + (mid >> 1)*8 + lr;
                uint32_t off = SW128((uint32_t)(row*128 + (ks*2 + (mid & 1))*16));
                ldsm4(bh[np], bbase + off);
                ldsm4(bl[np], bbase + 16384 + off);
            }
            #pragma unroll
            for (int mf = 0; mf < 2; mf++){
                #pragma unroll
                for (int nf = 0; nf < 8; nf++){
                    uint32_t* ph = &bh[nf >> 1][(nf & 1)*2];
                    uint32_t* pl = &bl[nf >> 1][(nf & 1)*2];
                    mma_bf16(acc[mf][nf], ah[mf], ph[0], ph[1]);
                    mma_bf16(acc[mf][nf], ah[mf], pl[0], pl[1]);
                    if (TERMS == 3) mma_bf16(acc[mf][nf], al[mf], ph[0], ph[1]);
                }
            }
        }
        __syncthreads();
    }

    // epilogue
    #pragma unroll
    for (int mf = 0; mf < 2; mf++){
        int m0 = bm + wm*32 + mf*16 + (lane >> 2);
        #pragma unroll
        for (int half = 0; half < 2; half++){
            int m = m0 + half*8;
            if (m >= M) continue;
            #pragma unroll
            for (int nf = 0; nf < 8; nf++){
                float d0 = acc[mf][nf][half*2 + 0];
                float d1 = acc[mf][nf][half*2 + 1];
                int c0 = bn + wn*64 + nf*8 + (lane & 3)*2;
                if (mode == 0){
                    float2 o = make_float2(d0 + bias[c0], d1 + bias[c0+1]);
                    *(float2*)(C + (size_t)m*N + c0) = o;
                } else if (mode == 1){
                    float a = d0 + bias[c0];
                    float g = d1 + bias[c0+1];
                    float ge = 0.5f*g*(1.0f + erff(g*0.70710678118654752440f));
                    float v = a*ge;
                    int u = c0 >> 1;
                    __nv_bfloat16 hh = __float2bfloat16(v);
                    __nv_bfloat16 ll = __float2bfloat16(v - __bfloat162float(hh));
                    Oh[(size_t)m*HIDm + u] = hh;
                    Ol[(size_t)m*HIDm + u] = ll;
                } else {
                    const float* gv = g_gb + (blk*7 + frame_class(m))*Dm;
                    float2 o;
                    o.x = (d0 + bias[c0])   * gv[c0];
                    o.y = (d1 + bias[c0+1]) * gv[c0+1];
                    *(float2*)(C + (size_t)m*N + c0) = o;
                }
            }
        }
    }
}

// ---------------- flash attention (HMMA, pure bf16), 64 queries x 64-key blocks ----------------
// grid: (nframes, 5 qtiles, 8 heads), 128 threads (4 warps x 16 q rows)
__global__ __launch_bounds__(128) void fattn(const float* __restrict__ QKV){
    int frame = blockIdx.x, qt = blockIdx.y, h = blockIdx.z;
    int qbase, r0s, r0n, r1s, r1n;
    if (frame < 6){
        qbase = frame*SEQ;
        r0s = frame*SEQ;              r0n = SEQ;
        int lo = frame-4; if (lo < 0) lo = 0;
        r1s = NZR + lo*SEQ;           r1n = (frame - lo)*SEQ;
    } else {
        int f = frame - 6;
        qbase = NZR + f*SEQ;
        r0s = NZR;                    r0n = (f+1)*SEQ;
        r1s = 0;                      r1n = 0;
    }
    int nk = r0n + r1n;
    int q0 = qt*64;
    int nq = SEQ - q0; if (nq > 64) nq = 64;   // qt=4 -> nq=1

    __shared__ __align__(128) char sbuf[24576];
    char* sQh = sbuf;
    char* sKc = sbuf + 8192;
    char* sVc = sbuf + 16384;
    uint32_t bQh = smem_u32(sQh), bK = smem_u32(sKc), bV = smem_u32(sVc);
    int tid = threadIdx.x, lane = tid & 31, wid = tid >> 5;
    int lr = lane & 7, mid = lane >> 3;

    // load Q tile (bf16)
    for (int idx = tid; idx < 1024; idx += 128){
        int r = idx >> 4, c4 = idx & 15;
        int rr = (r < nq) ? r : (nq-1);
        float4 v = *(const float4*)(QKV + (size_t)(qbase + q0 + rr)*QKVD + h*DH + c4*4);
        uint32_t off = SW128((uint32_t)(r*128 + c4*8));
        *(uint2*)(sQh + off) = pack4h(v);
    }
    __syncthreads();
    uint32_t qh[4][4];
    #pragma unroll
    for (int ks = 0; ks < 4; ks++){
        uint32_t off = SW128((uint32_t)((wid*16 + (mid&1)*8 + lr)*128 + (ks*2 + (mid>>1))*16));
        ldsm4(qh[ks], bQh + off);
    }

    float o[8][4];
    #pragma unroll
    for (int j=0;j<8;j++){ o[j][0]=0.f;o[j][1]=0.f;o[j][2]=0.f;o[j][3]=0.f; }
    float m0=-1e30f, m1=-1e30f, l0=0.f, l1=0.f;

    int nkb = (nk + 63) >> 6;
    for (int kb = 0; kb < nkb; kb++){
        int k0 = kb << 6;
        __syncthreads();
        for (int idx = tid; idx < 1024; idx += 128){
            int r = idx >> 4, c4 = idx & 15;
            int i = k0 + r;
            int g = (i < r0n) ? (r0s + i) : ((i < nk) ? (r1s + i - r0n) : r0s);
            const float* base = QKV + (size_t)g*QKVD + h*DH + c4*4;
            float4 kv = *(const float4*)(base + 512);
            float4 vv = *(const float4*)(base + 1024);
            uint32_t off = SW128((uint32_t)(r*128 + c4*8));
            *(uint2*)(sKc + off) = pack4h(kv);
            *(uint2*)(sVc + off) = pack4h(vv);
        }
        __syncthreads();

        // S = Q K^T
        float s[8][4];
        #pragma unroll
        for (int j=0;j<8;j++){ s[j][0]=0.f;s[j][1]=0.f;s[j][2]=0.f;s[j][3]=0.f; }
        #pragma unroll
        for (int ks = 0; ks < 4; ks++){
            #pragma unroll
            for (int np = 0; np < 4; np++){
                uint32_t bk[4];
                uint32_t off = SW128((uint32_t)((np*16 + (mid>>1)*8 + lr)*128 + (ks*2 + (mid&1))*16));
                ldsm4(bk, bK + off);
                mma_bf16(s[np*2],   qh[ks], bk[0], bk[1]);
                mma_bf16(s[np*2+1], qh[ks], bk[2], bk[3]);
            }
        }
        // online softmax
        float mx0 = -1e30f, mx1 = -1e30f;
        #pragma unroll
        for (int j = 0; j < 8; j++){
            int c = k0 + j*8 + (lane & 3)*2;
            s[j][0] = (c   < nk) ? s[j][0]*0.125f : -1e30f;
            s[j][1] = (c+1 < nk) ? s[j][1]*0.125f : -1e30f;
            s[j][2] = (c   < nk) ? s[j][2]*0.125f : -1e30f;
            s[j][3] = (c+1 < nk) ? s[j][3]*0.125f : -1e30f;
            mx0 = fmaxf(mx0, fmaxf(s[j][0], s[j][1]));
            mx1 = fmaxf(mx1, fmaxf(s[j][2], s[j][3]));
        }
        mx0 = fmaxf(mx0, __shfl_xor_sync(0xffffffffu, mx0, 1));
        mx0 = fmaxf(mx0, __shfl_xor_sync(0xffffffffu, mx0, 2));
        mx1 = fmaxf(mx1, __shfl_xor_sync(0xffffffffu, mx1, 1));
        mx1 = fmaxf(mx1, __shfl_xor_sync(0xffffffffu, mx1, 2));
        float mn0 = fmaxf(m0, mx0), mn1 = fmaxf(m1, mx1);
        float f0 = __expf(m0 - mn0), f1 = __expf(m1 - mn1);
        m0 = mn0; m1 = mn1;
        l0 *= f0; l1 *= f1;
        #pragma unroll
        for (int j=0;j<8;j++){ o[j][0]*=f0; o[j][1]*=f0; o[j][2]*=f1; o[j][3]*=f1; }
        uint32_t pp[8][2];
        #pragma unroll
        for (int j = 0; j < 8; j++){
            float p0 = __expf(s[j][0]-m0), p1 = __expf(s[j][1]-m0);
            float p2 = __expf(s[j][2]-m1), p3 = __expf(s[j][3]-m1);
            l0 += p0 + p1; l1 += p2 + p3;
            pp[j][0] = pack2h(p0, p1);
            pp[j][1] = pack2h(p2, p3);
        }
        // O += P V
        #pragma unroll
        for (int ks = 0; ks < 4; ks++){
            uint32_t ah[4] = {pp[2*ks][0], pp[2*ks][1], pp[2*ks+1][0], pp[2*ks+1][1]};
            #pragma unroll
            for (int vd = 0; vd < 4; vd++){
                uint32_t bv[4];
                uint32_t off = SW128((uint32_t)((ks*16 + (lane & 15))*128 + vd*32 + (lane >> 4)*16));
                ldsm4t(bv, bV + off);
                mma_bf16(o[vd*2],   ah, bv[0], bv[1]);
                mma_bf16(o[vd*2+1], ah, bv[2], bv[3]);
            }
        }
    }
    l0 += __shfl_xor_sync(0xffffffffu, l0, 1);
    l0 += __shfl_xor_sync(0xffffffffu, l0, 2);
    l1 += __shfl_xor_sync(0xffffffffu, l1, 1);
    l1 += __shfl_xor_sync(0xffffffffu, l1, 2);
    float i0 = 1.0f/l0, i1 = 1.0f/l1;
    int row0 = wid*16 + (lane >> 2);
    #pragma unroll
    for (int j = 0; j < 8; j++){
        int c = j*8 + (lane & 3)*2;
        if (row0 < nq){
            size_t idx = (size_t)(qbase + q0 + row0)*Dm + h*DH + c;
            uint32_t hh, ll;
            split2(o[j][0]*i0, o[j][1]*i0, hh, ll);
            *(uint32_t*)(g_xh + idx) = hh;
            *(uint32_t*)(g_xl + idx) = ll;
        }
        if (row0 + 8 < nq){
            size_t idx = (size_t)(qbase + q0 + row0 + 8)*Dm + h*DH + c;
            uint32_t hh, ll;
            split2(o[j][2]*i1, o[j][3]*i1, hh, ll);
            *(uint32_t*)(g_xh + idx) = hh;
            *(uint32_t*)(g_xl + idx) = ll;
        }
    }
}

// ---------------- unpatch ----------------
__global__ void unpatch_kernel(const float* __restrict__ Wu, const float* __restrict__ bu,
                               float* __restrict__ out){
    int token = blockIdx.x;
    int f = token >> 8, s = token & 255;
    const float* x = g_state + (size_t)(f*SEQ + s)*Dm;
    __shared__ float xs[Dm];
    int tid = threadIdx.x;
    for (int d2 = tid; d2 < Dm; d2 += 128) xs[d2] = x[d2];
    __syncthreads();
    int warp = tid >> 5, lane = tid & 31;
    for (int j = warp; j < 12; j += 4){
        float acc = 0.f;
        for (int d2 = lane; d2 < Dm; d2 += 32) acc += xs[d2] * Wu[d2*12 + j];
        acc = warpSum(acc);
        if (lane == 0){
            int c = j >> 2, ph = (j >> 1) & 1, pw = j & 1;
            int h2 = s >> 4, w2 = s & 15;
            out[f*3072 + c*1024 + (h2*2 + ph)*32 + (w2*2 + pw)] = acc + bu[j];
        }
    }
}

// ---------------- host ----------------
template <typename T>
static T* symaddr(const void* sym){
    void* p = nullptr;
    cudaGetSymbolAddress(&p, sym);
    return (T*)p;
}

extern "C" void kernel_launch(void* const* d_in, const int* in_sizes, int n_in,
                              void* d_out, int out_size){
    const float* z        = (const float*)d_in[0];
    const float* frames   = (const float*)d_in[1];
    const int*   actions  = (const int*)  d_in[2];
    const int*   ts       = (const int*)  d_in[3];
    const float* W_patch  = (const float*)d_in[4];
    const float* b_patch  = (const float*)d_in[5];
    const float* W_unpatch= (const float*)d_in[6];
    const float* b_unpatch= (const float*)d_in[7];
    const float* registers= (const float*)d_in[8];
    const float* pe_grid  = (const float*)d_in[9];
    const float* action_e = (const float*)d_in[10];
    const float* time_emb = (const float*)d_in[11];
    const float* W_mod1   = (const float*)d_in[12];
    const float* b_mod1   = (const float*)d_in[13];
    const float* W_mod2   = (const float*)d_in[14];
    const float* b_mod2   = (const float*)d_in[15];
    const float* W_q      = (const float*)d_in[16];
    const float* b_q      = (const float*)d_in[17];
    const float* W_k      = (const float*)d_in[18];
    const float* b_k      = (const float*)d_in[19];
    const float* W_v      = (const float*)d_in[20];
    const float* b_v      = (const float*)d_in[21];
    const float* W_o      = (const float*)d_in[22];
    const float* b_o      = (const float*)d_in[23];
    const float* W_g1     = (const float*)d_in[24];
    const float* b_g1     = (const float*)d_in[25];
    const float* W_g2     = (const float*)d_in[26];
    const float* b_g2     = (const float*)d_in[27];
    const float* W_geglu  = (const float*)d_in[28];
    const float* b_geglu  = (const float*)d_in[29];
    const float* W_ffout  = (const float*)d_in[30];
    const float* b_ffout  = (const float*)d_in[31];
    float* out = (float*)d_out;

    float* pState = symaddr<float>(g_state);
    float* pQKV   = symaddr<float>(g_qkv);
    float* pAtto  = symaddr<float>(g_atto);
    float* pBqkv  = symaddr<float>(g_bqkv);
    float* pBgg   = symaddr<float>(g_bgg2);
    __nv_bfloat16* nh = symaddr<__nv_bfloat16>(g_nh);
    __nv_bfloat16* nl = symaddr<__nv_bfloat16>(g_nl);
    __nv_bfloat16* xh = symaddr<__nv_bfloat16>(g_xh);
    __nv_bfloat16* xl = symaddr<__nv_bfloat16>(g_xl);
    __nv_bfloat16* yh = symaddr<__nv_bfloat16>(g_yh);
    __nv_bfloat16* yl = symaddr<__nv_bfloat16>(g_yl);
    __nv_bfloat16* wqkvh = symaddr<__nv_bfloat16>(g_wqkv_h);
    __nv_bfloat16* wqkvl = symaddr<__nv_bfloat16>(g_wqkv_l);
    __nv_bfloat16* woh   = symaddr<__nv_bfloat16>(g_wo_h);
    __nv_bfloat16* wol   = symaddr<__nv_bfloat16>(g_wo_l);
    __nv_bfloat16* wggh  = symaddr<__nv_bfloat16>(g_wgg_h);
    __nv_bfloat16* wggl  = symaddr<__nv_bfloat16>(g_wgg_l);
    __nv_bfloat16* wffh  = symaddr<__nv_bfloat16>(g_wff_h);
    __nv_bfloat16* wffl  = symaddr<__nv_bfloat16>(g_wff_l);

    cudaFuncSetAttribute(gemm_mma_t<128,3>, cudaFuncAttributeMaxDynamicSharedMemorySize, 131072);
    cudaFuncSetAttribute(gemm_mma_t<128,2>, cudaFuncAttributeMaxDynamicSharedMemorySize, 131072);
    cudaFuncSetAttribute(gemm_mma_t<64,3>,  cudaFuncAttributeMaxDynamicSharedMemorySize, 98304);

    cond_kernel<<<7, 128>>>(ts, time_emb);
    modvec_kernel<<<dim3(NBLK*7, 12), 256>>>(W_mod1, b_mod1, W_mod2, b_mod2,
                                             W_g1, b_g1, W_g2, b_g2);
    embed_kernel<<<NTOK, 128>>>(z, frames, actions, W_patch, b_patch,
                                registers, pe_grid, action_e);

    dim3 tb(32, 8);
    transp_split<<<dim3(16,16,NBLK), tb>>>(W_q, wqkvh,              wqkvl,              512, 512, 0,
                                           (size_t)512*512, (size_t)QKVD*512);
    transp_split<<<dim3(16,16,NBLK), tb>>>(W_k, wqkvh + 512*512,    wqkvl + 512*512,    512, 512, 0,
                                           (size_t)512*512, (size_t)QKVD*512);
    transp_split<<<dim3(16,16,NBLK), tb>>>(W_v, wqkvh + 1024*512,   wqkvl + 1024*512,   512, 512, 0,
                                           (size_t)512*512, (size_t)QKVD*512);
    transp_split<<<dim3(16,16,NBLK), tb>>>(W_o, woh, wol, 512, 512, 0,
                                           (size_t)512*512, (size_t)512*512);
    transp_split<<<dim3(128,16,NBLK), tb>>>(W_geglu, wggh, wggl, 512, 4096, 1,
                                            (size_t)512*4096, (size_t)4096*512);
    transp_split<<<dim3(16,64,NBLK), tb>>>(W_ffout, wffh, wffl, 2048, 512, 0,
                                           (size_t)2048*512, (size_t)512*2048);
    prep_bias<<<NBLK, 256>>>(b_q, b_k, b_v, b_geglu);

    for (int i = 0; i < NBLK; i++){
        // Last block: xa stream's post-attention work is dead (only zr reaches the output).
        int Mpost   = (i == NBLK-1) ? NZR : NTOK;
        int nframes = (i == NBLK-1) ? 6   : 11;
        int mt128   = (Mpost + 127) / 128;
        int mt64    = (Mpost + 63) / 64;
        int qt128   = (NTOK + 127) / 128;   // QKV always full (K/V needed for cross-attn)

        mod_kernel<<<NTOK, 128>>>(i);
        gemm_mma_t<128,2><<<dim3(QKVD/128, qt128), 256, 131072>>>(nh, nl,
            wqkvh + (size_t)i*QKVD*512, wqkvl + (size_t)i*QKVD*512,
            pBqkv + i*QKVD, pQKV, nullptr, nullptr, NTOK, QKVD, 512, 0, i);
        fattn<<<dim3(nframes, 5, NHh), 128>>>(pQKV);
        gemm_mma_t<64,3><<<dim3(4, mt64), 128, 98304>>>(xh, xl,
            woh + (size_t)i*512*512, wol + (size_t)i*512*512,
            b_o + i*512, pAtto, nullptr, nullptr, Mpost, 512, 512, 0, i);
        postattn_kernel<<<Mpost, 128>>>(i);
        gemm_mma_t<128,3><<<dim3(32, mt128), 256, 131072>>>(xh, xl,
            wggh + (size_t)i*4096*512, wggl + (size_t)i*4096*512,
            pBgg + i*4096, nullptr, yh, yl, Mpost, 4096, 512, 1, i);
        gemm_mma_t<64,3><<<dim3(4, mt64), 128, 98304>>>(yh, yl,
            wffh + (size_t)i*512*2048, wffl + (size_t)i*512*2048,
            b_ffout + i*512, pState, nullptr, nullptr, Mpost, 512, 2048, 2, i);
    }
    unpatch_kernel<<<1536, 128>>>(W_unpatch, b_unpatch, out);
}

// round 16
// speedup vs baseline: 4.6685x; 1.0406x over previous
#include <cuda_runtime.h>
#include <cuda_bf16.h>
#include <cstdint>
#include <math.h>

// ---------------- problem constants ----------------
#define Dm    512
#define NHh   8
#define DH    64
#define NBLK  6
#define SEQ   257
#define NZR   1542
#define NXA   1285
#define NTOK  2827
#define HIDm  2048
#define QKVD  1536

// ---------------- scratch ----------------
__device__ float g_state[NTOK*Dm];
__device__ __nv_bfloat16 g_qkvb[NTOK*QKVD];   // bf16 QKV (post-bias)
__device__ float g_atto [NTOK*Dm];

__device__ __nv_bfloat16 g_nh[NTOK*Dm];     // norm split
__device__ __nv_bfloat16 g_nl[NTOK*Dm];
__device__ __nv_bfloat16 g_xh[NTOK*Dm];     // att / h split
__device__ __nv_bfloat16 g_xl[NTOK*Dm];
__device__ __nv_bfloat16 g_yh[NTOK*HIDm];   // act split
__device__ __nv_bfloat16 g_yl[NTOK*HIDm];

__device__ float g_cond [7*Dm];
__device__ float g_silu [7*Dm];
__device__ float g_m1   [NBLK*7*1024];
__device__ float g_m2   [NBLK*7*1024];
__device__ float g_ga   [NBLK*7*Dm];
__device__ float g_gb   [NBLK*7*Dm];

// pre-transposed, split weights (row = output col n, K contiguous)
__device__ __nv_bfloat16 g_wqkv_h[NBLK*QKVD*Dm];
__device__ __nv_bfloat16 g_wqkv_l[NBLK*QKVD*Dm];
__device__ __nv_bfloat16 g_wo_h  [NBLK*Dm*Dm];
__device__ __nv_bfloat16 g_wo_l  [NBLK*Dm*Dm];
__device__ __nv_bfloat16 g_wgg_h [NBLK*2*HIDm*Dm];
__device__ __nv_bfloat16 g_wgg_l [NBLK*2*HIDm*Dm];
__device__ __nv_bfloat16 g_wff_h [NBLK*Dm*HIDm];
__device__ __nv_bfloat16 g_wff_l [NBLK*Dm*HIDm];
__device__ float g_bqkv[NBLK*QKVD];
__device__ float g_bgg2[NBLK*2*HIDm];

// ---------------- helpers ----------------
__device__ __forceinline__ uint32_t smem_u32(const void* p){
    uint32_t a;
    asm("{ .reg .u64 t; cvta.to.shared.u64 t, %1; cvt.u32.u64 %0, t; }" : "=r"(a) : "l"(p));
    return a;
}
#define SW128(off) ((off) ^ (((off)>>3) & 0x70))

__device__ __forceinline__ void ldsm4(uint32_t* r, uint32_t addr){
    asm volatile("ldmatrix.sync.aligned.m8n8.x4.shared.b16 {%0,%1,%2,%3}, [%4];"
        : "=r"(r[0]), "=r"(r[1]), "=r"(r[2]), "=r"(r[3]) : "r"(addr));
}
__device__ __forceinline__ void ldsm4t(uint32_t* r, uint32_t addr){
    asm volatile("ldmatrix.sync.aligned.m8n8.x4.trans.shared.b16 {%0,%1,%2,%3}, [%4];"
        : "=r"(r[0]), "=r"(r[1]), "=r"(r[2]), "=r"(r[3]) : "r"(addr));
}
__device__ __forceinline__ void mma_bf16(float* d, const uint32_t* a, uint32_t b0, uint32_t b1){
    asm volatile("mma.sync.aligned.m16n8k16.row.col.f32.bf16.bf16.f32 "
        "{%0,%1,%2,%3}, {%4,%5,%6,%7}, {%8,%9}, {%0,%1,%2,%3};"
        : "+f"(d[0]), "+f"(d[1]), "+f"(d[2]), "+f"(d[3])
        : "r"(a[0]), "r"(a[1]), "r"(a[2]), "r"(a[3]), "r"(b0), "r"(b1));
}

__device__ __forceinline__ float warpSum(float v){
    #pragma unroll
    for (int o = 16; o > 0; o >>= 1) v += __shfl_xor_sync(0xffffffffu, v, o);
    return v;
}
__device__ __forceinline__ void blockReduce2(float& s, float& q){
    s = warpSum(s); q = warpSum(q);
    __shared__ float sh[8];
    int w = threadIdx.x >> 5;
    if ((threadIdx.x & 31) == 0) { sh[w] = s; sh[4+w] = q; }
    __syncthreads();
    s = sh[0]+sh[1]+sh[2]+sh[3];
    q = sh[4]+sh[5]+sh[6]+sh[7];
    __syncthreads();
}
__device__ __forceinline__ int frame_class(int t){ return (t < NZR) ? (t / SEQ) : 6; }

__device__ __forceinline__ void split2(float x, float y, uint32_t& h, uint32_t& l){
    __nv_bfloat16 hx = __float2bfloat16(x), hy = __float2bfloat16(y);
    __nv_bfloat16 lx = __float2bfloat16(x - __bfloat162float(hx));
    __nv_bfloat16 ly = __float2bfloat16(y - __bfloat162float(hy));
    h = (uint32_t)__bfloat16_as_ushort(hx) | ((uint32_t)__bfloat16_as_ushort(hy) << 16);
    l = (uint32_t)__bfloat16_as_ushort(lx) | ((uint32_t)__bfloat16_as_ushort(ly) << 16);
}
__device__ __forceinline__ uint32_t pack2h(float x, float y){
    __nv_bfloat16 a = __float2bfloat16(x), b = __float2bfloat16(y);
    return (uint32_t)__bfloat16_as_ushort(a) | ((uint32_t)__bfloat16_as_ushort(b) << 16);
}

// ---------------- conditioning ----------------
__global__ void cond_kernel(const int* __restrict__ ts, const float* __restrict__ time_emb){
    int c = blockIdx.x;
    int row = (c < 6) ? ts[c] : 0;
    for (int d = threadIdx.x; d < Dm; d += blockDim.x){
        float x = time_emb[row*Dm + d];
        g_cond[c*Dm + d] = x;
        g_silu[c*Dm + d] = x / (1.0f + expf(-x));
    }
}

__global__ void modvec_kernel(const float* __restrict__ Wm1, const float* __restrict__ bm1,
                              const float* __restrict__ Wm2, const float* __restrict__ bm2,
                              const float* __restrict__ Wg1, const float* __restrict__ bg1,
                              const float* __restrict__ Wg2, const float* __restrict__ bg2){
    int ic = blockIdx.x;
    int i  = ic / 7, c = ic % 7;
    int j  = blockIdx.y * 256 + threadIdx.x;
    __shared__ float vs[Dm], vp[Dm];
    for (int k = threadIdx.x; k < Dm; k += 256){
        vs[k] = g_silu[c*Dm + k];
        vp[k] = g_cond[c*Dm + k];
    }
    __syncthreads();
    const float* W; const float* b; float* out; int nd; const float* v; int col;
    if (j < 1024)      { W = Wm1 + i*Dm*1024; b = bm1 + i*1024; out = g_m1 + ic*1024; nd = 1024; v = vs; col = j; }
    else if (j < 2048) { W = Wm2 + i*Dm*1024; b = bm2 + i*1024; out = g_m2 + ic*1024; nd = 1024; v = vs; col = j - 1024; }
    else if (j < 2560) { W = Wg1 + i*Dm*Dm;   b = bg1 + i*Dm;   out = g_ga + ic*Dm;   nd = Dm;   v = vp; col = j - 2048; }
    else               { W = Wg2 + i*Dm*Dm;   b = bg2 + i*Dm;   out = g_gb + ic*Dm;   nd = Dm;   v = vp; col = j - 2560; }
    float acc = b[col];
    #pragma unroll 8
    for (int k = 0; k < Dm; k++) acc += v[k] * W[k*nd + col];
    out[col] = acc;
}

// ---------------- embed ----------------
__global__ void embed_kernel(const float* __restrict__ z, const float* __restrict__ frames,
                             const int* __restrict__ actions,
                             const float* __restrict__ Wp, const float* __restrict__ bp,
                             const float* __restrict__ regs, const float* __restrict__ pe,
                             const float* __restrict__ aemb){
    int t = blockIdx.x;
    int tid = threadIdx.x;
    int f, s;
    const float* img;
    const float* special = nullptr;
    if (t < NZR) {
        f = t / SEQ; s = t % SEQ; img = z;
        if (s == SEQ-1) special = regs;
    } else {
        int u = t - NZR; f = u / SEQ; s = u % SEQ; img = frames;
        if (s == SEQ-1) special = aemb + actions[f]*Dm;
    }
    if (special){
        for (int d = tid; d < Dm; d += 128) g_state[t*Dm + d] = special[d];
        return;
    }
    __shared__ float pv[12];
    if (tid < 12){
        int c = tid >> 2, ph = (tid >> 1) & 1, pw = tid & 1;
        int h2 = s >> 4, w2 = s & 15;
        pv[tid] = img[f*3072 + c*1024 + (h2*2 + ph)*32 + (w2*2 + pw)];
    }
    __syncthreads();
    for (int d = tid; d < Dm; d += 128){
        float acc = bp[d] + pe[s*Dm + d];
        #pragma unroll
        for (int jj = 0; jj < 12; jj++) acc += pv[jj] * Wp[jj*Dm + d];
        g_state[t*Dm + d] = acc;
    }
}

// ---------------- weight prep ----------------
// generic (batched over blocks via z)
__global__ void transp_split(const float* __restrict__ in, __nv_bfloat16* __restrict__ ohi,
                             __nv_bfloat16* __restrict__ olo, int K, int N, int il,
                             size_t inz, size_t outz){
    in  += (size_t)blockIdx.z * inz;
    ohi += (size_t)blockIdx.z * outz;
    olo += (size_t)blockIdx.z * outz;
    __shared__ float t[32][33];
    int r0 = blockIdx.x*32, k0 = blockIdx.y*32;
    int tx = threadIdx.x, ty = threadIdx.y;
    int u0 = r0 >> 1;
    for (int i = ty; i < 32; i += 8){
        int col = il ? ((tx < 16) ? (u0 + tx) : (HIDm + u0 + tx - 16)) : (r0 + tx);
        t[i][tx] = in[(size_t)(k0 + i)*N + col];
    }
    __syncthreads();
    for (int j = ty; j < 32; j += 8){
        int ci = il ? ((j>>1) + ((j&1)?16:0)) : j;
        float v = t[tx][ci];
        __nv_bfloat16 h = __float2bfloat16(v);
        __nv_bfloat16 l = __float2bfloat16(v - __bfloat162float(h));
        size_t o = (size_t)(r0 + j)*K + k0 + tx;
        ohi[o] = h; olo[o] = l;
    }
}

// q/k/v/o 512x512 transposes merged: z = w*NBLK + i, w in 0..3
__global__ void transp_split4(const float* __restrict__ Wq, const float* __restrict__ Wk,
                              const float* __restrict__ Wv, const float* __restrict__ Wo){
    int zi = blockIdx.z;
    int w = zi / NBLK, i = zi % NBLK;
    const float* in;
    __nv_bfloat16 *ohi, *olo;
    if (w == 0){ in = Wq + (size_t)i*512*512; ohi = g_wqkv_h + (size_t)i*QKVD*512;            olo = g_wqkv_l + (size_t)i*QKVD*512; }
    else if (w == 1){ in = Wk + (size_t)i*512*512; ohi = g_wqkv_h + (size_t)i*QKVD*512 + 512*512; olo = g_wqkv_l + (size_t)i*QKVD*512 + 512*512; }
    else if (w == 2){ in = Wv + (size_t)i*512*512; ohi = g_wqkv_h + (size_t)i*QKVD*512 + 1024*512; olo = g_wqkv_l + (size_t)i*QKVD*512 + 1024*512; }
    else { in = Wo + (size_t)i*512*512; ohi = g_wo_h + (size_t)i*512*512; olo = g_wo_l + (size_t)i*512*512; }
    __shared__ float t[32][33];
    int r0 = blockIdx.x*32, k0 = blockIdx.y*32;
    int tx = threadIdx.x, ty = threadIdx.y;
    for (int ii = ty; ii < 32; ii += 8)
        t[ii][tx] = in[(size_t)(k0 + ii)*512 + r0 + tx];
    __syncthreads();
    for (int j = ty; j < 32; j += 8){
        float v = t[tx][j];
        __nv_bfloat16 h = __float2bfloat16(v);
        __nv_bfloat16 l = __float2bfloat16(v - __bfloat162float(h));
        size_t o = (size_t)(r0 + j)*512 + k0 + tx;
        ohi[o] = h; olo[o] = l;
    }
}

__global__ void prep_bias(const float* __restrict__ bq, const float* __restrict__ bk,
                          const float* __restrict__ bv, const float* __restrict__ bgg){
    int i = blockIdx.x;
    for (int j = threadIdx.x; j < QKVD; j += 256){
        float v = (j < 512) ? bq[i*512 + j] : (j < 1024) ? bk[i*512 + j - 512] : bv[i*512 + j - 1024];
        g_bqkv[i*QKVD + j] = v;
    }
    for (int p = threadIdx.x; p < 2*HIDm; p += 256){
        int u = p >> 1;
        g_bgg2[i*2*HIDm + p] = (p & 1) ? bgg[i*2*HIDm + HIDm + u] : bgg[i*2*HIDm + u];
    }
}

// ---------------- AdaLN mod1: state -> nh/nl split ----------------
__global__ void mod_kernel(int blk){
    int t = blockIdx.x, tid = threadIdx.x;
    int c = frame_class(t);
    float4 v = ((const float4*)(g_state + (size_t)t*Dm))[tid];
    float s = v.x+v.y+v.z+v.w;
    float q = v.x*v.x + v.y*v.y + v.z*v.z + v.w*v.w;
    blockReduce2(s, q);
    float mu  = s * (1.0f/Dm);
    float var = q * (1.0f/Dm) - mu*mu;
    float rstd = rsqrtf(var + 1e-5f);
    const float* ms = g_m1 + (blk*7 + c)*1024;
    int d = tid*4;
    float o0 = (v.x-mu)*rstd*(1.0f+ms[d+0]) + ms[512+d+0];
    float o1 = (v.y-mu)*rstd*(1.0f+ms[d+1]) + ms[512+d+1];
    float o2 = (v.z-mu)*rstd*(1.0f+ms[d+2]) + ms[512+d+2];
    float o3 = (v.w-mu)*rstd*(1.0f+ms[d+3]) + ms[512+d+3];
    uint32_t h0,l0,h1,l1;
    split2(o0,o1,h0,l0); split2(o2,o3,h1,l1);
    ((uint2*)(g_nh + (size_t)t*Dm))[tid] = make_uint2(h0,h1);
    ((uint2*)(g_nl + (size_t)t*Dm))[tid] = make_uint2(l0,l1);
}

// ---------------- post-attn: h = mod2( norm*g1 + atto ) -> xh/xl ----------------
__global__ void postattn_kernel(int blk){
    int t = blockIdx.x, tid = threadIdx.x;
    int c = frame_class(t);
    const float* g1v = g_ga + (blk*7 + c)*Dm;
    float4 a = ((const float4*)(g_atto + (size_t)t*Dm))[tid];
    int d = tid*4;
    const __nv_bfloat16* nh = g_nh + (size_t)t*Dm + d;
    const __nv_bfloat16* nl = g_nl + (size_t)t*Dm + d;
    float n0 = __bfloat162float(nh[0]) + __bfloat162float(nl[0]);
    float n1 = __bfloat162float(nh[1]) + __bfloat162float(nl[1]);
    float n2 = __bfloat162float(nh[2]) + __bfloat162float(nl[2]);
    float n3 = __bfloat162float(nh[3]) + __bfloat162float(nl[3]);
    float4 v;
    v.x = n0*g1v[d+0] + a.x;
    v.y = n1*g1v[d+1] + a.y;
    v.z = n2*g1v[d+2] + a.z;
    v.w = n3*g1v[d+3] + a.w;
    float s = v.x+v.y+v.z+v.w;
    float q = v.x*v.x + v.y*v.y + v.z*v.z + v.w*v.w;
    blockReduce2(s, q);
    float mu  = s * (1.0f/Dm);
    float var = q * (1.0f/Dm) - mu*mu;
    float rstd = rsqrtf(var + 1e-5f);
    const float* ms = g_m2 + (blk*7 + c)*1024;
    float o0 = (v.x-mu)*rstd*(1.0f+ms[d+0]) + ms[512+d+0];
    float o1 = (v.y-mu)*rstd*(1.0f+ms[d+1]) + ms[512+d+1];
    float o2 = (v.z-mu)*rstd*(1.0f+ms[d+2]) + ms[512+d+2];
    float o3 = (v.w-mu)*rstd*(1.0f+ms[d+3]) + ms[512+d+3];
    uint32_t h0,l0,h1,l1;
    split2(o0,o1,h0,l0); split2(o2,o3,h1,l1);
    ((uint2*)(g_xh + (size_t)t*Dm))[tid] = make_uint2(h0,h1);
    ((uint2*)(g_xl + (size_t)t*Dm))[tid] = make_uint2(l0,l1);
}

// ---------------- bf16 split GEMM on mma.sync (HMMA), templated M-tile + #terms ----------------
// C[M,N] += A @ B^T with A = Ah+Al ([M][K] bf16 split), B rows = out cols ([N][K] split).
// TERMS==3: ah*bh + ah*bl + al*bh   TERMS==2: ah*bh + ah*bl (A-low never loaded)
// mode 0: C fp32 = acc + bias
// mode 1: GEGLU interleaved: out[m][u] = (a+ba)*gelu(g+bg), split bf16 into Oh/Ol (stride HIDm)
// mode 2: C fp32 = (acc + bias) * g_gb
// mode 3: Oh bf16 = bf16(acc + bias), stride N
template<int BM, int TERMS>
__global__ __launch_bounds__(BM*2) void gemm_mma_t(
    const __nv_bfloat16* __restrict__ Ah, const __nv_bfloat16* __restrict__ Al,
    const __nv_bfloat16* __restrict__ Bh, const __nv_bfloat16* __restrict__ Bl,
    const float* __restrict__ bias, float* __restrict__ C,
    __nv_bfloat16* __restrict__ Oh, __nv_bfloat16* __restrict__ Ol,
    int M, int N, int K, int mode, int blk)
{
    constexpr int T   = BM*2;
    constexpr int ASZ = BM*128;          // bytes of one A tile (BM x 64 bf16)
    constexpr int BUF = 2*ASZ + 32768;
    extern __shared__ char smem[];
    uint32_t sb = smem_u32(smem);
    int tid = threadIdx.x, lane = tid & 31, wid = tid >> 5;
    int bm = blockIdx.y * BM, bn = blockIdx.x * 128;
    int wm = wid >> 1, wn = wid & 1;
    int lr = lane & 7, mid = lane >> 3;

    float acc[2][8][4];
    #pragma unroll
    for (int i=0;i<2;i++)
        #pragma unroll
        for (int j=0;j<8;j++)
            #pragma unroll
            for (int k=0;k<4;k++) acc[i][j][k] = 0.f;

    auto load_chunk = [&](int cc, int buf){
        int kc = cc << 6;
        uint32_t sbase = sb + buf*BUF;
        #pragma unroll
        for (int p = 0; p < BM*8/T; p++){
            int idx = p*T + tid;
            int r = idx >> 3, ch = idx & 7;
            uint32_t so = SW128((uint32_t)(r*128 + ch*16));
            int row = bm + r;
            size_t aoff = (size_t)((row < M) ? row : (M-1))*K + kc + ch*8;
            uint32_t pr = (row < M) ? 16u : 0u;
            asm volatile("cp.async.cg.shared.global [%0], [%1], 16, %2;" :: "r"(sbase + so),       "l"(Ah + aoff), "r"(pr));
            if (TERMS == 3)
                asm volatile("cp.async.cg.shared.global [%0], [%1], 16, %2;" :: "r"(sbase + ASZ + so), "l"(Al + aoff), "r"(pr));
        }
        #pragma unroll
        for (int p = 0; p < 1024/T; p++){
            int idx = p*T + tid;
            int r = idx >> 3, ch = idx & 7;
            uint32_t so = SW128((uint32_t)(r*128 + ch*16));
            size_t boff = (size_t)(bn + r)*K + kc + ch*8;
            asm volatile("cp.async.cg.shared.global [%0], [%1], 16;" :: "r"(sbase + 2*ASZ + so),         "l"(Bh + boff));
            asm volatile("cp.async.cg.shared.global [%0], [%1], 16;" :: "r"(sbase + 2*ASZ + 16384 + so), "l"(Bl + boff));
        }
        asm volatile("cp.async.commit_group;" ::: "memory");
    };

    int nchunk = K >> 6;
    load_chunk(0, 0);
    for (int c = 0; c < nchunk; c++){
        int buf = c & 1;
        if (c + 1 < nchunk){
            load_chunk(c + 1, buf ^ 1);
            asm volatile("cp.async.wait_group 1;" ::: "memory");
        } else {
            asm volatile("cp.async.wait_group 0;" ::: "memory");
        }
        __syncthreads();
        uint32_t abase = sb + buf*BUF;
        uint32_t bbase = abase + 2*ASZ;
        #pragma unroll
        for (int ks = 0; ks < 4; ks++){
            uint32_t ah[2][4], al[2][4];
            #pragma unroll
            for (int mf = 0; mf < 2; mf++){
                int row = wm*32 + mf*16 + (mid & 1)*8 + lr;
                uint32_t off = SW128((uint32_t)(row*128 + (ks*2 + (mid >> 1))*16));
                ldsm4(ah[mf], abase + off);
                if (TERMS == 3) ldsm4(al[mf], abase + ASZ + off);
            }
            uint32_t bh[4][4], bl[4][4];
            #pragma unroll
            for (int np = 0; np < 4; np++){
                int row = wn*64 + np*16 + (mid >> 1)*8 + lr;
                uint32_t off = SW128((uint32_t)(row*128 + (ks*2 + (mid & 1))*16));
                ldsm4(bh[np], bbase + off);
                ldsm4(bl[np], bbase + 16384 + off);
            }
            #pragma unroll
            for (int mf = 0; mf < 2; mf++){
                #pragma unroll
                for (int nf = 0; nf < 8; nf++){
                    uint32_t* ph = &bh[nf >> 1][(nf & 1)*2];
                    uint32_t* pl = &bl[nf >> 1][(nf & 1)*2];
                    mma_bf16(acc[mf][nf], ah[mf], ph[0], ph[1]);
                    mma_bf16(acc[mf][nf], ah[mf], pl[0], pl[1]);
                    if (TERMS == 3) mma_bf16(acc[mf][nf], al[mf], ph[0], ph[1]);
                }
            }
        }
        __syncthreads();
    }

    // epilogue
    #pragma unroll
    for (int mf = 0; mf < 2; mf++){
        int m0 = bm + wm*32 + mf*16 + (lane >> 2);
        #pragma unroll
        for (int half = 0; half < 2; half++){
            int m = m0 + half*8;
            if (m >= M) continue;
            #pragma unroll
            for (int nf = 0; nf < 8; nf++){
                float d0 = acc[mf][nf][half*2 + 0];
                float d1 = acc[mf][nf][half*2 + 1];
                int c0 = bn + wn*64 + nf*8 + (lane & 3)*2;
                if (mode == 0){
                    float2 o = make_float2(d0 + bias[c0], d1 + bias[c0+1]);
                    *(float2*)(C + (size_t)m*N + c0) = o;
                } else if (mode == 1){
                    float a = d0 + bias[c0];
                    float g = d1 + bias[c0+1];
                    float ge = 0.5f*g*(1.0f + erff(g*0.70710678118654752440f));
                    float v = a*ge;
                    int u = c0 >> 1;
                    __nv_bfloat16 hh = __float2bfloat16(v);
                    __nv_bfloat16 ll = __float2bfloat16(v - __bfloat162float(hh));
                    Oh[(size_t)m*HIDm + u] = hh;
                    Ol[(size_t)m*HIDm + u] = ll;
                } else if (mode == 2){
                    const float* gv = g_gb + (blk*7 + frame_class(m))*Dm;
                    float2 o;
                    o.x = (d0 + bias[c0])   * gv[c0];
                    o.y = (d1 + bias[c0+1]) * gv[c0+1];
                    *(float2*)(C + (size_t)m*N + c0) = o;
                } else {
                    *(uint32_t*)(Oh + (size_t)m*N + c0) = pack2h(d0 + bias[c0], d1 + bias[c0+1]);
                }
            }
        }
    }
}

// ---------------- flash attention (HMMA, pure bf16 QKV input), 64q x 64k blocks ----------------
// grid: (nframes, 5 qtiles, 8 heads), 128 threads (4 warps x 16 q rows)
__global__ __launch_bounds__(128) void fattn(const __nv_bfloat16* __restrict__ QKV){
    int frame = blockIdx.x, qt = blockIdx.y, h = blockIdx.z;
    int qbase, r0s, r0n, r1s, r1n;
    if (frame < 6){
        qbase = frame*SEQ;
        r0s = frame*SEQ;              r0n = SEQ;
        int lo = frame-4; if (lo < 0) lo = 0;
        r1s = NZR + lo*SEQ;           r1n = (frame - lo)*SEQ;
    } else {
        int f = frame - 6;
        qbase = NZR + f*SEQ;
        r0s = NZR;                    r0n = (f+1)*SEQ;
        r1s = 0;                      r1n = 0;
    }
    int nk = r0n + r1n;
    int q0 = qt*64;
    int nq = SEQ - q0; if (nq > 64) nq = 64;   // qt=4 -> nq=1

    __shared__ __align__(128) char sbuf[24576];
    char* sQh = sbuf;
    char* sKc = sbuf + 8192;
    char* sVc = sbuf + 16384;
    uint32_t bQh = smem_u32(sQh), bK = smem_u32(sKc), bV = smem_u32(sVc);
    int tid = threadIdx.x, lane = tid & 31, wid = tid >> 5;
    int lr = lane & 7, mid = lane >> 3;

    // load Q tile (bf16, direct 16B copies)
    for (int idx = tid; idx < 512; idx += 128){
        int r = idx >> 3, c8 = idx & 7;
        int rr = (r < nq) ? r : (nq-1);
        const uint4* base = (const uint4*)(QKV + (size_t)(qbase + q0 + rr)*QKVD + h*DH);
        uint32_t off = SW128((uint32_t)(r*128 + c8*16));
        *(uint4*)(sQh + off) = base[c8];
    }
    __syncthreads();
    uint32_t qh[4][4];
    #pragma unroll
    for (int ks = 0; ks < 4; ks++){
        uint32_t off = SW128((uint32_t)((wid*16 + (mid&1)*8 + lr)*128 + (ks*2 + (mid>>1))*16));
        ldsm4(qh[ks], bQh + off);
    }

    float o[8][4];
    #pragma unroll
    for (int j=0;j<8;j++){ o[j][0]=0.f;o[j][1]=0.f;o[j][2]=0.f;o[j][3]=0.f; }
    float m0=-1e30f, m1=-1e30f, l0=0.f, l1=0.f;

    int nkb = (nk + 63) >> 6;
    for (int kb = 0; kb < nkb; kb++){
        int k0 = kb << 6;
        __syncthreads();
        for (int idx = tid; idx < 512; idx += 128){
            int r = idx >> 3, c8 = idx & 7;
            int i = k0 + r;
            int g = (i < r0n) ? (r0s + i) : ((i < nk) ? (r1s + i - r0n) : r0s);
            const uint4* base = (const uint4*)(QKV + (size_t)g*QKVD + h*DH);
            uint32_t off = SW128((uint32_t)(r*128 + c8*16));
            *(uint4*)(sKc + off) = base[64 + c8];    // K at +512 bf16
            *(uint4*)(sVc + off) = base[128 + c8];   // V at +1024 bf16
        }
        __syncthreads();

        // S = Q K^T
        float s[8][4];
        #pragma unroll
        for (int j=0;j<8;j++){ s[j][0]=0.f;s[j][1]=0.f;s[j][2]=0.f;s[j][3]=0.f; }
        #pragma unroll
        for (int ks = 0; ks < 4; ks++){
            #pragma unroll
            for (int np = 0; np < 4; np++){
                uint32_t bk[4];
                uint32_t off = SW128((uint32_t)((np*16 + (mid>>1)*8 + lr)*128 + (ks*2 + (mid&1))*16));
                ldsm4(bk, bK + off);
                mma_bf16(s[np*2],   qh[ks], bk[0], bk[1]);
                mma_bf16(s[np*2+1], qh[ks], bk[2], bk[3]);
            }
        }
        // online softmax
        float mx0 = -1e30f, mx1 = -1e30f;
        #pragma unroll
        for (int j = 0; j < 8; j++){
            int c = k0 + j*8 + (lane & 3)*2;
            s[j][0] = (c   < nk) ? s[j][0]*0.125f : -1e30f;
            s[j][1] = (c+1 < nk) ? s[j][1]*0.125f : -1e30f;
            s[j][2] = (c   < nk) ? s[j][2]*0.125f : -1e30f;
            s[j][3] = (c+1 < nk) ? s[j][3]*0.125f : -1e30f;
            mx0 = fmaxf(mx0, fmaxf(s[j][0], s[j][1]));
            mx1 = fmaxf(mx1, fmaxf(s[j][2], s[j][3]));
        }
        mx0 = fmaxf(mx0, __shfl_xor_sync(0xffffffffu, mx0, 1));
        mx0 = fmaxf(mx0, __shfl_xor_sync(0xffffffffu, mx0, 2));
        mx1 = fmaxf(mx1, __shfl_xor_sync(0xffffffffu, mx1, 1));
        mx1 = fmaxf(mx1, __shfl_xor_sync(0xffffffffu, mx1, 2));
        float mn0 = fmaxf(m0, mx0), mn1 = fmaxf(m1, mx1);
        float f0 = __expf(m0 - mn0), f1 = __expf(m1 - mn1);
        m0 = mn0; m1 = mn1;
        l0 *= f0; l1 *= f1;
        #pragma unroll
        for (int j=0;j<8;j++){ o[j][0]*=f0; o[j][1]*=f0; o[j][2]*=f1; o[j][3]*=f1; }
        uint32_t pp[8][2];
        #pragma unroll
        for (int j = 0; j < 8; j++){
            float p0 = __expf(s[j][0]-m0), p1 = __expf(s[j][1]-m0);
            float p2 = __expf(s[j][2]-m1), p3 = __expf(s[j][3]-m1);
            l0 += p0 + p1; l1 += p2 + p3;
            pp[j][0] = pack2h(p0, p1);
            pp[j][1] = pack2h(p2, p3);
        }
        // O += P V
        #pragma unroll
        for (int ks = 0; ks < 4; ks++){
            uint32_t ah[4] = {pp[2*ks][0], pp[2*ks][1], pp[2*ks+1][0], pp[2*ks+1][1]};
            #pragma unroll
            for (int vd = 0; vd < 4; vd++){
                uint32_t bv[4];
                uint32_t off = SW128((uint32_t)((ks*16 + (lane & 15))*128 + vd*32 + (lane >> 4)*16));
                ldsm4t(bv, bV + off);
                mma_bf16(o[vd*2],   ah, bv[0], bv[1]);
                mma_bf16(o[vd*2+1], ah, bv[2], bv[3]);
            }
        }
    }
    l0 += __shfl_xor_sync(0xffffffffu, l0, 1);
    l0 += __shfl_xor_sync(0xffffffffu, l0, 2);
    l1 += __shfl_xor_sync(0xffffffffu, l1, 1);
    l1 += __shfl_xor_sync(0xffffffffu, l1, 2);
    float i0 = 1.0f/l0, i1 = 1.0f/l1;
    int row0 = wid*16 + (lane >> 2);
    #pragma unroll
    for (int j = 0; j < 8; j++){
        int c = j*8 + (lane & 3)*2;
        if (row0 < nq){
            size_t idx = (size_t)(qbase + q0 + row0)*Dm + h*DH + c;
            uint32_t hh, ll;
            split2(o[j][0]*i0, o[j][1]*i0, hh, ll);
            *(uint32_t*)(g_xh + idx) = hh;
            *(uint32_t*)(g_xl + idx) = ll;
        }
        if (row0 + 8 < nq){
            size_t idx = (size_t)(qbase + q0 + row0 + 8)*Dm + h*DH + c;
            uint32_t hh, ll;
            split2(o[j][2]*i1, o[j][3]*i1, hh, ll);
            *(uint32_t*)(g_xh + idx) = hh;
            *(uint32_t*)(g_xl + idx) = ll;
        }
    }
}

// ---------------- unpatch ----------------
__global__ void unpatch_kernel(const float* __restrict__ Wu, const float* __restrict__ bu,
                               float* __restrict__ out){
    int token = blockIdx.x;
    int f = token >> 8, s = token & 255;
    const float* x = g_state + (size_t)(f*SEQ + s)*Dm;
    __shared__ float xs[Dm];
    int tid = threadIdx.x;
    for (int d2 = tid; d2 < Dm; d2 += 128) xs[d2] = x[d2];
    __syncthreads();
    int warp = tid >> 5, lane = tid & 31;
    for (int j = warp; j < 12; j += 4){
        float acc = 0.f;
        for (int d2 = lane; d2 < Dm; d2 += 32) acc += xs[d2] * Wu[d2*12 + j];
        acc = warpSum(acc);
        if (lane == 0){
            int c = j >> 2, ph = (j >> 1) & 1, pw = j & 1;
            int h2 = s >> 4, w2 = s & 15;
            out[f*3072 + c*1024 + (h2*2 + ph)*32 + (w2*2 + pw)] = acc + bu[j];
        }
    }
}

// ---------------- host ----------------
template <typename T>
static T* symaddr(const void* sym){
    void* p = nullptr;
    cudaGetSymbolAddress(&p, sym);
    return (T*)p;
}

extern "C" void kernel_launch(void* const* d_in, const int* in_sizes, int n_in,
                              void* d_out, int out_size){
    const float* z        = (const float*)d_in[0];
    const float* frames   = (const float*)d_in[1];
    const int*   actions  = (const int*)  d_in[2];
    const int*   ts       = (const int*)  d_in[3];
    const float* W_patch  = (const float*)d_in[4];
    const float* b_patch  = (const float*)d_in[5];
    const float* W_unpatch= (const float*)d_in[6];
    const float* b_unpatch= (const float*)d_in[7];
    const float* registers= (const float*)d_in[8];
    const float* pe_grid  = (const float*)d_in[9];
    const float* action_e = (const float*)d_in[10];
    const float* time_emb = (const float*)d_in[11];
    const float* W_mod1   = (const float*)d_in[12];
    const float* b_mod1   = (const float*)d_in[13];
    const float* W_mod2   = (const float*)d_in[14];
    const float* b_mod2   = (const float*)d_in[15];
    const float* W_q      = (const float*)d_in[16];
    const float* b_q      = (const float*)d_in[17];
    const float* W_k      = (const float*)d_in[18];
    const float* b_k      = (const float*)d_in[19];
    const float* W_v      = (const float*)d_in[20];
    const float* b_v      = (const float*)d_in[21];
    const float* W_o      = (const float*)d_in[22];
    const float* b_o      = (const float*)d_in[23];
    const float* W_g1     = (const float*)d_in[24];
    const float* b_g1     = (const float*)d_in[25];
    const float* W_g2     = (const float*)d_in[26];
    const float* b_g2     = (const float*)d_in[27];
    const float* W_geglu  = (const float*)d_in[28];
    const float* b_geglu  = (const float*)d_in[29];
    const float* W_ffout  = (const float*)d_in[30];
    const float* b_ffout  = (const float*)d_in[31];
    float* out = (float*)d_out;

    float* pState = symaddr<float>(g_state);
    __nv_bfloat16* pQKVb = symaddr<__nv_bfloat16>(g_qkvb);
    float* pAtto  = symaddr<float>(g_atto);
    float* pBqkv  = symaddr<float>(g_bqkv);
    float* pBgg   = symaddr<float>(g_bgg2);
    __nv_bfloat16* nh = symaddr<__nv_bfloat16>(g_nh);
    __nv_bfloat16* nl = symaddr<__nv_bfloat16>(g_nl);
    __nv_bfloat16* xh = symaddr<__nv_bfloat16>(g_xh);
    __nv_bfloat16* xl = symaddr<__nv_bfloat16>(g_xl);
    __nv_bfloat16* yh = symaddr<__nv_bfloat16>(g_yh);
    __nv_bfloat16* yl = symaddr<__nv_bfloat16>(g_yl);
    __nv_bfloat16* wqkvh = symaddr<__nv_bfloat16>(g_wqkv_h);
    __nv_bfloat16* wqkvl = symaddr<__nv_bfloat16>(g_wqkv_l);
    __nv_bfloat16* woh   = symaddr<__nv_bfloat16>(g_wo_h);
    __nv_bfloat16* wol   = symaddr<__nv_bfloat16>(g_wo_l);
    __nv_bfloat16* wggh  = symaddr<__nv_bfloat16>(g_wgg_h);
    __nv_bfloat16* wggl  = symaddr<__nv_bfloat16>(g_wgg_l);
    __nv_bfloat16* wffh  = symaddr<__nv_bfloat16>(g_wff_h);
    __nv_bfloat16* wffl  = symaddr<__nv_bfloat16>(g_wff_l);

    cudaFuncSetAttribute(gemm_mma_t<128,3>, cudaFuncAttributeMaxDynamicSharedMemorySize, 131072);
    cudaFuncSetAttribute(gemm_mma_t<128,2>, cudaFuncAttributeMaxDynamicSharedMemorySize, 131072);
    cudaFuncSetAttribute(gemm_mma_t<64,3>,  cudaFuncAttributeMaxDynamicSharedMemorySize, 98304);

    cond_kernel<<<7, 128>>>(ts, time_emb);
    modvec_kernel<<<dim3(NBLK*7, 12), 256>>>(W_mod1, b_mod1, W_mod2, b_mod2,
                                             W_g1, b_g1, W_g2, b_g2);
    embed_kernel<<<NTOK, 128>>>(z, frames, actions, W_patch, b_patch,
                                registers, pe_grid, action_e);

    dim3 tb(32, 8);
    transp_split4<<<dim3(16,16,4*NBLK), tb>>>(W_q, W_k, W_v, W_o);
    transp_split<<<dim3(128,16,NBLK), tb>>>(W_geglu, wggh, wggl, 512, 4096, 1,
                                            (size_t)512*4096, (size_t)4096*512);
    transp_split<<<dim3(16,64,NBLK), tb>>>(W_ffout, wffh, wffl, 2048, 512, 0,
                                           (size_t)2048*512, (size_t)512*2048);
    prep_bias<<<NBLK, 256>>>(b_q, b_k, b_v, b_geglu);

    for (int i = 0; i < NBLK; i++){
        // Last block: xa stream's post-attention work is dead (only zr reaches the output).
        int Mpost   = (i == NBLK-1) ? NZR : NTOK;
        int nframes = (i == NBLK-1) ? 6   : 11;
        int mt128   = (Mpost + 127) / 128;
        int mt64    = (Mpost + 63) / 64;
        int qt128   = (NTOK + 127) / 128;   // QKV always full (K/V needed for cross-attn)

        mod_kernel<<<NTOK, 128>>>(i);
        gemm_mma_t<128,2><<<dim3(QKVD/128, qt128), 256, 131072>>>(nh, nl,
            wqkvh + (size_t)i*QKVD*512, wqkvl + (size_t)i*QKVD*512,
            pBqkv + i*QKVD, nullptr, pQKVb, nullptr, NTOK, QKVD, 512, 3, i);
        fattn<<<dim3(nframes, 5, NHh), 128>>>(pQKVb);
        gemm_mma_t<64,3><<<dim3(4, mt64), 128, 98304>>>(xh, xl,
            woh + (size_t)i*512*512, wol + (size_t)i*512*512,
            b_o + i*512, pAtto, nullptr, nullptr, Mpost, 512, 512, 0, i);
        postattn_kernel<<<Mpost, 128>>>(i);
        gemm_mma_t<128,3><<<dim3(32, mt128), 256, 131072>>>(xh, xl,
            wggh + (size_t)i*4096*512, wggl + (size_t)i*4096*512,
            pBgg + i*4096, nullptr, yh, yl, Mpost, 4096, 512, 1, i);
        gemm_mma_t<64,3><<<dim3(4, mt64), 128, 98304>>>(yh, yl,
            wffh + (size_t)i*512*2048, wffl + (size_t)i*512*2048,
            b_ffout + i*512, pState, nullptr, nullptr, Mpost, 512, 2048, 2, i);
    }
    unpatch_kernel<<<1536, 128>>>(W_unpatch, b_unpatch, out);
}